// round 2
// baseline (speedup 1.0000x reference)
#include <cuda_runtime.h>
#include <cuda_bf16.h>
#include <math.h>

// ---------------- problem constants ----------------
#define Tn     4096      // B*S tokens
#define Sn     2048
#define Bn     2
#define DIMn   2048
#define NHn    16
#define NOPEn  128
#define ROPEn  64
#define QDn    192       // NOPE+ROPE
#define VHn    128
#define KVRn   512
#define NEn    8
#define MINTERn 1408
#define SHIn   2816
#define QPROJ  3072      // NH*QD
#define KVAP   576       // KVR+ROPE
#define KVBP   4096      // NH*(NOPE+VH)
#define MOE_ROWS 9216    // 72 tiles of 128 (worst-case padded 8192 + 8*127)
#define MOE_TILES 72

// ---------------- scratch (device globals; no allocs allowed) ----------------
__device__ float g_nx[Tn*DIMn];
__device__ float g_q[Tn*QPROJ];
__device__ float g_kv[Tn*KVAP];
__device__ float g_ckv[Tn*KVRn];
__device__ float g_kpe[Tn*ROPEn];
__device__ float g_kvb[Tn*KVBP];
__device__ float g_scores[134217728];       // 32 * 2048 * 2048
__device__ float g_attn[Tn*DIMn];
__device__ float g_h[Tn*DIMn];
__device__ float g_nh[Tn*DIMn];
__device__ float g_xg[MOE_ROWS*DIMn];
__device__ float g_t1[MOE_ROWS*MINTERn];
__device__ float g_t3[MOE_ROWS*MINTERn];
__device__ float g_eo[MOE_ROWS*DIMn];
__device__ float g_s1[Tn*SHIn];
__device__ float g_s3[Tn*SHIn];
__device__ float g_sh[Tn*DIMn];
__device__ int   g_counts[NEn];
__device__ int   g_off[NEn+1];
__device__ int   g_tile_expert[MOE_TILES];
__device__ int   g_bucket_ts[NEn*Tn];
__device__ float g_bucket_gate[NEn*Tn];
__device__ int   g_flat_tok[MOE_ROWS];
__device__ int   g_tok2row[Tn*2];
__device__ float g_tok2gate[Tn*2];

// ---------------- generic SGEMM: C = A @ W^T (or A @ B), batched ----------------
// flags: bit0 accumulate (C+=), bit1 causal tile skip, bit2 K-limit by row tile,
//        bit3 W is [K,N] (A@B form; requires N%4==0)
__global__ __launch_bounds__(256) void sgemm_k(
    const float* __restrict__ A, const float* __restrict__ W, float* __restrict__ C,
    int M, int N, int K, int lda, int ldb, int ldc,
    long sA0, long sA1, long sW0, long sW1, long sC0, long sC1, int ZH,
    const int* __restrict__ tileExpert, long wStride, int flags)
{
    int bx = blockIdx.x, by = blockIdx.y, z = blockIdx.z;
    if ((flags & 2) && bx > by) return;               // fully-masked causal tile
    if (tileExpert) { int te = tileExpert[by]; if (te < 0) return; W += (long)te * wStride; }
    int zb = z / ZH, zh = z - zb * ZH;
    A += zb * sA0 + (long)zh * sA1;
    W += zb * sW0 + (long)zh * sW1;
    C += zb * sC0 + (long)zh * sC1;
    int Keff = K;
    if (flags & 4) { int kl = (by + 1) * 128; if (kl < Keff) Keff = kl; }

    __shared__ float As[8][128];
    __shared__ float Bs[8][128];
    int tid = threadIdx.x;
    int ty = tid >> 4, tx = tid & 15;
    float acc[8][8];
#pragma unroll
    for (int i = 0; i < 8; i++)
#pragma unroll
        for (int j = 0; j < 8; j++) acc[i][j] = 0.f;

    int arow = tid >> 1;
    int ak   = (tid & 1) * 4;
    const float* Ap = A + (long)(by * 128 + arow) * lda + ak;
    bool aval = (by * 128 + arow) < M;

    bool transB = (flags & 8) != 0;
    int wrow = tid >> 1;
    int wk   = (tid & 1) * 4;
    const float* Wp1 = W + (long)(bx * 128 + wrow) * ldb + wk;
    bool wval1 = (bx * 128 + wrow) < N;
    int bkr = tid >> 5;
    int bcc = (tid & 31) * 4;
    const float* Wp2 = W + (long)bkr * ldb + bx * 128 + bcc;
    bool wval2 = (bx * 128 + bcc) < N;

    for (int k0 = 0; k0 < Keff; k0 += 8) {
        float4 fa = make_float4(0.f, 0.f, 0.f, 0.f);
        if (aval) fa = *(const float4*)(Ap + k0);
        As[ak+0][arow] = fa.x; As[ak+1][arow] = fa.y;
        As[ak+2][arow] = fa.z; As[ak+3][arow] = fa.w;
        if (!transB) {
            float4 fw = make_float4(0.f, 0.f, 0.f, 0.f);
            if (wval1) fw = *(const float4*)(Wp1 + k0);
            Bs[wk+0][wrow] = fw.x; Bs[wk+1][wrow] = fw.y;
            Bs[wk+2][wrow] = fw.z; Bs[wk+3][wrow] = fw.w;
        } else {
            float4 fw = make_float4(0.f, 0.f, 0.f, 0.f);
            if (wval2) fw = *(const float4*)(Wp2 + (long)k0 * ldb);
            *(float4*)&Bs[bkr][bcc] = fw;
        }
        __syncthreads();
#pragma unroll
        for (int kk = 0; kk < 8; kk++) {
            float4 a0 = *(const float4*)&As[kk][ty * 8];
            float4 a1 = *(const float4*)&As[kk][ty * 8 + 4];
            float4 b0 = *(const float4*)&Bs[kk][tx * 8];
            float4 b1 = *(const float4*)&Bs[kk][tx * 8 + 4];
            float ra[8] = {a0.x, a0.y, a0.z, a0.w, a1.x, a1.y, a1.z, a1.w};
            float rb[8] = {b0.x, b0.y, b0.z, b0.w, b1.x, b1.y, b1.z, b1.w};
#pragma unroll
            for (int i = 0; i < 8; i++)
#pragma unroll
                for (int j = 0; j < 8; j++)
                    acc[i][j] = fmaf(ra[i], rb[j], acc[i][j]);
        }
        __syncthreads();
    }

    bool add = (flags & 1) != 0;
#pragma unroll
    for (int i = 0; i < 8; i++) {
        int cr = by * 128 + ty * 8 + i;
        if (cr < M) {
            float* Cr = C + (long)cr * ldc + bx * 128 + tx * 8;
#pragma unroll
            for (int j = 0; j < 8; j++) {
                int cc = bx * 128 + tx * 8 + j;
                if (cc < N) { if (add) Cr[j] += acc[i][j]; else Cr[j] = acc[i][j]; }
            }
        }
    }
}

// ---------------- reductions ----------------
__device__ __forceinline__ float warpSum(float v) {
#pragma unroll
    for (int o = 16; o; o >>= 1) v += __shfl_xor_sync(0xffffffffu, v, o);
    return v;
}
__device__ __forceinline__ float warpMax(float v) {
#pragma unroll
    for (int o = 16; o; o >>= 1) v = fmaxf(v, __shfl_xor_sync(0xffffffffu, v, o));
    return v;
}

// ---------------- rmsnorm ----------------
__global__ void rmsnorm_k(const float* __restrict__ x, const float* __restrict__ w,
                          float* __restrict__ y, int D, int ldx, int ldy)
{
    long t = blockIdx.x;
    const float* xr = x + t * ldx;
    float* yr = y + t * ldy;
    float s = 0.f;
    for (int d = threadIdx.x; d < D; d += blockDim.x) { float v = xr[d]; s += v * v; }
    __shared__ float sh[32];
    __shared__ float bc;
    s = warpSum(s);
    int lane = threadIdx.x & 31, wp = threadIdx.x >> 5;
    if (!lane) sh[wp] = s;
    __syncthreads();
    if (threadIdx.x < 32) {
        float r = (threadIdx.x < (blockDim.x >> 5)) ? sh[threadIdx.x] : 0.f;
        r = warpSum(r);
        if (!threadIdx.x) bc = rsqrtf(r / D + 1e-6f);
    }
    __syncthreads();
    float sc = bc;
    for (int d = threadIdx.x; d < D; d += blockDim.x) yr[d] = xr[d] * sc * w[d];
}

// ---------------- rope on k_pe ----------------
__global__ void rope_kpe_k(const float* __restrict__ kv, const float* __restrict__ fc,
                           const float* __restrict__ fs, float* __restrict__ kpe)
{
    long t = blockIdx.x;
    int j = threadIdx.x;                 // 0..31
    int pos = (int)(t % Sn);
    float x1 = kv[t * KVAP + KVRn + 2 * j];
    float x2 = kv[t * KVAP + KVRn + 2 * j + 1];
    float c = fc[pos * 32 + j], s = fs[pos * 32 + j];
    kpe[t * ROPEn + 2 * j]     = x1 * c - x2 * s;
    kpe[t * ROPEn + 2 * j + 1] = x1 * s + x2 * c;
}

// ---------------- rope + scale on q (in place) ----------------
__global__ void ropescale_q_k(float* __restrict__ q, const float* __restrict__ fc,
                              const float* __restrict__ fs)
{
    long th = blockIdx.x;                // t*16 + h
    int pos = (int)((th >> 4) % Sn);
    float* r = q + th * QDn;
    int i = threadIdx.x;                 // 0..95 (pairs)
    const float sc = 0.07216878364870322f;   // 1/sqrt(192)
    if (i < 64) {
        r[2 * i]     *= sc;
        r[2 * i + 1] *= sc;
    } else {
        int j = i - 64;
        float x1 = r[128 + 2 * j], x2 = r[128 + 2 * j + 1];
        float c = fc[pos * 32 + j], s = fs[pos * 32 + j];
        r[128 + 2 * j]     = (x1 * c - x2 * s) * sc;
        r[128 + 2 * j + 1] = (x1 * s + x2 * c) * sc;
    }
}

// ---------------- causal softmax over score rows ----------------
__global__ void softmax_causal_k(float* __restrict__ scores)
{
    long row = blockIdx.x;               // 32*S rows
    int q = (int)(row % Sn);
    float* p = scores + row * Sn;
    int n = q + 1;
    float m = -3.4e38f;
    for (int k = threadIdx.x; k < n; k += blockDim.x) m = fmaxf(m, p[k]);
    __shared__ float shm[32];
    __shared__ float bc0, bc1;
    m = warpMax(m);
    int lane = threadIdx.x & 31, wp = threadIdx.x >> 5;
    if (!lane) shm[wp] = m;
    __syncthreads();
    if (threadIdx.x < 32) {
        float r = (threadIdx.x < (blockDim.x >> 5)) ? shm[threadIdx.x] : -3.4e38f;
        r = warpMax(r);
        if (!threadIdx.x) bc0 = r;
    }
    __syncthreads();
    m = bc0;
    float sum = 0.f;
    for (int k = threadIdx.x; k < n; k += blockDim.x) {
        float e = expf(p[k] - m);
        p[k] = e;
        sum += e;
    }
    __syncthreads();
    sum = warpSum(sum);
    if (!lane) shm[wp] = sum;
    __syncthreads();
    if (threadIdx.x < 32) {
        float r = (threadIdx.x < (blockDim.x >> 5)) ? shm[threadIdx.x] : 0.f;
        r = warpSum(r);
        if (!threadIdx.x) bc1 = 1.f / r;
    }
    __syncthreads();
    float inv = bc1;
    for (int k = threadIdx.x; k < n; k += blockDim.x) p[k] *= inv;
    for (int k = n + threadIdx.x; k < Sn; k += blockDim.x) p[k] = 0.f;
}

// ---------------- router: logits -> top2 -> buckets ----------------
__global__ void router_k(const float* __restrict__ nh, const float* __restrict__ rw,
                         int* __restrict__ counts, int* __restrict__ bucket_ts,
                         float* __restrict__ bucket_gate)
{
    long t = blockIdx.x;
    int wp = threadIdx.x >> 5, lane = threadIdx.x & 31;
    const float* xr = nh + t * DIMn;
    float s = 0.f;
    for (int d = lane; d < DIMn; d += 32) s += xr[d] * rw[(long)wp * DIMn + d];
    s = warpSum(s);
    __shared__ float logit[NEn];
    if (!lane) logit[wp] = s;
    __syncthreads();
    if (threadIdx.x == 0) {
        float mx = logit[0];
#pragma unroll
        for (int e = 1; e < NEn; e++) mx = fmaxf(mx, logit[e]);
        float p[NEn];
#pragma unroll
        for (int e = 0; e < NEn; e++) p[e] = expf(logit[e] - mx);
        int i0 = 0;
#pragma unroll
        for (int e = 1; e < NEn; e++) if (p[e] > p[i0]) i0 = e;
        int i1 = (i0 == 0) ? 1 : 0;
#pragma unroll
        for (int e = 0; e < NEn; e++) if (e != i0 && p[e] > p[i1]) i1 = e;
        float denom = p[i0] + p[i1];
        float g0 = p[i0] / denom, g1 = p[i1] / denom;
        int pos0 = atomicAdd(&counts[i0], 1);
        bucket_ts[i0 * Tn + pos0] = (int)(t * 2);
        bucket_gate[i0 * Tn + pos0] = g0;
        int pos1 = atomicAdd(&counts[i1], 1);
        bucket_ts[i1 * Tn + pos1] = (int)(t * 2 + 1);
        bucket_gate[i1 * Tn + pos1] = g1;
    }
}

// ---------------- expert offsets + tile->expert map ----------------
__global__ void offsets_k(const int* __restrict__ counts, int* __restrict__ off,
                          int* __restrict__ tile_expert)
{
    for (int tl = 0; tl < MOE_TILES; tl++) tile_expert[tl] = -1;
    int o = 0;
    for (int e = 0; e < NEn; e++) {
        off[e] = o;
        int nt = (counts[e] + 127) >> 7;
        for (int i = 0; i < nt; i++) tile_expert[(o >> 7) + i] = e;
        o += nt * 128;
    }
    off[NEn] = o;
}

// ---------------- compact buckets -> flat rows + inverse map ----------------
__global__ void compact_k(const int* __restrict__ counts, const int* __restrict__ off,
                          const int* __restrict__ bucket_ts, const float* __restrict__ bucket_gate,
                          int* __restrict__ flat_tok, int* __restrict__ tok2row,
                          float* __restrict__ tok2gate)
{
    int e = blockIdx.x;
    int cnt = counts[e], base = off[e];
    for (int i = threadIdx.x; i < cnt; i += blockDim.x) {
        int ts = bucket_ts[e * Tn + i];
        int r = base + i;
        flat_tok[r] = ts >> 1;
        tok2row[ts] = r;
        tok2gate[ts] = bucket_gate[e * Tn + i];
    }
}

// ---------------- gather routed tokens ----------------
__global__ void gather_k(const float* __restrict__ nh, const int* __restrict__ flat_tok,
                         float* __restrict__ xg)
{
    long r = blockIdx.x;
    int t = flat_tok[r];
    float4* dst = (float4*)(xg + r * DIMn);
    if (t < 0) {
        float4 z = make_float4(0.f, 0.f, 0.f, 0.f);
        for (int i = threadIdx.x; i < DIMn / 4; i += blockDim.x) dst[i] = z;
    } else {
        const float4* src = (const float4*)(nh + (long)t * DIMn);
        for (int i = threadIdx.x; i < DIMn / 4; i += blockDim.x) dst[i] = src[i];
    }
}

// ---------------- silu(a)*b -> a ----------------
__global__ void silumul_k(float* __restrict__ a, const float* __restrict__ b, long n)
{
    long i = (long)blockIdx.x * blockDim.x + threadIdx.x;
    if (i < n) {
        float x = a[i];
        float s = x / (1.f + expf(-x));
        a[i] = s * b[i];
    }
}

// ---------------- final combine: out = h + sh + g0*eo[r0] + g1*eo[r1] ----------------
__global__ void combine_k(const float* __restrict__ h, const float* __restrict__ sh,
                          const float* __restrict__ eo, const int* __restrict__ tok2row,
                          const float* __restrict__ tok2gate, float* __restrict__ out)
{
    long t = blockIdx.x;
    int r0 = tok2row[t * 2], r1 = tok2row[t * 2 + 1];
    float g0 = tok2gate[t * 2], g1 = tok2gate[t * 2 + 1];
    const float4* H = (const float4*)(h + t * DIMn);
    const float4* SH = (const float4*)(sh + t * DIMn);
    const float4* E0 = (const float4*)(eo + (long)r0 * DIMn);
    const float4* E1 = (const float4*)(eo + (long)r1 * DIMn);
    float4* O = (float4*)(out + t * DIMn);
    for (int i = threadIdx.x; i < DIMn / 4; i += blockDim.x) {
        float4 a = H[i], b = SH[i], c = E0[i], d = E1[i];
        float4 o;
        o.x = a.x + b.x + g0 * c.x + g1 * d.x;
        o.y = a.y + b.y + g0 * c.y + g1 * d.y;
        o.z = a.z + b.z + g0 * c.z + g1 * d.z;
        o.w = a.w + b.w + g0 * c.w + g1 * d.w;
        O[i] = o;
    }
}

// ---------------- host side ----------------
#define SYM(p, s) do { void* _q = nullptr; cudaGetSymbolAddress(&_q, s); p = (decltype(p))_q; } while (0)

static void launch_sgemm(const float* A, const float* W, float* C,
                         int M, int N, int K, int lda, int ldb, int ldc,
                         long sA0, long sA1, long sW0, long sW1, long sC0, long sC1,
                         int ZH, int Z, const int* tileExpert, long wStride, int flags)
{
    dim3 grid((N + 127) / 128, (M + 127) / 128, Z);
    sgemm_k<<<grid, 256>>>(A, W, C, M, N, K, lda, ldb, ldc,
                           sA0, sA1, sW0, sW1, sC0, sC1, ZH, tileExpert, wStride, flags);
}

extern "C" void kernel_launch(void* const* d_in, const int* in_sizes, int n_in,
                              void* d_out, int out_size)
{
    const float* x       = (const float*)d_in[0];
    const float* fcos    = (const float*)d_in[1];
    const float* fsin    = (const float*)d_in[2];
    const float* attn_w  = (const float*)d_in[3];
    const float* wq      = (const float*)d_in[4];
    const float* wkv_a   = (const float*)d_in[5];
    const float* kv_w    = (const float*)d_in[6];
    const float* wkv_b   = (const float*)d_in[7];
    const float* wo      = (const float*)d_in[8];
    const float* ffn_w   = (const float*)d_in[9];
    const float* rw      = (const float*)d_in[10];
    const float* e_w1    = (const float*)d_in[11];
    const float* e_w3    = (const float*)d_in[12];
    const float* e_w2    = (const float*)d_in[13];
    const float* s_w1    = (const float*)d_in[14];
    const float* s_w3    = (const float*)d_in[15];
    const float* s_w2    = (const float*)d_in[16];
    float* out = (float*)d_out;

    float *nx, *q, *kv, *ckv, *kpe, *kvb, *scores, *attn, *h, *nh;
    float *xg, *t1, *t3, *eo, *s1, *s3, *sh;
    int *counts, *off, *tile_expert, *bucket_ts, *flat_tok, *tok2row;
    float *bucket_gate, *tok2gate;
    SYM(nx, g_nx); SYM(q, g_q); SYM(kv, g_kv); SYM(ckv, g_ckv); SYM(kpe, g_kpe);
    SYM(kvb, g_kvb); SYM(scores, g_scores); SYM(attn, g_attn); SYM(h, g_h); SYM(nh, g_nh);
    SYM(xg, g_xg); SYM(t1, g_t1); SYM(t3, g_t3); SYM(eo, g_eo);
    SYM(s1, g_s1); SYM(s3, g_s3); SYM(sh, g_sh);
    SYM(counts, g_counts); SYM(off, g_off); SYM(tile_expert, g_tile_expert);
    SYM(bucket_ts, g_bucket_ts); SYM(bucket_gate, g_bucket_gate);
    SYM(flat_tok, g_flat_tok); SYM(tok2row, g_tok2row); SYM(tok2gate, g_tok2gate);

    const long SS = (long)Sn * Sn;

    // 1. attention-input rmsnorm
    rmsnorm_k<<<Tn, 256>>>(x, attn_w, nx, DIMn, DIMn, DIMn);
    // 2. q projection
    launch_sgemm(nx, wq, q, Tn, QPROJ, DIMn, DIMn, DIMn, QPROJ,
                 0, 0, 0, 0, 0, 0, 1, 1, nullptr, 0, 0);
    // 3. kv_a projection
    launch_sgemm(nx, wkv_a, kv, Tn, KVAP, DIMn, DIMn, DIMn, KVAP,
                 0, 0, 0, 0, 0, 0, 1, 1, nullptr, 0, 0);
    // 4. c_kv rmsnorm
    rmsnorm_k<<<Tn, 256>>>(kv, kv_w, ckv, KVRn, KVAP, KVRn);
    // 5. rope k_pe
    rope_kpe_k<<<Tn, 32>>>(kv, fcos, fsin, kpe);
    // 6. kv_b projection
    launch_sgemm(ckv, wkv_b, kvb, Tn, KVBP, KVRn, KVRn, KVRn, KVBP,
                 0, 0, 0, 0, 0, 0, 1, 1, nullptr, 0, 0);
    // 7. rope + scale q (in place)
    ropescale_q_k<<<Tn * NHn, 96>>>(q, fcos, fsin);
    // 8. scores = q_nope @ k_nope^T   (batched over 32 (b,h); causal tile skip)
    launch_sgemm(q, kvb, scores, Sn, Sn, NOPEn, QPROJ, KVBP, Sn,
                 (long)Sn * QPROJ, QDn, (long)Sn * KVBP, 256, 16 * SS, SS,
                 16, 32, nullptr, 0, 2);
    // 9. scores += q_pe @ k_pe^T  (k_pe shared across heads)
    launch_sgemm(q + NOPEn, kpe, scores, Sn, Sn, ROPEn, QPROJ, ROPEn, Sn,
                 (long)Sn * QPROJ, QDn, (long)Sn * ROPEn, 0, 16 * SS, SS,
                 16, 32, nullptr, 0, 1 | 2);
    // 10. causal softmax
    softmax_causal_k<<<32 * Sn, 256>>>(scores);
    // 11. attn = P @ V  (transB form, K-limited by causal row tile)
    launch_sgemm(scores, kvb + NOPEn, attn, Sn, VHn, Sn, Sn, KVBP, DIMn,
                 16 * SS, SS, (long)Sn * KVBP, 256, (long)Sn * DIMn, VHn,
                 16, 32, nullptr, 0, 4 | 8);
    // 12. h = x + attn @ wo^T
    cudaMemcpyAsync(h, x, (size_t)Tn * DIMn * sizeof(float), cudaMemcpyDeviceToDevice, 0);
    launch_sgemm(attn, wo, h, Tn, DIMn, DIMn, DIMn, DIMn, DIMn,
                 0, 0, 0, 0, 0, 0, 1, 1, nullptr, 0, 1);
    // 13. ffn rmsnorm
    rmsnorm_k<<<Tn, 256>>>(h, ffn_w, nh, DIMn, DIMn, DIMn);
    // 14. routing
    cudaMemsetAsync(counts, 0, NEn * sizeof(int), 0);
    cudaMemsetAsync(flat_tok, 0xFF, MOE_ROWS * sizeof(int), 0);
    router_k<<<Tn, 256>>>(nh, rw, counts, bucket_ts, bucket_gate);
    offsets_k<<<1, 1>>>(counts, off, tile_expert);
    compact_k<<<NEn, 256>>>(counts, off, bucket_ts, bucket_gate, flat_tok, tok2row, tok2gate);
    gather_k<<<MOE_ROWS, 256>>>(nh, flat_tok, xg);
    // 15. expert FFN (grouped GEMM via tile->expert indirection)
    launch_sgemm(xg, e_w1, t1, MOE_ROWS, MINTERn, DIMn, DIMn, DIMn, MINTERn,
                 0, 0, 0, 0, 0, 0, 1, 1, tile_expert, (long)MINTERn * DIMn, 0);
    launch_sgemm(xg, e_w3, t3, MOE_ROWS, MINTERn, DIMn, DIMn, DIMn, MINTERn,
                 0, 0, 0, 0, 0, 0, 1, 1, tile_expert, (long)MINTERn * DIMn, 0);
    {
        long n = (long)MOE_ROWS * MINTERn;
        silumul_k<<<(int)((n + 255) / 256), 256>>>(t1, t3, n);
    }
    launch_sgemm(t1, e_w2, eo, MOE_ROWS, DIMn, MINTERn, MINTERn, MINTERn, DIMn,
                 0, 0, 0, 0, 0, 0, 1, 1, tile_expert, (long)DIMn * MINTERn, 0);
    // 16. shared FFN
    launch_sgemm(nh, s_w1, s1, Tn, SHIn, DIMn, DIMn, DIMn, SHIn,
                 0, 0, 0, 0, 0, 0, 1, 1, nullptr, 0, 0);
    launch_sgemm(nh, s_w3, s3, Tn, SHIn, DIMn, DIMn, DIMn, SHIn,
                 0, 0, 0, 0, 0, 0, 1, 1, nullptr, 0, 0);
    {
        long n = (long)Tn * SHIn;
        silumul_k<<<(int)((n + 255) / 256), 256>>>(s1, s3, n);
    }
    launch_sgemm(s1, s_w2, sh, Tn, DIMn, SHIn, SHIn, SHIn, DIMn,
                 0, 0, 0, 0, 0, 0, 1, 1, nullptr, 0, 0);
    // 17. combine
    combine_k<<<Tn, 256>>>(h, sh, eo, tok2row, tok2gate, out);
}

// round 4
// speedup vs baseline: 3.1591x; 3.1591x over previous
#include <cuda_runtime.h>
#include <cuda_bf16.h>
#include <math.h>
#include <stdint.h>

// ---------------- problem constants ----------------
#define Tn     4096
#define Sn     2048
#define DIMn   2048
#define NHn    16
#define NOPEn  128
#define ROPEn  64
#define QDn    192
#define VHn    128
#define KVRn   512
#define NEn    8
#define MINTERn 1408
#define SHIn   2816
#define QPROJ  3072
#define KVAP   576
#define KVBP   4096
#define MOE_ROWS 9216
#define MOE_TILES 72
#define ZSn    32

// ---------------- scratch ----------------
__device__ float g_nx[Tn*DIMn];
__device__ float g_q[Tn*QPROJ];
__device__ float g_kv[Tn*KVAP];
__device__ float g_ckv[Tn*KVRn];
__device__ float g_kpe[Tn*ROPEn];
__device__ float g_kvb[(size_t)Tn*KVBP];
__device__ float g_kcat[(size_t)ZSn*Sn*QDn];
__device__ float g_vT[(size_t)ZSn*VHn*Sn];
__device__ float g_scores[134217728];
__device__ float g_attn[Tn*DIMn];
__device__ float g_h[Tn*DIMn];
__device__ float g_nh[Tn*DIMn];
__device__ float g_xg[(size_t)MOE_ROWS*DIMn];
__device__ float g_t1[(size_t)MOE_ROWS*MINTERn];
__device__ float g_t3[(size_t)MOE_ROWS*MINTERn];
__device__ float g_eo[(size_t)MOE_ROWS*DIMn];
__device__ float g_s1[(size_t)Tn*SHIn];
__device__ float g_s3[(size_t)Tn*SHIn];
__device__ float g_sh[Tn*DIMn];
__device__ int   g_counts[NEn];
__device__ int   g_off[NEn+1];
__device__ int   g_tile_expert[MOE_TILES];
__device__ int   g_bucket_ts[NEn*Tn];
__device__ float g_bucket_gate[NEn*Tn];
__device__ int   g_flat_tok[MOE_ROWS];
__device__ int   g_tok2row[Tn*2];
__device__ float g_tok2gate[Tn*2];

// ---------------- mma helpers ----------------
__device__ __forceinline__ uint32_t f2tf32(float x) {
    uint32_t r; asm("cvt.rna.tf32.f32 %0, %1;" : "=r"(r) : "f"(x)); return r;
}
__device__ __forceinline__ void mma8(float* c, const uint32_t* a, const uint32_t* b) {
    asm volatile("mma.sync.aligned.m16n8k8.row.col.f32.tf32.tf32.f32 "
        "{%0,%1,%2,%3}, {%4,%5,%6,%7}, {%8,%9}, {%0,%1,%2,%3};"
        : "+f"(c[0]), "+f"(c[1]), "+f"(c[2]), "+f"(c[3])
        : "r"(a[0]), "r"(a[1]), "r"(a[2]), "r"(a[3]), "r"(b[0]), "r"(b[1]));
}

// ---------------- generic tf32 tensor GEMM ----------------
// C[M,N] = A[M,K] @ B[N,K]^T  (both K-major), batched via blockIdx.z.
// Requires: M % 128 == 0, K % 32 == 0, N even.
// flags: bit0 accumulate, bit1 causal tile skip, bit2 causal K-limit
#define LDP 36
#define TILEF (128*LDP)            // floats per tile buffer
#define TG_SMEM (4*TILEF*4)        // 2 stages x (A+B) = 73728 B

__global__ __launch_bounds__(256) void tgemm_k(
    const float* __restrict__ A, const float* __restrict__ B, float* __restrict__ C,
    int M, int N, int K, int lda, int ldb, int ldc,
    long sA0, long sA1, long sB0, long sB1, long sC0, long sC1, int ZH,
    const int* __restrict__ tileExpert, long wStride, int flags)
{
    int bx = blockIdx.x, by = blockIdx.y, z = blockIdx.z;
    if ((flags & 2) && bx > by) return;
    if (tileExpert) { int te = tileExpert[by]; if (te < 0) return; B += (long)te * wStride; }
    int zb = z / ZH, zh = z - zb * ZH;
    A += zb * sA0 + (long)zh * sA1;
    B += zb * sB0 + (long)zh * sB1;
    C += zb * sC0 + (long)zh * sC1;
    int Keff = K;
    if (flags & 4) { int kl = (by + 1) * 128; if (kl < Keff) Keff = kl; }
    int NT = Keff >> 5;

    extern __shared__ float sm[];
    float* Sa = sm;                 // [2][TILEF]
    float* Sb = sm + 2 * TILEF;     // [2][TILEF]

    int tid = threadIdx.x;
    int wid = tid >> 5, lane = tid & 31;
    int wy = wid & 1, wx = wid >> 1;
    int lr = lane >> 2, lk = lane & 3;

    // global load mapping: 4 chunks; idx = tid + ch*256 -> row = idx>>3, kcol = (idx&7)*4
    int grow[4], gcol[4];
    bool bv[4];
#pragma unroll
    for (int ch = 0; ch < 4; ch++) {
        int idx = tid + ch * 256;
        grow[ch] = idx >> 3;
        gcol[ch] = (idx & 7) * 4;
        bv[ch] = (bx * 128 + grow[ch]) < N;
    }

    const float4 z4 = make_float4(0.f, 0.f, 0.f, 0.f);
    float4 fa[4], fb[4];
#pragma unroll
    for (int ch = 0; ch < 4; ch++) {
        fa[ch] = *(const float4*)(A + (long)(by * 128 + grow[ch]) * lda + gcol[ch]);
        fb[ch] = bv[ch] ? *(const float4*)(B + (long)(bx * 128 + grow[ch]) * ldb + gcol[ch]) : z4;
    }
    // store tile 0
#pragma unroll
    for (int ch = 0; ch < 4; ch++) {
        uint32_t* pa = (uint32_t*)(Sa + grow[ch] * LDP + gcol[ch]);
        pa[0] = f2tf32(fa[ch].x); pa[1] = f2tf32(fa[ch].y); pa[2] = f2tf32(fa[ch].z); pa[3] = f2tf32(fa[ch].w);
        uint32_t* pb = (uint32_t*)(Sb + grow[ch] * LDP + gcol[ch]);
        pb[0] = f2tf32(fb[ch].x); pb[1] = f2tf32(fb[ch].y); pb[2] = f2tf32(fb[ch].z); pb[3] = f2tf32(fb[ch].w);
    }
    __syncthreads();

    float acc[4][4][4];
#pragma unroll
    for (int mt = 0; mt < 4; mt++)
#pragma unroll
        for (int nt = 0; nt < 4; nt++)
#pragma unroll
            for (int i = 0; i < 4; i++) acc[mt][nt][i] = 0.f;

    for (int it = 0; it < NT; ++it) {
        if (it + 1 < NT) {
            int k0 = (it + 1) * 32;
#pragma unroll
            for (int ch = 0; ch < 4; ch++) {
                fa[ch] = *(const float4*)(A + (long)(by * 128 + grow[ch]) * lda + k0 + gcol[ch]);
                fb[ch] = bv[ch] ? *(const float4*)(B + (long)(bx * 128 + grow[ch]) * ldb + k0 + gcol[ch]) : z4;
            }
        }
        int st = it & 1;
        const uint32_t* Au = (const uint32_t*)(Sa + st * TILEF);
        const uint32_t* Bu = (const uint32_t*)(Sb + st * TILEF);
#pragma unroll
        for (int ks = 0; ks < 4; ks++) {
            int k0 = ks * 8;
            uint32_t af[4][4], bf[4][2];
#pragma unroll
            for (int mt = 0; mt < 4; mt++) {
                int m = wy * 64 + mt * 16 + lr;
                af[mt][0] = Au[m * LDP + k0 + lk];
                af[mt][1] = Au[(m + 8) * LDP + k0 + lk];
                af[mt][2] = Au[m * LDP + k0 + 4 + lk];
                af[mt][3] = Au[(m + 8) * LDP + k0 + 4 + lk];
            }
#pragma unroll
            for (int nt = 0; nt < 4; nt++) {
                int n = wx * 32 + nt * 8 + lr;
                bf[nt][0] = Bu[n * LDP + k0 + lk];
                bf[nt][1] = Bu[n * LDP + k0 + 4 + lk];
            }
#pragma unroll
            for (int mt = 0; mt < 4; mt++)
#pragma unroll
                for (int nt = 0; nt < 4; nt++)
                    mma8(acc[mt][nt], af[mt], bf[nt]);
        }
        if (it + 1 < NT) {
            int ns = (it + 1) & 1;
#pragma unroll
            for (int ch = 0; ch < 4; ch++) {
                uint32_t* pa = (uint32_t*)(Sa + ns * TILEF + grow[ch] * LDP + gcol[ch]);
                pa[0] = f2tf32(fa[ch].x); pa[1] = f2tf32(fa[ch].y); pa[2] = f2tf32(fa[ch].z); pa[3] = f2tf32(fa[ch].w);
                uint32_t* pb = (uint32_t*)(Sb + ns * TILEF + grow[ch] * LDP + gcol[ch]);
                pb[0] = f2tf32(fb[ch].x); pb[1] = f2tf32(fb[ch].y); pb[2] = f2tf32(fb[ch].z); pb[3] = f2tf32(fb[ch].w);
            }
            __syncthreads();
        }
    }

    // epilogue
    bool doacc = (flags & 1) != 0;
#pragma unroll
    for (int mt = 0; mt < 4; mt++) {
        int m0 = by * 128 + wy * 64 + mt * 16 + lr;
#pragma unroll
        for (int nt = 0; nt < 4; nt++) {
            int c0 = bx * 128 + wx * 32 + nt * 8 + 2 * lk;
            if (c0 < N) {
                float* p0 = C + (long)m0 * ldc + c0;
                float* p1 = C + (long)(m0 + 8) * ldc + c0;
                float2 v0 = make_float2(acc[mt][nt][0], acc[mt][nt][1]);
                float2 v1 = make_float2(acc[mt][nt][2], acc[mt][nt][3]);
                if (doacc) {
                    float2 o0 = *(const float2*)p0, o1 = *(const float2*)p1;
                    v0.x += o0.x; v0.y += o0.y; v1.x += o1.x; v1.y += o1.y;
                }
                *(float2*)p0 = v0;
                *(float2*)p1 = v1;
            }
        }
    }
}

// ---------------- reductions ----------------
__device__ __forceinline__ float warpSum(float v) {
#pragma unroll
    for (int o = 16; o; o >>= 1) v += __shfl_xor_sync(0xffffffffu, v, o);
    return v;
}
__device__ __forceinline__ float warpMax(float v) {
#pragma unroll
    for (int o = 16; o; o >>= 1) v = fmaxf(v, __shfl_xor_sync(0xffffffffu, v, o));
    return v;
}

// ---------------- rmsnorm ----------------
__global__ void rmsnorm_k(const float* __restrict__ x, const float* __restrict__ w,
                          float* __restrict__ y, int D, int ldx, int ldy)
{
    long t = blockIdx.x;
    const float* xr = x + t * ldx;
    float* yr = y + t * ldy;
    float s = 0.f;
    for (int d = threadIdx.x; d < D; d += blockDim.x) { float v = xr[d]; s += v * v; }
    __shared__ float sh[32];
    __shared__ float bc;
    s = warpSum(s);
    int lane = threadIdx.x & 31, wp = threadIdx.x >> 5;
    if (!lane) sh[wp] = s;
    __syncthreads();
    if (threadIdx.x < 32) {
        float r = (threadIdx.x < (blockDim.x >> 5)) ? sh[threadIdx.x] : 0.f;
        r = warpSum(r);
        if (!threadIdx.x) bc = rsqrtf(r / D + 1e-6f);
    }
    __syncthreads();
    float sc = bc;
    for (int d = threadIdx.x; d < D; d += blockDim.x) yr[d] = xr[d] * sc * w[d];
}

// ---------------- rope on k_pe ----------------
__global__ void rope_kpe_k(const float* __restrict__ kv, const float* __restrict__ fc,
                           const float* __restrict__ fs, float* __restrict__ kpe)
{
    long t = blockIdx.x;
    int j = threadIdx.x;
    int pos = (int)(t % Sn);
    float x1 = kv[t * KVAP + KVRn + 2 * j];
    float x2 = kv[t * KVAP + KVRn + 2 * j + 1];
    float c = fc[pos * 32 + j], s = fs[pos * 32 + j];
    kpe[t * ROPEn + 2 * j]     = x1 * c - x2 * s;
    kpe[t * ROPEn + 2 * j + 1] = x1 * s + x2 * c;
}

// ---------------- rope + scale on q ----------------
__global__ void ropescale_q_k(float* __restrict__ q, const float* __restrict__ fc,
                              const float* __restrict__ fs)
{
    long th = blockIdx.x;
    int pos = (int)((th >> 4) % Sn);
    float* r = q + th * QDn;
    int i = threadIdx.x;
    const float sc = 0.07216878364870322f;   // 1/sqrt(192)
    if (i < 64) {
        r[2 * i]     *= sc;
        r[2 * i + 1] *= sc;
    } else {
        int j = i - 64;
        float x1 = r[128 + 2 * j], x2 = r[128 + 2 * j + 1];
        float c = fc[pos * 32 + j], s = fs[pos * 32 + j];
        r[128 + 2 * j]     = (x1 * c - x2 * s) * sc;
        r[128 + 2 * j + 1] = (x1 * s + x2 * c) * sc;
    }
}

// ---------------- build [k_nope | k_pe] concat ----------------
__global__ void kcat_k(const float* __restrict__ kvb, const float* __restrict__ kpe,
                       float* __restrict__ kcat)
{
    int s = blockIdx.x, z = blockIdx.y, j = threadIdx.x;
    long t = (long)(z >> 4) * Sn + s;
    float v = (j < NOPEn) ? kvb[t * KVBP + (z & 15) * 256 + j]
                          : kpe[t * ROPEn + (j - NOPEn)];
    kcat[((long)z * Sn + s) * QDn + j] = v;
}

// ---------------- transpose V -> vT[z][d][k] ----------------
__global__ void vtrans_k(const float* __restrict__ kvb, float* __restrict__ vT)
{
    __shared__ float tsm[32][33];
    int z = blockIdx.z, zb = z >> 4, zh = z & 15;
    int kt = blockIdx.x * 32, dt = blockIdx.y * 32;
    int tx = threadIdx.x, ty = threadIdx.y;
#pragma unroll
    for (int i = 0; i < 4; i++) {
        int k = kt + ty + i * 8;
        tsm[ty + i * 8][tx] = kvb[((long)zb * Sn + k) * KVBP + zh * 256 + NOPEn + dt + tx];
    }
    __syncthreads();
#pragma unroll
    for (int i = 0; i < 4; i++) {
        int d = dt + ty + i * 8;
        vT[((long)z * VHn + d) * Sn + kt + tx] = tsm[tx][ty + i * 8];
    }
}

// ---------------- causal softmax ----------------
__global__ void softmax_causal_k(float* __restrict__ scores)
{
    long rowi = blockIdx.x;
    int q = (int)(rowi % Sn);
    float* p = scores + rowi * Sn;
    int n = q + 1;
    float m = -3.4e38f;
    for (int k = threadIdx.x; k < n; k += blockDim.x) m = fmaxf(m, p[k]);
    __shared__ float shm[32];
    __shared__ float bc0, bc1;
    m = warpMax(m);
    int lane = threadIdx.x & 31, wp = threadIdx.x >> 5;
    if (!lane) shm[wp] = m;
    __syncthreads();
    if (threadIdx.x < 32) {
        float r = (threadIdx.x < (blockDim.x >> 5)) ? shm[threadIdx.x] : -3.4e38f;
        r = warpMax(r);
        if (!threadIdx.x) bc0 = r;
    }
    __syncthreads();
    m = bc0;
    float sum = 0.f;
    for (int k = threadIdx.x; k < n; k += blockDim.x) {
        float e = expf(p[k] - m);
        p[k] = e;
        sum += e;
    }
    __syncthreads();
    sum = warpSum(sum);
    if (!lane) shm[wp] = sum;
    __syncthreads();
    if (threadIdx.x < 32) {
        float r = (threadIdx.x < (blockDim.x >> 5)) ? shm[threadIdx.x] : 0.f;
        r = warpSum(r);
        if (!threadIdx.x) bc1 = 1.f / r;
    }
    __syncthreads();
    float inv = bc1;
    for (int k = threadIdx.x; k < n; k += blockDim.x) p[k] *= inv;
    for (int k = n + threadIdx.x; k < Sn; k += blockDim.x) p[k] = 0.f;
}

// ---------------- router ----------------
__global__ void router_k(const float* __restrict__ nh, const float* __restrict__ rw,
                         int* __restrict__ counts, int* __restrict__ bucket_ts,
                         float* __restrict__ bucket_gate)
{
    long t = blockIdx.x;
    int wp = threadIdx.x >> 5, lane = threadIdx.x & 31;
    const float* xr = nh + t * DIMn;
    float s = 0.f;
    for (int d = lane; d < DIMn; d += 32) s += xr[d] * rw[(long)wp * DIMn + d];
    s = warpSum(s);
    __shared__ float logit[NEn];
    if (!lane) logit[wp] = s;
    __syncthreads();
    if (threadIdx.x == 0) {
        float mx = logit[0];
#pragma unroll
        for (int e = 1; e < NEn; e++) mx = fmaxf(mx, logit[e]);
        float p[NEn];
#pragma unroll
        for (int e = 0; e < NEn; e++) p[e] = expf(logit[e] - mx);
        int i0 = 0;
#pragma unroll
        for (int e = 1; e < NEn; e++) if (p[e] > p[i0]) i0 = e;
        int i1 = (i0 == 0) ? 1 : 0;
#pragma unroll
        for (int e = 0; e < NEn; e++) if (e != i0 && p[e] > p[i1]) i1 = e;
        float denom = p[i0] + p[i1];
        float g0 = p[i0] / denom, g1 = p[i1] / denom;
        int pos0 = atomicAdd(&counts[i0], 1);
        bucket_ts[i0 * Tn + pos0] = (int)(t * 2);
        bucket_gate[i0 * Tn + pos0] = g0;
        int pos1 = atomicAdd(&counts[i1], 1);
        bucket_ts[i1 * Tn + pos1] = (int)(t * 2 + 1);
        bucket_gate[i1 * Tn + pos1] = g1;
    }
}

__global__ void offsets_k(const int* __restrict__ counts, int* __restrict__ off,
                          int* __restrict__ tile_expert)
{
    for (int tl = 0; tl < MOE_TILES; tl++) tile_expert[tl] = -1;
    int o = 0;
    for (int e = 0; e < NEn; e++) {
        off[e] = o;
        int nt = (counts[e] + 127) >> 7;
        for (int i = 0; i < nt; i++) tile_expert[(o >> 7) + i] = e;
        o += nt * 128;
    }
    off[NEn] = o;
}

__global__ void compact_k(const int* __restrict__ counts, const int* __restrict__ off,
                          const int* __restrict__ bucket_ts, const float* __restrict__ bucket_gate,
                          int* __restrict__ flat_tok, int* __restrict__ tok2row,
                          float* __restrict__ tok2gate)
{
    int e = blockIdx.x;
    int cnt = counts[e], base = off[e];
    for (int i = threadIdx.x; i < cnt; i += blockDim.x) {
        int ts = bucket_ts[e * Tn + i];
        int r = base + i;
        flat_tok[r] = ts >> 1;
        tok2row[ts] = r;
        tok2gate[ts] = bucket_gate[e * Tn + i];
    }
}

__global__ void gather_k(const float* __restrict__ nh, const int* __restrict__ flat_tok,
                         float* __restrict__ xg)
{
    long r = blockIdx.x;
    int t = flat_tok[r];
    float4* dst = (float4*)(xg + r * DIMn);
    if (t < 0) {
        float4 zz = make_float4(0.f, 0.f, 0.f, 0.f);
        for (int i = threadIdx.x; i < DIMn / 4; i += blockDim.x) dst[i] = zz;
    } else {
        const float4* src = (const float4*)(nh + (long)t * DIMn);
        for (int i = threadIdx.x; i < DIMn / 4; i += blockDim.x) dst[i] = src[i];
    }
}

__global__ void silumul_k(float* __restrict__ a, const float* __restrict__ b, long n)
{
    long i = (long)blockIdx.x * blockDim.x + threadIdx.x;
    if (i < n) {
        float x = a[i];
        float s = x / (1.f + expf(-x));
        a[i] = s * b[i];
    }
}

__global__ void combine_k(const float* __restrict__ h, const float* __restrict__ sh,
                          const float* __restrict__ eo, const int* __restrict__ tok2row,
                          const float* __restrict__ tok2gate, float* __restrict__ out)
{
    long t = blockIdx.x;
    int r0 = tok2row[t * 2], r1 = tok2row[t * 2 + 1];
    float g0 = tok2gate[t * 2], g1 = tok2gate[t * 2 + 1];
    const float4* H = (const float4*)(h + t * DIMn);
    const float4* SH = (const float4*)(sh + t * DIMn);
    const float4* E0 = (const float4*)(eo + (long)r0 * DIMn);
    const float4* E1 = (const float4*)(eo + (long)r1 * DIMn);
    float4* O = (float4*)(out + t * DIMn);
    for (int i = threadIdx.x; i < DIMn / 4; i += blockDim.x) {
        float4 a = H[i], b = SH[i], c = E0[i], d = E1[i];
        float4 o;
        o.x = a.x + b.x + g0 * c.x + g1 * d.x;
        o.y = a.y + b.y + g0 * c.y + g1 * d.y;
        o.z = a.z + b.z + g0 * c.z + g1 * d.z;
        o.w = a.w + b.w + g0 * c.w + g1 * d.w;
        O[i] = o;
    }
}

// ---------------- host ----------------
#define SYM(p, s) do { void* _q = nullptr; cudaGetSymbolAddress(&_q, s); p = (decltype(p))_q; } while (0)

static void launch_tgemm(const float* A, const float* B, float* C,
                         int M, int N, int K, int lda, int ldb, int ldc,
                         long sA0, long sA1, long sB0, long sB1, long sC0, long sC1,
                         int ZH, int Z, const int* tileExpert, long wStride, int flags)
{
    dim3 grid((N + 127) / 128, M / 128, Z);
    tgemm_k<<<grid, 256, TG_SMEM>>>(A, B, C, M, N, K, lda, ldb, ldc,
                                    sA0, sA1, sB0, sB1, sC0, sC1, ZH,
                                    tileExpert, wStride, flags);
}

extern "C" void kernel_launch(void* const* d_in, const int* in_sizes, int n_in,
                              void* d_out, int out_size)
{
    cudaFuncSetAttribute(tgemm_k, cudaFuncAttributeMaxDynamicSharedMemorySize, TG_SMEM);

    const float* x       = (const float*)d_in[0];
    const float* fcos    = (const float*)d_in[1];
    const float* fsin    = (const float*)d_in[2];
    const float* attn_w  = (const float*)d_in[3];
    const float* wq      = (const float*)d_in[4];
    const float* wkv_a   = (const float*)d_in[5];
    const float* kv_w    = (const float*)d_in[6];
    const float* wkv_b   = (const float*)d_in[7];
    const float* wo      = (const float*)d_in[8];
    const float* ffn_w   = (const float*)d_in[9];
    const float* rw      = (const float*)d_in[10];
    const float* e_w1    = (const float*)d_in[11];
    const float* e_w3    = (const float*)d_in[12];
    const float* e_w2    = (const float*)d_in[13];
    const float* s_w1    = (const float*)d_in[14];
    const float* s_w3    = (const float*)d_in[15];
    const float* s_w2    = (const float*)d_in[16];
    float* out = (float*)d_out;

    float *nx, *q, *kv, *ckv, *kpe, *kvb, *kcat, *vT, *scores, *attn, *h, *nh;
    float *xg, *t1, *t3, *eo, *s1, *s3, *sh;
    int *counts, *off, *tile_expert, *bucket_ts, *flat_tok, *tok2row;
    float *bucket_gate, *tok2gate;
    SYM(nx, g_nx); SYM(q, g_q); SYM(kv, g_kv); SYM(ckv, g_ckv); SYM(kpe, g_kpe);
    SYM(kvb, g_kvb); SYM(kcat, g_kcat); SYM(vT, g_vT); SYM(scores, g_scores);
    SYM(attn, g_attn); SYM(h, g_h); SYM(nh, g_nh);
    SYM(xg, g_xg); SYM(t1, g_t1); SYM(t3, g_t3); SYM(eo, g_eo);
    SYM(s1, g_s1); SYM(s3, g_s3); SYM(sh, g_sh);
    SYM(counts, g_counts); SYM(off, g_off); SYM(tile_expert, g_tile_expert);
    SYM(bucket_ts, g_bucket_ts); SYM(bucket_gate, g_bucket_gate);
    SYM(flat_tok, g_flat_tok); SYM(tok2row, g_tok2row); SYM(tok2gate, g_tok2gate);

    const long SS = (long)Sn * Sn;

    // 1. attention-input rmsnorm
    rmsnorm_k<<<Tn, 256>>>(x, attn_w, nx, DIMn, DIMn, DIMn);
    // 2. q projection
    launch_tgemm(nx, wq, q, Tn, QPROJ, DIMn, DIMn, DIMn, QPROJ,
                 0, 0, 0, 0, 0, 0, 1, 1, nullptr, 0, 0);
    // 3. kv_a projection
    launch_tgemm(nx, wkv_a, kv, Tn, KVAP, DIMn, DIMn, DIMn, KVAP,
                 0, 0, 0, 0, 0, 0, 1, 1, nullptr, 0, 0);
    // 4. c_kv rmsnorm
    rmsnorm_k<<<Tn, 256>>>(kv, kv_w, ckv, KVRn, KVAP, KVRn);
    // 5. rope k_pe
    rope_kpe_k<<<Tn, 32>>>(kv, fcos, fsin, kpe);
    // 6. kv_b projection
    launch_tgemm(ckv, wkv_b, kvb, Tn, KVBP, KVRn, KVRn, KVRn, KVBP,
                 0, 0, 0, 0, 0, 0, 1, 1, nullptr, 0, 0);
    // 7. rope + scale q
    ropescale_q_k<<<Tn * NHn, 96>>>(q, fcos, fsin);
    // 8. kcat + vT
    { dim3 g(Sn, ZSn); kcat_k<<<g, QDn>>>(kvb, kpe, kcat); }
    { dim3 g(Sn / 32, VHn / 32, ZSn); dim3 b(32, 8); vtrans_k<<<g, b>>>(kvb, vT); }
    // 9. scores = [q_nope|q_pe] @ kcat^T   (K=192, causal tile skip)
    launch_tgemm(q, kcat, scores, Sn, Sn, QDn, QPROJ, QDn, Sn,
                 (long)Sn * QPROJ, QDn, 16L * Sn * QDn, (long)Sn * QDn, 16 * SS, SS,
                 16, 32, nullptr, 0, 2);
    // 10. softmax
    softmax_causal_k<<<32 * Sn, 256>>>(scores);
    // 11. attn = P @ V   (vT K-major, causal K-limit)
    launch_tgemm(scores, vT, attn, Sn, VHn, Sn, Sn, Sn, DIMn,
                 16 * SS, SS, 16L * VHn * Sn, (long)VHn * Sn, (long)Sn * DIMn, VHn,
                 16, 32, nullptr, 0, 4);
    // 12. h = x + attn @ wo^T
    cudaMemcpyAsync(h, x, (size_t)Tn * DIMn * sizeof(float), cudaMemcpyDeviceToDevice, 0);
    launch_tgemm(attn, wo, h, Tn, DIMn, DIMn, DIMn, DIMn, DIMn,
                 0, 0, 0, 0, 0, 0, 1, 1, nullptr, 0, 1);
    // 13. ffn rmsnorm
    rmsnorm_k<<<Tn, 256>>>(h, ffn_w, nh, DIMn, DIMn, DIMn);
    // 14. routing
    cudaMemsetAsync(counts, 0, NEn * sizeof(int), 0);
    cudaMemsetAsync(flat_tok, 0xFF, MOE_ROWS * sizeof(int), 0);
    router_k<<<Tn, 256>>>(nh, rw, counts, bucket_ts, bucket_gate);
    offsets_k<<<1, 1>>>(counts, off, tile_expert);
    compact_k<<<NEn, 256>>>(counts, off, bucket_ts, bucket_gate, flat_tok, tok2row, tok2gate);
    gather_k<<<MOE_ROWS, 256>>>(nh, flat_tok, xg);
    // 15. expert FFN (grouped GEMM via tile->expert indirection)
    launch_tgemm(xg, e_w1, t1, MOE_ROWS, MINTERn, DIMn, DIMn, DIMn, MINTERn,
                 0, 0, 0, 0, 0, 0, 1, 1, tile_expert, (long)MINTERn * DIMn, 0);
    launch_tgemm(xg, e_w3, t3, MOE_ROWS, MINTERn, DIMn, DIMn, DIMn, MINTERn,
                 0, 0, 0, 0, 0, 0, 1, 1, tile_expert, (long)MINTERn * DIMn, 0);
    {
        long n = (long)MOE_ROWS * MINTERn;
        silumul_k<<<(int)((n + 255) / 256), 256>>>(t1, t3, n);
    }
    launch_tgemm(t1, e_w2, eo, MOE_ROWS, DIMn, MINTERn, MINTERn, MINTERn, DIMn,
                 0, 0, 0, 0, 0, 0, 1, 1, tile_expert, (long)DIMn * MINTERn, 0);
    // 16. shared FFN
    launch_tgemm(nh, s_w1, s1, Tn, SHIn, DIMn, DIMn, DIMn, SHIn,
                 0, 0, 0, 0, 0, 0, 1, 1, nullptr, 0, 0);
    launch_tgemm(nh, s_w3, s3, Tn, SHIn, DIMn, DIMn, DIMn, SHIn,
                 0, 0, 0, 0, 0, 0, 1, 1, nullptr, 0, 0);
    {
        long n = (long)Tn * SHIn;
        silumul_k<<<(int)((n + 255) / 256), 256>>>(s1, s3, n);
    }
    launch_tgemm(s1, s_w2, sh, Tn, DIMn, SHIn, SHIn, SHIn, DIMn,
                 0, 0, 0, 0, 0, 0, 1, 1, nullptr, 0, 0);
    // 17. combine
    combine_k<<<Tn, 256>>>(h, sh, eo, tok2row, tok2gate, out);
}

// round 5
// speedup vs baseline: 3.4932x; 1.1058x over previous
#include <cuda_runtime.h>
#include <cuda_bf16.h>
#include <math.h>
#include <stdint.h>

// ---------------- problem constants ----------------
#define Tn     4096
#define Sn     2048
#define DIMn   2048
#define NHn    16
#define NOPEn  128
#define ROPEn  64
#define QDn    192
#define VHn    128
#define KVRn   512
#define NEn    8
#define MINTERn 1408
#define SHIn   2816
#define QPROJ  3072
#define KVAP   576
#define KVBP   4096
#define MOE_ROWS 9216
#define MOE_TILES 72
#define ZSn    32

// ---------------- scratch ----------------
__device__ float g_nx[Tn*DIMn];
__device__ float g_q[Tn*QPROJ];
__device__ float g_kv[Tn*KVAP];
__device__ float g_ckv[Tn*KVRn];
__device__ float g_kpe[Tn*ROPEn];
__device__ float g_kvb[(size_t)Tn*KVBP];
__device__ float g_kcat[(size_t)ZSn*Sn*QDn];
__device__ float g_vT[(size_t)ZSn*VHn*Sn];
__device__ float g_scores[134217728];
__device__ float g_inv[ZSn*Sn];
__device__ float g_attn[Tn*DIMn];
__device__ float g_h[Tn*DIMn];
__device__ float g_nh[Tn*DIMn];
__device__ float g_xg[(size_t)MOE_ROWS*DIMn];
__device__ float g_t1[(size_t)MOE_ROWS*MINTERn];
__device__ float g_t3[(size_t)MOE_ROWS*MINTERn];
__device__ float g_eo[(size_t)MOE_ROWS*DIMn];
__device__ float g_s1[(size_t)Tn*SHIn];
__device__ float g_s3[(size_t)Tn*SHIn];
__device__ float g_sh[Tn*DIMn];
__device__ int   g_counts[NEn];
__device__ int   g_off[NEn+1];
__device__ int   g_tile_expert[MOE_TILES];
__device__ int   g_bucket_ts[NEn*Tn];
__device__ float g_bucket_gate[NEn*Tn];
__device__ int   g_flat_tok[MOE_ROWS];
__device__ int   g_tok2row[Tn*2];
__device__ float g_tok2gate[Tn*2];
// tf32-rounded weight copies
__device__ float g_wq_r[(size_t)QPROJ*DIMn];
__device__ float g_wkva_r[(size_t)KVAP*DIMn];
__device__ float g_wkvb_r[(size_t)KVBP*KVRn];
__device__ float g_wo_r[(size_t)DIMn*2048];
__device__ float g_ew1_r[(size_t)NEn*MINTERn*DIMn];
__device__ float g_ew3_r[(size_t)NEn*MINTERn*DIMn];
__device__ float g_ew2_r[(size_t)NEn*DIMn*MINTERn];
__device__ float g_sw1_r[(size_t)SHIn*DIMn];
__device__ float g_sw3_r[(size_t)SHIn*DIMn];
__device__ float g_sw2_r[(size_t)DIMn*SHIn];

// ---------------- helpers ----------------
__device__ __forceinline__ uint32_t f2tf32(float x) {
    uint32_t r; asm("cvt.rna.tf32.f32 %0, %1;" : "=r"(r) : "f"(x)); return r;
}
__device__ __forceinline__ float rndtf(float x) { return __uint_as_float(f2tf32(x)); }
__device__ __forceinline__ void mma8(float* c, const uint32_t* a, const uint32_t* b) {
    asm volatile("mma.sync.aligned.m16n8k8.row.col.f32.tf32.tf32.f32 "
        "{%0,%1,%2,%3}, {%4,%5,%6,%7}, {%8,%9}, {%0,%1,%2,%3};"
        : "+f"(c[0]), "+f"(c[1]), "+f"(c[2]), "+f"(c[3])
        : "r"(a[0]), "r"(a[1]), "r"(a[2]), "r"(a[3]), "r"(b[0]), "r"(b[1]));
}
__device__ __forceinline__ void cpasync16(uint32_t dst, const void* src, int sz) {
    asm volatile("cp.async.cg.shared.global [%0], [%1], 16, %2;"
                 :: "r"(dst), "l"(src), "r"(sz));
}
__device__ __forceinline__ void cpcommit() { asm volatile("cp.async.commit_group;"); }
__device__ __forceinline__ void cpwait1() { asm volatile("cp.async.wait_group 1;"); }

// ---------------- generic tf32 tensor GEMM (cp.async 3-stage) ----------------
// C[M,N] = A[M,K] @ B[N,K]^T, K-major, batched over blockIdx.z.
// Inputs MUST be tf32-rounded in gmem. M%128==0, K%32==0.
// flags: 1 accumulate, 2 causal tile skip, 4 causal K-limit, 8 round output
#define LDP 36
#define ABYTES (128*LDP*4)

template<int TNW>
__global__ __launch_bounds__(256) void tgemm_k(
    const float* __restrict__ A, const float* __restrict__ B, float* __restrict__ C,
    int M, int N, int K, int lda, int ldb, int ldc,
    long sA0, long sA1, long sB0, long sB1, long sC0, long sC1, int ZH,
    const int* __restrict__ tileExpert, long wStride,
    const float* __restrict__ rowscale, long rsStride, int flags)
{
    constexpr int NTT = TNW / 32;            // per-warp n subtiles (4 or 8)
    constexpr int BBYTES = TNW * LDP * 4;
    constexpr int STAGEB = ABYTES + BBYTES;
    constexpr int BCH = TNW / 32;            // B float4 chunks per thread (4 or 8)

    int bx = blockIdx.x, by = blockIdx.y, z = blockIdx.z;
    if ((flags & 2) && (long)bx * TNW > (long)by * 128 + 127) return;
    if (tileExpert) { int te = tileExpert[by]; if (te < 0) return; B += (long)te * wStride; }
    int zb = z / ZH, zh = z - zb * ZH;
    A += zb * sA0 + (long)zh * sA1;
    B += zb * sB0 + (long)zh * sB1;
    C += zb * sC0 + (long)zh * sC1;
    int Keff = K;
    if (flags & 4) { int kl = (by + 1) * 128; if (kl < Keff) Keff = kl; }
    int NT = Keff >> 5;

    extern __shared__ char smraw[];
    uint32_t sb = (uint32_t)__cvta_generic_to_shared(smraw);

    int tid = threadIdx.x;
    int wid = tid >> 5, lane = tid & 31;
    int wy = wid & 1, wx = wid >> 1;
    int lr = lane >> 2, lk = lane & 3;

    // cp.async mapping
    int arow[4], acq[4];
#pragma unroll
    for (int ch = 0; ch < 4; ch++) {
        int idx = tid + ch * 256;
        arow[ch] = idx >> 3; acq[ch] = (idx & 7) * 4;
    }
    int brow[BCH], bcq[BCH], bsz[BCH];
    const float* bsrc0 = B;
#pragma unroll
    for (int ch = 0; ch < BCH; ch++) {
        int idx = tid + ch * 256;
        brow[ch] = idx >> 3; bcq[ch] = (idx & 7) * 4;
        bsz[ch] = ((bx * TNW + brow[ch]) < N) ? 16 : 0;
    }

    auto issue = [&](int s, int k0) {
        uint32_t Ab = sb + s * STAGEB;
        uint32_t Bb = Ab + ABYTES;
#pragma unroll
        for (int ch = 0; ch < 4; ch++) {
            const float* src = A + (long)(by * 128 + arow[ch]) * lda + k0 + acq[ch];
            cpasync16(Ab + arow[ch] * (LDP*4) + acq[ch] * 4, src, 16);
        }
#pragma unroll
        for (int ch = 0; ch < BCH; ch++) {
            const float* src = bsz[ch] ? (B + (long)(bx * TNW + brow[ch]) * ldb + k0 + bcq[ch]) : bsrc0;
            cpasync16(Bb + brow[ch] * (LDP*4) + bcq[ch] * 4, src, bsz[ch]);
        }
    };

    // prologue: stages 0,1
#pragma unroll
    for (int s = 0; s < 2; s++) {
        if (s < NT) issue(s, s * 32);
        cpcommit();
    }

    float acc[4][NTT][4];
#pragma unroll
    for (int mt = 0; mt < 4; mt++)
#pragma unroll
        for (int nt = 0; nt < NTT; nt++)
#pragma unroll
            for (int i = 0; i < 4; i++) acc[mt][nt][i] = 0.f;

    for (int it = 0; it < NT; ++it) {
        cpwait1();
        __syncthreads();
        // issue stage it+2
        if (it + 2 < NT) issue((it + 2) % 3, (it + 2) * 32);
        cpcommit();

        int st = it % 3;
        const uint32_t* Au = (const uint32_t*)(smraw + st * STAGEB);
        const uint32_t* Bu = (const uint32_t*)(smraw + st * STAGEB + ABYTES);
#pragma unroll
        for (int ks = 0; ks < 4; ks++) {
            int k0 = ks * 8;
            uint32_t af[4][4], bf[NTT][2];
#pragma unroll
            for (int mt = 0; mt < 4; mt++) {
                int m = wy * 64 + mt * 16 + lr;
                af[mt][0] = Au[m * LDP + k0 + lk];
                af[mt][1] = Au[(m + 8) * LDP + k0 + lk];
                af[mt][2] = Au[m * LDP + k0 + 4 + lk];
                af[mt][3] = Au[(m + 8) * LDP + k0 + 4 + lk];
            }
#pragma unroll
            for (int nt = 0; nt < NTT; nt++) {
                int n = wx * (TNW / 4) + nt * 8 + lr;
                bf[nt][0] = Bu[n * LDP + k0 + lk];
                bf[nt][1] = Bu[n * LDP + k0 + 4 + lk];
            }
#pragma unroll
            for (int mt = 0; mt < 4; mt++)
#pragma unroll
                for (int nt = 0; nt < NTT; nt++)
                    mma8(acc[mt][nt], af[mt], bf[nt]);
        }
        __syncthreads();
    }

    // epilogue
    bool doacc = (flags & 1) != 0;
    bool dornd = (flags & 8) != 0;
    long zr = (long)z * rsStride;
#pragma unroll
    for (int mt = 0; mt < 4; mt++) {
        int m0 = by * 128 + wy * 64 + mt * 16 + lr;
        float rs0 = 1.f, rs1 = 1.f;
        if (rowscale) { rs0 = rowscale[zr + m0]; rs1 = rowscale[zr + m0 + 8]; }
#pragma unroll
        for (int nt = 0; nt < NTT; nt++) {
            int c0 = bx * TNW + wx * (TNW / 4) + nt * 8 + 2 * lk;
            if (c0 < N) {
                float* p0 = C + (long)m0 * ldc + c0;
                float* p1 = C + (long)(m0 + 8) * ldc + c0;
                float2 v0 = make_float2(acc[mt][nt][0] * rs0, acc[mt][nt][1] * rs0);
                float2 v1 = make_float2(acc[mt][nt][2] * rs1, acc[mt][nt][3] * rs1);
                if (doacc) {
                    float2 o0 = *(const float2*)p0, o1 = *(const float2*)p1;
                    v0.x += o0.x; v0.y += o0.y; v1.x += o1.x; v1.y += o1.y;
                }
                if (dornd) {
                    v0.x = rndtf(v0.x); v0.y = rndtf(v0.y);
                    v1.x = rndtf(v1.x); v1.y = rndtf(v1.y);
                }
                *(float2*)p0 = v0;
                *(float2*)p1 = v1;
            }
        }
    }
}

// ---------------- elementwise tf32 round (weights) ----------------
__global__ void rnd_k(const float4* __restrict__ src, float4* __restrict__ dst, long n4)
{
    long i = (long)blockIdx.x * blockDim.x + threadIdx.x;
    if (i < n4) {
        float4 v = src[i];
        v.x = rndtf(v.x); v.y = rndtf(v.y); v.z = rndtf(v.z); v.w = rndtf(v.w);
        dst[i] = v;
    }
}

// ---------------- reductions ----------------
__device__ __forceinline__ float warpSum(float v) {
#pragma unroll
    for (int o = 16; o; o >>= 1) v += __shfl_xor_sync(0xffffffffu, v, o);
    return v;
}
__device__ __forceinline__ float warpMax(float v) {
#pragma unroll
    for (int o = 16; o; o >>= 1) v = fmaxf(v, __shfl_xor_sync(0xffffffffu, v, o));
    return v;
}

// ---------------- rmsnorm (tf32-rounded output) ----------------
__global__ void rmsnorm_k(const float* __restrict__ x, const float* __restrict__ w,
                          float* __restrict__ y, int D, int ldx, int ldy)
{
    long t = blockIdx.x;
    const float* xr = x + t * ldx;
    float* yr = y + t * ldy;
    float s = 0.f;
    for (int d = threadIdx.x; d < D; d += blockDim.x) { float v = xr[d]; s += v * v; }
    __shared__ float sh[32];
    __shared__ float bc;
    s = warpSum(s);
    int lane = threadIdx.x & 31, wp = threadIdx.x >> 5;
    if (!lane) sh[wp] = s;
    __syncthreads();
    if (threadIdx.x < 32) {
        float r = (threadIdx.x < (blockDim.x >> 5)) ? sh[threadIdx.x] : 0.f;
        r = warpSum(r);
        if (!threadIdx.x) bc = rsqrtf(r / D + 1e-6f);
    }
    __syncthreads();
    float sc = bc;
    for (int d = threadIdx.x; d < D; d += blockDim.x) yr[d] = rndtf(xr[d] * sc * w[d]);
}

// ---------------- rope on k_pe ----------------
__global__ void rope_kpe_k(const float* __restrict__ kv, const float* __restrict__ fc,
                           const float* __restrict__ fs, float* __restrict__ kpe)
{
    long t = blockIdx.x;
    int j = threadIdx.x;
    int pos = (int)(t % Sn);
    float x1 = kv[t * KVAP + KVRn + 2 * j];
    float x2 = kv[t * KVAP + KVRn + 2 * j + 1];
    float c = fc[pos * 32 + j], s = fs[pos * 32 + j];
    kpe[t * ROPEn + 2 * j]     = x1 * c - x2 * s;
    kpe[t * ROPEn + 2 * j + 1] = x1 * s + x2 * c;
}

// ---------------- rope + scale on q (tf32-rounded) ----------------
__global__ void ropescale_q_k(float* __restrict__ q, const float* __restrict__ fc,
                              const float* __restrict__ fs)
{
    long th = blockIdx.x;
    int pos = (int)((th >> 4) % Sn);
    float* r = q + th * QDn;
    int i = threadIdx.x;
    const float sc = 0.07216878364870322f;   // 1/sqrt(192)
    if (i < 64) {
        r[2 * i]     = rndtf(r[2 * i] * sc);
        r[2 * i + 1] = rndtf(r[2 * i + 1] * sc);
    } else {
        int j = i - 64;
        float x1 = r[128 + 2 * j], x2 = r[128 + 2 * j + 1];
        float c = fc[pos * 32 + j], s = fs[pos * 32 + j];
        r[128 + 2 * j]     = rndtf((x1 * c - x2 * s) * sc);
        r[128 + 2 * j + 1] = rndtf((x1 * s + x2 * c) * sc);
    }
}

// ---------------- build [k_nope | k_pe] concat (rounded) ----------------
__global__ void kcat_k(const float* __restrict__ kvb, const float* __restrict__ kpe,
                       float* __restrict__ kcat)
{
    int s = blockIdx.x, z = blockIdx.y, j = threadIdx.x;
    long t = (long)(z >> 4) * Sn + s;
    float v = (j < NOPEn) ? kvb[t * KVBP + (z & 15) * 256 + j]
                          : kpe[t * ROPEn + (j - NOPEn)];
    kcat[((long)z * Sn + s) * QDn + j] = rndtf(v);
}

// ---------------- transpose V -> vT[z][d][k] (rounded) ----------------
__global__ void vtrans_k(const float* __restrict__ kvb, float* __restrict__ vT)
{
    __shared__ float tsm[32][33];
    int z = blockIdx.z, zb = z >> 4, zh = z & 15;
    int kt = blockIdx.x * 32, dt = blockIdx.y * 32;
    int tx = threadIdx.x, ty = threadIdx.y;
#pragma unroll
    for (int i = 0; i < 4; i++) {
        int k = kt + ty + i * 8;
        tsm[ty + i * 8][tx] = kvb[((long)zb * Sn + k) * KVBP + zh * 256 + NOPEn + dt + tx];
    }
    __syncthreads();
#pragma unroll
    for (int i = 0; i < 4; i++) {
        int d = dt + ty + i * 8;
        vT[((long)z * VHn + d) * Sn + kt + tx] = rndtf(tsm[tx][ty + i * 8]);
    }
}

// ---------------- causal softmax: 2-pass, rounded P, invsum out ----------------
__global__ void softmax2_k(float* __restrict__ scores, float* __restrict__ inv)
{
    long rowi = blockIdx.x;
    int q = (int)(rowi % Sn);
    float* p = scores + rowi * Sn;
    int n = q + 1;
    float m = -3.4e38f;
    for (int k = threadIdx.x; k < n; k += blockDim.x) m = fmaxf(m, p[k]);
    __shared__ float shm[32];
    __shared__ float bc0, bc1;
    m = warpMax(m);
    int lane = threadIdx.x & 31, wp = threadIdx.x >> 5;
    if (!lane) shm[wp] = m;
    __syncthreads();
    if (threadIdx.x < 32) {
        float r = (threadIdx.x < (blockDim.x >> 5)) ? shm[threadIdx.x] : -3.4e38f;
        r = warpMax(r);
        if (!threadIdx.x) bc0 = r;
    }
    __syncthreads();
    m = bc0;
    float sum = 0.f;
    for (int k = threadIdx.x; k < n; k += blockDim.x) {
        float e = expf(p[k] - m);
        p[k] = rndtf(e);
        sum += e;
    }
    __syncthreads();
    sum = warpSum(sum);
    if (!lane) shm[wp] = sum;
    __syncthreads();
    if (threadIdx.x < 32) {
        float r = (threadIdx.x < (blockDim.x >> 5)) ? shm[threadIdx.x] : 0.f;
        r = warpSum(r);
        if (!threadIdx.x) { bc1 = 1.f / r; inv[rowi] = 1.f / r; }
    }
    // zero only the diagonal-tile padding (cols n .. tile end)
    int kend = ((q >> 7) + 1) << 7;
    for (int k = n + threadIdx.x; k < kend; k += blockDim.x) p[k] = 0.f;
}

// ---------------- router ----------------
__global__ void router_k(const float* __restrict__ nh, const float* __restrict__ rw,
                         int* __restrict__ counts, int* __restrict__ bucket_ts,
                         float* __restrict__ bucket_gate)
{
    long t = blockIdx.x;
    int wp = threadIdx.x >> 5, lane = threadIdx.x & 31;
    const float* xr = nh + t * DIMn;
    float s = 0.f;
    for (int d = lane; d < DIMn; d += 32) s += xr[d] * rw[(long)wp * DIMn + d];
    s = warpSum(s);
    __shared__ float logit[NEn];
    if (!lane) logit[wp] = s;
    __syncthreads();
    if (threadIdx.x == 0) {
        float mx = logit[0];
#pragma unroll
        for (int e = 1; e < NEn; e++) mx = fmaxf(mx, logit[e]);
        float p[NEn];
#pragma unroll
        for (int e = 0; e < NEn; e++) p[e] = expf(logit[e] - mx);
        int i0 = 0;
#pragma unroll
        for (int e = 1; e < NEn; e++) if (p[e] > p[i0]) i0 = e;
        int i1 = (i0 == 0) ? 1 : 0;
#pragma unroll
        for (int e = 0; e < NEn; e++) if (e != i0 && p[e] > p[i1]) i1 = e;
        float denom = p[i0] + p[i1];
        float g0 = p[i0] / denom, g1 = p[i1] / denom;
        int pos0 = atomicAdd(&counts[i0], 1);
        bucket_ts[i0 * Tn + pos0] = (int)(t * 2);
        bucket_gate[i0 * Tn + pos0] = g0;
        int pos1 = atomicAdd(&counts[i1], 1);
        bucket_ts[i1 * Tn + pos1] = (int)(t * 2 + 1);
        bucket_gate[i1 * Tn + pos1] = g1;
    }
}

__global__ void offsets_k(const int* __restrict__ counts, int* __restrict__ off,
                          int* __restrict__ tile_expert)
{
    for (int tl = 0; tl < MOE_TILES; tl++) tile_expert[tl] = -1;
    int o = 0;
    for (int e = 0; e < NEn; e++) {
        off[e] = o;
        int nt = (counts[e] + 127) >> 7;
        for (int i = 0; i < nt; i++) tile_expert[(o >> 7) + i] = e;
        o += nt * 128;
    }
    off[NEn] = o;
}

__global__ void compact_k(const int* __restrict__ counts, const int* __restrict__ off,
                          const int* __restrict__ bucket_ts, const float* __restrict__ bucket_gate,
                          int* __restrict__ flat_tok, int* __restrict__ tok2row,
                          float* __restrict__ tok2gate)
{
    int e = blockIdx.x;
    int cnt = counts[e], base = off[e];
    for (int i = threadIdx.x; i < cnt; i += blockDim.x) {
        int ts = bucket_ts[e * Tn + i];
        int r = base + i;
        flat_tok[r] = ts >> 1;
        tok2row[ts] = r;
        tok2gate[ts] = bucket_gate[e * Tn + i];
    }
}

__global__ void gather_k(const float* __restrict__ nh, const int* __restrict__ flat_tok,
                         float* __restrict__ xg)
{
    long r = blockIdx.x;
    int t = flat_tok[r];
    float4* dst = (float4*)(xg + r * DIMn);
    if (t < 0) {
        float4 zz = make_float4(0.f, 0.f, 0.f, 0.f);
        for (int i = threadIdx.x; i < DIMn / 4; i += blockDim.x) dst[i] = zz;
    } else {
        const float4* src = (const float4*)(nh + (long)t * DIMn);
        for (int i = threadIdx.x; i < DIMn / 4; i += blockDim.x) dst[i] = src[i];
    }
}

__global__ void silumul_k(float* __restrict__ a, const float* __restrict__ b, long n)
{
    long i = (long)blockIdx.x * blockDim.x + threadIdx.x;
    if (i < n) {
        float x = a[i];
        float s = x / (1.f + expf(-x));
        a[i] = rndtf(s * b[i]);
    }
}

__global__ void combine_k(const float* __restrict__ h, const float* __restrict__ sh,
                          const float* __restrict__ eo, const int* __restrict__ tok2row,
                          const float* __restrict__ tok2gate, float* __restrict__ out)
{
    long t = blockIdx.x;
    int r0 = tok2row[t * 2], r1 = tok2row[t * 2 + 1];
    float g0 = tok2gate[t * 2], g1 = tok2gate[t * 2 + 1];
    const float4* H = (const float4*)(h + t * DIMn);
    const float4* SH = (const float4*)(sh + t * DIMn);
    const float4* E0 = (const float4*)(eo + (long)r0 * DIMn);
    const float4* E1 = (const float4*)(eo + (long)r1 * DIMn);
    float4* O = (float4*)(out + t * DIMn);
    for (int i = threadIdx.x; i < DIMn / 4; i += blockDim.x) {
        float4 a = H[i], b = SH[i], c = E0[i], d = E1[i];
        float4 o;
        o.x = a.x + b.x + g0 * c.x + g1 * d.x;
        o.y = a.y + b.y + g0 * c.y + g1 * d.y;
        o.z = a.z + b.z + g0 * c.z + g1 * d.z;
        o.w = a.w + b.w + g0 * c.w + g1 * d.w;
        O[i] = o;
    }
}

// ---------------- host ----------------
#define SYM(p, s) do { void* _q = nullptr; cudaGetSymbolAddress(&_q, s); p = (decltype(p))_q; } while (0)

static void launch_tgemm(int tnw, const float* A, const float* B, float* C,
                         int M, int N, int K, int lda, int ldb, int ldc,
                         long sA0, long sA1, long sB0, long sB1, long sC0, long sC1,
                         int ZH, int Z, const int* tileExpert, long wStride,
                         const float* rowscale, long rsStride, int flags)
{
    dim3 grid((N + tnw - 1) / tnw, M / 128, Z);
    int smem = 3 * (ABYTES + tnw * LDP * 4);
    if (tnw == 128)
        tgemm_k<128><<<grid, 256, smem>>>(A, B, C, M, N, K, lda, ldb, ldc,
            sA0, sA1, sB0, sB1, sC0, sC1, ZH, tileExpert, wStride, rowscale, rsStride, flags);
    else
        tgemm_k<256><<<grid, 256, smem>>>(A, B, C, M, N, K, lda, ldb, ldc,
            sA0, sA1, sB0, sB1, sC0, sC1, ZH, tileExpert, wStride, rowscale, rsStride, flags);
}

static void launch_rnd(const float* src, float* dst, long n)
{
    long n4 = n / 4;
    rnd_k<<<(int)((n4 + 255) / 256), 256>>>((const float4*)src, (float4*)dst, n4);
}

extern "C" void kernel_launch(void* const* d_in, const int* in_sizes, int n_in,
                              void* d_out, int out_size)
{
    cudaFuncSetAttribute(tgemm_k<128>, cudaFuncAttributeMaxDynamicSharedMemorySize,
                         3 * (ABYTES + 128 * LDP * 4));
    cudaFuncSetAttribute(tgemm_k<256>, cudaFuncAttributeMaxDynamicSharedMemorySize,
                         3 * (ABYTES + 256 * LDP * 4));

    const float* x       = (const float*)d_in[0];
    const float* fcos    = (const float*)d_in[1];
    const float* fsin    = (const float*)d_in[2];
    const float* attn_w  = (const float*)d_in[3];
    const float* wq      = (const float*)d_in[4];
    const float* wkv_a   = (const float*)d_in[5];
    const float* kv_w    = (const float*)d_in[6];
    const float* wkv_b   = (const float*)d_in[7];
    const float* wo      = (const float*)d_in[8];
    const float* ffn_w   = (const float*)d_in[9];
    const float* rw      = (const float*)d_in[10];
    const float* e_w1    = (const float*)d_in[11];
    const float* e_w3    = (const float*)d_in[12];
    const float* e_w2    = (const float*)d_in[13];
    const float* s_w1    = (const float*)d_in[14];
    const float* s_w3    = (const float*)d_in[15];
    const float* s_w2    = (const float*)d_in[16];
    float* out = (float*)d_out;

    float *nx, *q, *kv, *ckv, *kpe, *kvb, *kcat, *vT, *scores, *inv, *attn, *h, *nh;
    float *xg, *t1, *t3, *eo, *s1, *s3, *sh;
    int *counts, *off, *tile_expert, *bucket_ts, *flat_tok, *tok2row;
    float *bucket_gate, *tok2gate;
    float *wq_r, *wkva_r, *wkvb_r, *wo_r, *ew1_r, *ew3_r, *ew2_r, *sw1_r, *sw3_r, *sw2_r;
    SYM(nx, g_nx); SYM(q, g_q); SYM(kv, g_kv); SYM(ckv, g_ckv); SYM(kpe, g_kpe);
    SYM(kvb, g_kvb); SYM(kcat, g_kcat); SYM(vT, g_vT); SYM(scores, g_scores);
    SYM(inv, g_inv); SYM(attn, g_attn); SYM(h, g_h); SYM(nh, g_nh);
    SYM(xg, g_xg); SYM(t1, g_t1); SYM(t3, g_t3); SYM(eo, g_eo);
    SYM(s1, g_s1); SYM(s3, g_s3); SYM(sh, g_sh);
    SYM(counts, g_counts); SYM(off, g_off); SYM(tile_expert, g_tile_expert);
    SYM(bucket_ts, g_bucket_ts); SYM(bucket_gate, g_bucket_gate);
    SYM(flat_tok, g_flat_tok); SYM(tok2row, g_tok2row); SYM(tok2gate, g_tok2gate);
    SYM(wq_r, g_wq_r); SYM(wkva_r, g_wkva_r); SYM(wkvb_r, g_wkvb_r); SYM(wo_r, g_wo_r);
    SYM(ew1_r, g_ew1_r); SYM(ew3_r, g_ew3_r); SYM(ew2_r, g_ew2_r);
    SYM(sw1_r, g_sw1_r); SYM(sw3_r, g_sw3_r); SYM(sw2_r, g_sw2_r);

    const long SS = (long)Sn * Sn;

    // 0. round weights to tf32 copies
    launch_rnd(wq, wq_r, (long)QPROJ * DIMn);
    launch_rnd(wkv_a, wkva_r, (long)KVAP * DIMn);
    launch_rnd(wkv_b, wkvb_r, (long)KVBP * KVRn);
    launch_rnd(wo, wo_r, (long)DIMn * 2048);
    launch_rnd(e_w1, ew1_r, (long)NEn * MINTERn * DIMn);
    launch_rnd(e_w3, ew3_r, (long)NEn * MINTERn * DIMn);
    launch_rnd(e_w2, ew2_r, (long)NEn * DIMn * MINTERn);
    launch_rnd(s_w1, sw1_r, (long)SHIn * DIMn);
    launch_rnd(s_w3, sw3_r, (long)SHIn * DIMn);
    launch_rnd(s_w2, sw2_r, (long)DIMn * SHIn);

    // 1. attention-input rmsnorm (rounded)
    rmsnorm_k<<<Tn, 256>>>(x, attn_w, nx, DIMn, DIMn, DIMn);
    // 2. q projection
    launch_tgemm(256, nx, wq_r, q, Tn, QPROJ, DIMn, DIMn, DIMn, QPROJ,
                 0, 0, 0, 0, 0, 0, 1, 1, nullptr, 0, nullptr, 0, 0);
    // 3. kv_a projection
    launch_tgemm(128, nx, wkva_r, kv, Tn, KVAP, DIMn, DIMn, DIMn, KVAP,
                 0, 0, 0, 0, 0, 0, 1, 1, nullptr, 0, nullptr, 0, 0);
    // 4. c_kv rmsnorm (rounded)
    rmsnorm_k<<<Tn, 256>>>(kv, kv_w, ckv, KVRn, KVAP, KVRn);
    // 5. rope k_pe
    rope_kpe_k<<<Tn, 32>>>(kv, fcos, fsin, kpe);
    // 6. kv_b projection
    launch_tgemm(256, ckv, wkvb_r, kvb, Tn, KVBP, KVRn, KVRn, KVRn, KVBP,
                 0, 0, 0, 0, 0, 0, 1, 1, nullptr, 0, nullptr, 0, 0);
    // 7. rope + scale q (rounded)
    ropescale_q_k<<<Tn * NHn, 96>>>(q, fcos, fsin);
    // 8. kcat + vT (rounded)
    { dim3 g(Sn, ZSn); kcat_k<<<g, QDn>>>(kvb, kpe, kcat); }
    { dim3 g(Sn / 32, VHn / 32, ZSn); dim3 b(32, 8); vtrans_k<<<g, b>>>(kvb, vT); }
    // 9. scores = q @ kcat^T (K=192, causal skip)
    launch_tgemm(256, q, kcat, scores, Sn, Sn, QDn, QPROJ, QDn, Sn,
                 (long)Sn * QPROJ, QDn, 16L * Sn * QDn, (long)Sn * QDn, 16 * SS, SS,
                 16, 32, nullptr, 0, nullptr, 0, 2);
    // 10. softmax (2-pass, pad-zero, invsum)
    softmax2_k<<<32 * Sn, 256>>>(scores, inv);
    // 11. attn = (P @ V) * invsum, rounded (K-limit)
    launch_tgemm(128, scores, vT, attn, Sn, VHn, Sn, Sn, Sn, DIMn,
                 16 * SS, SS, 16L * VHn * Sn, (long)VHn * Sn, (long)Sn * DIMn, VHn,
                 16, 32, nullptr, 0, inv, Sn, 4 | 8);
    // 12. h = x + attn @ wo^T
    cudaMemcpyAsync(h, x, (size_t)Tn * DIMn * sizeof(float), cudaMemcpyDeviceToDevice, 0);
    launch_tgemm(256, attn, wo_r, h, Tn, DIMn, DIMn, DIMn, DIMn, DIMn,
                 0, 0, 0, 0, 0, 0, 1, 1, nullptr, 0, nullptr, 0, 1);
    // 13. ffn rmsnorm (rounded)
    rmsnorm_k<<<Tn, 256>>>(h, ffn_w, nh, DIMn, DIMn, DIMn);
    // 14. routing
    cudaMemsetAsync(counts, 0, NEn * sizeof(int), 0);
    cudaMemsetAsync(flat_tok, 0xFF, MOE_ROWS * sizeof(int), 0);
    router_k<<<Tn, 256>>>(nh, rw, counts, bucket_ts, bucket_gate);
    offsets_k<<<1, 1>>>(counts, off, tile_expert);
    compact_k<<<NEn, 256>>>(counts, off, bucket_ts, bucket_gate, flat_tok, tok2row, tok2gate);
    gather_k<<<MOE_ROWS, 256>>>(nh, flat_tok, xg);
    // 15. expert FFN (grouped)
    launch_tgemm(256, xg, ew1_r, t1, MOE_ROWS, MINTERn, DIMn, DIMn, DIMn, MINTERn,
                 0, 0, 0, 0, 0, 0, 1, 1, tile_expert, (long)MINTERn * DIMn, nullptr, 0, 0);
    launch_tgemm(256, xg, ew3_r, t3, MOE_ROWS, MINTERn, DIMn, DIMn, DIMn, MINTERn,
                 0, 0, 0, 0, 0, 0, 1, 1, tile_expert, (long)MINTERn * DIMn, nullptr, 0, 0);
    {
        long n = (long)MOE_ROWS * MINTERn;
        silumul_k<<<(int)((n + 255) / 256), 256>>>(t1, t3, n);
    }
    launch_tgemm(256, t1, ew2_r, eo, MOE_ROWS, DIMn, MINTERn, MINTERn, MINTERn, DIMn,
                 0, 0, 0, 0, 0, 0, 1, 1, tile_expert, (long)DIMn * MINTERn, nullptr, 0, 0);
    // 16. shared FFN
    launch_tgemm(256, nh, sw1_r, s1, Tn, SHIn, DIMn, DIMn, DIMn, SHIn,
                 0, 0, 0, 0, 0, 0, 1, 1, nullptr, 0, nullptr, 0, 0);
    launch_tgemm(256, nh, sw3_r, s3, Tn, SHIn, DIMn, DIMn, DIMn, SHIn,
                 0, 0, 0, 0, 0, 0, 1, 1, nullptr, 0, nullptr, 0, 0);
    {
        long n = (long)Tn * SHIn;
        silumul_k<<<(int)((n + 255) / 256), 256>>>(s1, s3, n);
    }
    launch_tgemm(256, s1, sw2_r, sh, Tn, DIMn, SHIn, SHIn, SHIn, DIMn,
                 0, 0, 0, 0, 0, 0, 1, 1, nullptr, 0, nullptr, 0, 0);
    // 17. combine
    combine_k<<<Tn, 256>>>(h, sh, eo, tok2row, tok2gate, out);
}

// round 6
// speedup vs baseline: 5.0420x; 1.4434x over previous
#include <cuda_runtime.h>
#include <cuda_fp16.h>
#include <math.h>
#include <stdint.h>

// ---------------- problem constants ----------------
#define Tn     4096
#define Sn     2048
#define DIMn   2048
#define NHn    16
#define NOPEn  128
#define ROPEn  64
#define QDn    192
#define VHn    128
#define KVRn   512
#define NEn    8
#define MINTERn 1408
#define SHIn   2816
#define QPROJ  3072
#define KVAP   576
#define KVBP   4096
#define MOE_ROWS 9216
#define MOE_TILES 72
#define ZSn    32

// ---------------- fp32 scratch ----------------
__device__ float g_q[(size_t)Tn*QPROJ];
__device__ float g_kv[(size_t)Tn*KVAP];
__device__ float g_kpe[(size_t)Tn*ROPEn];
__device__ float g_kvb[(size_t)Tn*KVBP];
__device__ float g_scores[(size_t)ZSn*Sn*Sn];
__device__ float g_inv[ZSn*Sn];
__device__ float g_h[(size_t)Tn*DIMn];
__device__ float g_eo[(size_t)MOE_ROWS*DIMn];
__device__ float g_sh[(size_t)Tn*DIMn];
__device__ int   g_counts[NEn];
__device__ int   g_off[NEn+1];
__device__ int   g_tile_expert[MOE_TILES];
__device__ int   g_bucket_ts[NEn*Tn];
__device__ float g_bucket_gate[NEn*Tn];
__device__ int   g_flat_tok[MOE_ROWS];
__device__ int   g_tok2row[Tn*2];
__device__ float g_tok2gate[Tn*2];
// ---------------- fp16 scratch ----------------
__device__ __half g_nx_h[(size_t)Tn*DIMn];
__device__ __half g_ckv_h[(size_t)Tn*KVRn];
__device__ __half g_qh[(size_t)Tn*QPROJ];
__device__ __half g_kcat_h[(size_t)ZSn*Sn*QDn];
__device__ __half g_vT_h[(size_t)ZSn*VHn*Sn];
__device__ __half g_ph[(size_t)ZSn*Sn*Sn];
__device__ __half g_attn_h[(size_t)Tn*DIMn];
__device__ __half g_nh_h[(size_t)Tn*DIMn];
__device__ __half g_xg_h[(size_t)MOE_ROWS*DIMn];
__device__ __half g_t1h[(size_t)MOE_ROWS*MINTERn];
__device__ __half g_t3h[(size_t)MOE_ROWS*MINTERn];
__device__ __half g_s1h[(size_t)Tn*SHIn];
__device__ __half g_s3h[(size_t)Tn*SHIn];
// fp16 weight copies
__device__ __half g_wq_h[(size_t)QPROJ*DIMn];
__device__ __half g_wkva_h[(size_t)KVAP*DIMn];
__device__ __half g_wkvb_h[(size_t)KVBP*KVRn];
__device__ __half g_wo_h[(size_t)DIMn*DIMn];
__device__ __half g_ew1_h[(size_t)NEn*MINTERn*DIMn];
__device__ __half g_ew3_h[(size_t)NEn*MINTERn*DIMn];
__device__ __half g_ew2_h[(size_t)NEn*DIMn*MINTERn];
__device__ __half g_sw1_h[(size_t)SHIn*DIMn];
__device__ __half g_sw3_h[(size_t)SHIn*DIMn];
__device__ __half g_sw2_h[(size_t)DIMn*SHIn];

// ---------------- helpers ----------------
__device__ __forceinline__ void mma16(float* c, const uint32_t* a, const uint32_t* b) {
    asm volatile("mma.sync.aligned.m16n8k16.row.col.f32.f16.f16.f32 "
        "{%0,%1,%2,%3}, {%4,%5,%6,%7}, {%8,%9}, {%0,%1,%2,%3};"
        : "+f"(c[0]), "+f"(c[1]), "+f"(c[2]), "+f"(c[3])
        : "r"(a[0]), "r"(a[1]), "r"(a[2]), "r"(a[3]), "r"(b[0]), "r"(b[1]));
}
__device__ __forceinline__ void cpasync16(uint32_t dst, const void* src, int sz) {
    asm volatile("cp.async.cg.shared.global [%0], [%1], 16, %2;"
                 :: "r"(dst), "l"(src), "r"(sz));
}
__device__ __forceinline__ void cpcommit() { asm volatile("cp.async.commit_group;"); }
__device__ __forceinline__ void cpwait1() { asm volatile("cp.async.wait_group 1;"); }

// ---------------- generic fp16 tensor GEMM (cp.async 3-stage) ----------------
// C[M,N] = A[M,K] @ B[N,K]^T, K-major fp16 operands, fp32 accumulate.
// M%128==0, K%32==0.
// flags: 1 accumulate(fp32 out), 2 causal tile skip, 4 causal K-limit, 8 fp16 out
#define LDPH 20                      // uint32 per SMEM row (16 data + 4 pad)
#define AROWB (LDPH*4)               // 80 bytes

template<int TNW>
__global__ __launch_bounds__(256) void hgemm_k(
    const __half* __restrict__ A, const __half* __restrict__ B, void* __restrict__ Cv,
    int M, int N, int K, int lda, int ldb, int ldc,
    long sA0, long sA1, long sB0, long sB1, long sC0, long sC1, int ZH,
    const int* __restrict__ tileExpert, long wStride,
    const float* __restrict__ rowscale, long rsStride, int flags)
{
    constexpr int NTT = TNW / 32;
    constexpr int ABY = 128 * AROWB;
    constexpr int BBY = TNW * AROWB;
    constexpr int STG = ABY + BBY;
    constexpr int BCH = TNW / 64;

    int bx = blockIdx.x, by = blockIdx.y, z = blockIdx.z;
    if ((flags & 2) && (long)bx * TNW > (long)by * 128 + 127) return;
    if (tileExpert) { int te = tileExpert[by]; if (te < 0) return; B += (long)te * wStride; }
    int zb = z / ZH, zh = z - zb * ZH;
    A += zb * sA0 + (long)zh * sA1;
    B += zb * sB0 + (long)zh * sB1;
    int Keff = K;
    if (flags & 4) { int kl = (by + 1) * 128; if (kl < Keff) Keff = kl; }
    int NT = Keff >> 5;

    extern __shared__ char smraw[];
    uint32_t sb = (uint32_t)__cvta_generic_to_shared(smraw);

    int tid = threadIdx.x;
    int wid = tid >> 5, lane = tid & 31;
    int wy = wid & 1, wx = wid >> 1;
    int lr = lane >> 2, lk = lane & 3;

    // cp.async mapping: 16B = 8 halves; 4 chunks per 32-half row
    int ar0 = tid >> 2, ac0 = tid & 3;          // A chunks: ch 0..1 rows ar0, ar0+64
    int bsz[BCH];
#pragma unroll
    for (int ch = 0; ch < BCH; ch++) {
        int row = (tid + ch * 256) >> 2;
        bsz[ch] = ((bx * TNW + row) < N) ? 16 : 0;
    }
    const __half* bsrc0 = B;

    auto issue = [&](int s, int k0) {
        uint32_t Ab = sb + s * STG;
        uint32_t Bb = Ab + ABY;
#pragma unroll
        for (int ch = 0; ch < 2; ch++) {
            int row = ar0 + ch * 64;
            const __half* src = A + (long)(by * 128 + row) * lda + k0 + ac0 * 8;
            cpasync16(Ab + row * AROWB + ac0 * 16, src, 16);
        }
#pragma unroll
        for (int ch = 0; ch < BCH; ch++) {
            int idx = tid + ch * 256;
            int row = idx >> 2, cq = idx & 3;
            const __half* src = bsz[ch] ? (B + (long)(bx * TNW + row) * ldb + k0 + cq * 8) : bsrc0;
            cpasync16(Bb + row * AROWB + cq * 16, src, bsz[ch]);
        }
    };

#pragma unroll
    for (int s = 0; s < 2; s++) {
        if (s < NT) issue(s, s * 32);
        cpcommit();
    }

    float acc[4][NTT][4];
#pragma unroll
    for (int mt = 0; mt < 4; mt++)
#pragma unroll
        for (int nt = 0; nt < NTT; nt++)
#pragma unroll
            for (int i = 0; i < 4; i++) acc[mt][nt][i] = 0.f;

    for (int it = 0; it < NT; ++it) {
        cpwait1();
        __syncthreads();
        if (it + 2 < NT) issue((it + 2) % 3, (it + 2) * 32);
        cpcommit();

        int st = it % 3;
        const uint32_t* Au = (const uint32_t*)(smraw + st * STG);
        const uint32_t* Bu = (const uint32_t*)(smraw + st * STG + ABY);
#pragma unroll
        for (int ks = 0; ks < 2; ks++) {
            int k0 = ks * 8;
            uint32_t af[4][4], bf[NTT][2];
#pragma unroll
            for (int mt = 0; mt < 4; mt++) {
                int m = wy * 64 + mt * 16 + lr;
                af[mt][0] = Au[m * LDPH + k0 + lk];
                af[mt][1] = Au[(m + 8) * LDPH + k0 + lk];
                af[mt][2] = Au[m * LDPH + k0 + 4 + lk];
                af[mt][3] = Au[(m + 8) * LDPH + k0 + 4 + lk];
            }
#pragma unroll
            for (int nt = 0; nt < NTT; nt++) {
                int n = wx * (TNW / 4) + nt * 8 + lr;
                bf[nt][0] = Bu[n * LDPH + k0 + lk];
                bf[nt][1] = Bu[n * LDPH + k0 + 4 + lk];
            }
#pragma unroll
            for (int mt = 0; mt < 4; mt++)
#pragma unroll
                for (int nt = 0; nt < NTT; nt++)
                    mma16(acc[mt][nt], af[mt], bf[nt]);
        }
        __syncthreads();
    }

    // epilogue
    bool doacc = (flags & 1) != 0;
    bool outh = (flags & 8) != 0;
    long zr = (long)z * rsStride;
    float* Cf = (float*)Cv + zb * sC0 + (long)zh * sC1;
    __half* Ch = (__half*)Cv + zb * sC0 + (long)zh * sC1;
#pragma unroll
    for (int mt = 0; mt < 4; mt++) {
        int m0 = by * 128 + wy * 64 + mt * 16 + lr;
        float rs0 = 1.f, rs1 = 1.f;
        if (rowscale) { rs0 = rowscale[zr + m0]; rs1 = rowscale[zr + m0 + 8]; }
#pragma unroll
        for (int nt = 0; nt < NTT; nt++) {
            int c0 = bx * TNW + wx * (TNW / 4) + nt * 8 + 2 * lk;
            if (c0 < N) {
                float2 v0 = make_float2(acc[mt][nt][0] * rs0, acc[mt][nt][1] * rs0);
                float2 v1 = make_float2(acc[mt][nt][2] * rs1, acc[mt][nt][3] * rs1);
                if (outh) {
                    *(__half2*)(Ch + (long)m0 * ldc + c0) = __float22half2_rn(v0);
                    *(__half2*)(Ch + (long)(m0 + 8) * ldc + c0) = __float22half2_rn(v1);
                } else {
                    float* p0 = Cf + (long)m0 * ldc + c0;
                    float* p1 = Cf + (long)(m0 + 8) * ldc + c0;
                    if (doacc) {
                        float2 o0 = *(const float2*)p0, o1 = *(const float2*)p1;
                        v0.x += o0.x; v0.y += o0.y; v1.x += o1.x; v1.y += o1.y;
                    }
                    *(float2*)p0 = v0;
                    *(float2*)p1 = v1;
                }
            }
        }
    }
}

// ---------------- weight fp32 -> fp16 ----------------
__global__ void cvth_k(const float2* __restrict__ src, __half2* __restrict__ dst, long n2)
{
    long i = (long)blockIdx.x * blockDim.x + threadIdx.x;
    if (i < n2) dst[i] = __float22half2_rn(src[i]);
}

// ---------------- reductions ----------------
__device__ __forceinline__ float warpSum(float v) {
#pragma unroll
    for (int o = 16; o; o >>= 1) v += __shfl_xor_sync(0xffffffffu, v, o);
    return v;
}
__device__ __forceinline__ float warpMax(float v) {
#pragma unroll
    for (int o = 16; o; o >>= 1) v = fmaxf(v, __shfl_xor_sync(0xffffffffu, v, o));
    return v;
}

// ---------------- rmsnorm: fp32 in -> fp16 out ----------------
__global__ void rmsnorm_h(const float* __restrict__ x, const float* __restrict__ w,
                          __half* __restrict__ y, int D, int ldx, int ldy)
{
    long t = blockIdx.x;
    const float* xr = x + t * ldx;
    __half* yr = y + t * ldy;
    float s = 0.f;
    for (int d = threadIdx.x; d < D; d += blockDim.x) { float v = xr[d]; s += v * v; }
    __shared__ float sh[32];
    __shared__ float bc;
    s = warpSum(s);
    int lane = threadIdx.x & 31, wp = threadIdx.x >> 5;
    if (!lane) sh[wp] = s;
    __syncthreads();
    if (threadIdx.x < 32) {
        float r = (threadIdx.x < (blockDim.x >> 5)) ? sh[threadIdx.x] : 0.f;
        r = warpSum(r);
        if (!threadIdx.x) bc = rsqrtf(r / D + 1e-6f);
    }
    __syncthreads();
    float sc = bc;
    for (int d = threadIdx.x; d < D; d += blockDim.x)
        yr[d] = __float2half_rn(xr[d] * sc * w[d]);
}

// ---------------- rope on k_pe (fp32) ----------------
__global__ void rope_kpe_k(const float* __restrict__ kv, const float* __restrict__ fc,
                           const float* __restrict__ fs, float* __restrict__ kpe)
{
    long t = blockIdx.x;
    int j = threadIdx.x;
    int pos = (int)(t % Sn);
    float x1 = kv[t * KVAP + KVRn + 2 * j];
    float x2 = kv[t * KVAP + KVRn + 2 * j + 1];
    float c = fc[pos * 32 + j], s = fs[pos * 32 + j];
    kpe[t * ROPEn + 2 * j]     = x1 * c - x2 * s;
    kpe[t * ROPEn + 2 * j + 1] = x1 * s + x2 * c;
}

// ---------------- rope + scale on q: fp32 in -> fp16 out ----------------
__global__ void ropescale_qh(const float* __restrict__ q, const float* __restrict__ fc,
                             const float* __restrict__ fs, __half* __restrict__ qh)
{
    long th = blockIdx.x;
    int pos = (int)((th >> 4) % Sn);
    const float* r = q + th * QDn;
    __half* o = qh + th * QDn;
    int i = threadIdx.x;
    const float sc = 0.07216878364870322f;   // 1/sqrt(192)
    if (i < 64) {
        o[2 * i]     = __float2half_rn(r[2 * i] * sc);
        o[2 * i + 1] = __float2half_rn(r[2 * i + 1] * sc);
    } else {
        int j = i - 64;
        float x1 = r[128 + 2 * j], x2 = r[128 + 2 * j + 1];
        float c = fc[pos * 32 + j], s = fs[pos * 32 + j];
        o[128 + 2 * j]     = __float2half_rn((x1 * c - x2 * s) * sc);
        o[128 + 2 * j + 1] = __float2half_rn((x1 * s + x2 * c) * sc);
    }
}

// ---------------- [k_nope | k_pe] concat -> fp16 ----------------
__global__ void kcat_h(const float* __restrict__ kvb, const float* __restrict__ kpe,
                       __half* __restrict__ kcat)
{
    int s = blockIdx.x, z = blockIdx.y, j = threadIdx.x;
    long t = (long)(z >> 4) * Sn + s;
    float v = (j < NOPEn) ? kvb[t * KVBP + (z & 15) * 256 + j]
                          : kpe[t * ROPEn + (j - NOPEn)];
    kcat[((long)z * Sn + s) * QDn + j] = __float2half_rn(v);
}

// ---------------- transpose V -> vT fp16 ----------------
__global__ void vtrans_h(const float* __restrict__ kvb, __half* __restrict__ vT)
{
    __shared__ float tsm[32][33];
    int z = blockIdx.z, zb = z >> 4, zh = z & 15;
    int kt = blockIdx.x * 32, dt = blockIdx.y * 32;
    int tx = threadIdx.x, ty = threadIdx.y;
#pragma unroll
    for (int i = 0; i < 4; i++) {
        int k = kt + ty + i * 8;
        tsm[ty + i * 8][tx] = kvb[((long)zb * Sn + k) * KVBP + zh * 256 + NOPEn + dt + tx];
    }
    __syncthreads();
#pragma unroll
    for (int i = 0; i < 4; i++) {
        int d = dt + ty + i * 8;
        vT[((long)z * VHn + d) * Sn + kt + tx] = __float2half_rn(tsm[tx][ty + i * 8]);
    }
}

// ---------------- softmax: fp32 scores -> fp16 P (unnormalized) + invsum ----------------
__global__ void softmax2_h(const float* __restrict__ scores, __half* __restrict__ ph,
                           float* __restrict__ inv)
{
    long rowi = blockIdx.x;
    int q = (int)(rowi % Sn);
    const float* p = scores + rowi * Sn;
    __half* po = ph + rowi * Sn;
    int n = q + 1;
    float m = -3.4e38f;
    for (int k = threadIdx.x; k < n; k += blockDim.x) m = fmaxf(m, p[k]);
    __shared__ float shm[32];
    __shared__ float bc0;
    m = warpMax(m);
    int lane = threadIdx.x & 31, wp = threadIdx.x >> 5;
    if (!lane) shm[wp] = m;
    __syncthreads();
    if (threadIdx.x < 32) {
        float r = (threadIdx.x < (blockDim.x >> 5)) ? shm[threadIdx.x] : -3.4e38f;
        r = warpMax(r);
        if (!threadIdx.x) bc0 = r;
    }
    __syncthreads();
    m = bc0;
    float sum = 0.f;
    for (int k = threadIdx.x; k < n; k += blockDim.x) {
        float e = expf(p[k] - m);
        po[k] = __float2half_rn(e);
        sum += e;
    }
    __syncthreads();
    sum = warpSum(sum);
    if (!lane) shm[wp] = sum;
    __syncthreads();
    if (threadIdx.x < 32) {
        float r = (threadIdx.x < (blockDim.x >> 5)) ? shm[threadIdx.x] : 0.f;
        r = warpSum(r);
        if (!threadIdx.x) inv[rowi] = 1.f / r;
    }
    int kend = ((q >> 7) + 1) << 7;
    for (int k = n + threadIdx.x; k < kend; k += blockDim.x) po[k] = __half(0.f);
}

// ---------------- router (reads fp16 nh) ----------------
__global__ void router_h(const __half* __restrict__ nh, const float* __restrict__ rw,
                         int* __restrict__ counts, int* __restrict__ bucket_ts,
                         float* __restrict__ bucket_gate)
{
    long t = blockIdx.x;
    int wp = threadIdx.x >> 5, lane = threadIdx.x & 31;
    const __half* xr = nh + t * DIMn;
    float s = 0.f;
    for (int d = lane; d < DIMn; d += 32) s += __half2float(xr[d]) * rw[(long)wp * DIMn + d];
    s = warpSum(s);
    __shared__ float logit[NEn];
    if (!lane) logit[wp] = s;
    __syncthreads();
    if (threadIdx.x == 0) {
        float mx = logit[0];
#pragma unroll
        for (int e = 1; e < NEn; e++) mx = fmaxf(mx, logit[e]);
        float p[NEn];
#pragma unroll
        for (int e = 0; e < NEn; e++) p[e] = expf(logit[e] - mx);
        int i0 = 0;
#pragma unroll
        for (int e = 1; e < NEn; e++) if (p[e] > p[i0]) i0 = e;
        int i1 = (i0 == 0) ? 1 : 0;
#pragma unroll
        for (int e = 0; e < NEn; e++) if (e != i0 && p[e] > p[i1]) i1 = e;
        float denom = p[i0] + p[i1];
        float g0 = p[i0] / denom, g1 = p[i1] / denom;
        int pos0 = atomicAdd(&counts[i0], 1);
        bucket_ts[i0 * Tn + pos0] = (int)(t * 2);
        bucket_gate[i0 * Tn + pos0] = g0;
        int pos1 = atomicAdd(&counts[i1], 1);
        bucket_ts[i1 * Tn + pos1] = (int)(t * 2 + 1);
        bucket_gate[i1 * Tn + pos1] = g1;
    }
}

__global__ void offsets_k(const int* __restrict__ counts, int* __restrict__ off,
                          int* __restrict__ tile_expert)
{
    for (int tl = 0; tl < MOE_TILES; tl++) tile_expert[tl] = -1;
    int o = 0;
    for (int e = 0; e < NEn; e++) {
        off[e] = o;
        int nt = (counts[e] + 127) >> 7;
        for (int i = 0; i < nt; i++) tile_expert[(o >> 7) + i] = e;
        o += nt * 128;
    }
    off[NEn] = o;
}

__global__ void compact_k(const int* __restrict__ counts, const int* __restrict__ off,
                          const int* __restrict__ bucket_ts, const float* __restrict__ bucket_gate,
                          int* __restrict__ flat_tok, int* __restrict__ tok2row,
                          float* __restrict__ tok2gate)
{
    int e = blockIdx.x;
    int cnt = counts[e], base = off[e];
    for (int i = threadIdx.x; i < cnt; i += blockDim.x) {
        int ts = bucket_ts[e * Tn + i];
        int r = base + i;
        flat_tok[r] = ts >> 1;
        tok2row[ts] = r;
        tok2gate[ts] = bucket_gate[e * Tn + i];
    }
}

// ---------------- gather fp16 rows ----------------
__global__ void gather_h(const __half* __restrict__ nh, const int* __restrict__ flat_tok,
                         __half* __restrict__ xg)
{
    long r = blockIdx.x;
    int t = flat_tok[r];
    uint4* dst = (uint4*)(xg + r * DIMn);
    int nch = DIMn / 8;
    if (t < 0) {
        uint4 zz = make_uint4(0u, 0u, 0u, 0u);
        for (int i = threadIdx.x; i < nch; i += blockDim.x) dst[i] = zz;
    } else {
        const uint4* src = (const uint4*)(nh + (long)t * DIMn);
        for (int i = threadIdx.x; i < nch; i += blockDim.x) dst[i] = src[i];
    }
}

// ---------------- silu(a)*b fp16 ----------------
__global__ void silumul_h(__half2* __restrict__ a, const __half2* __restrict__ b, long n2)
{
    long i = (long)blockIdx.x * blockDim.x + threadIdx.x;
    if (i < n2) {
        float2 x = __half22float2(a[i]);
        float2 y = __half22float2(b[i]);
        float s0 = x.x / (1.f + expf(-x.x));
        float s1 = x.y / (1.f + expf(-x.y));
        a[i] = __float22half2_rn(make_float2(s0 * y.x, s1 * y.y));
    }
}

// ---------------- combine ----------------
__global__ void combine_k(const float* __restrict__ h, const float* __restrict__ sh,
                          const float* __restrict__ eo, const int* __restrict__ tok2row,
                          const float* __restrict__ tok2gate, float* __restrict__ out)
{
    long t = blockIdx.x;
    int r0 = tok2row[t * 2], r1 = tok2row[t * 2 + 1];
    float g0 = tok2gate[t * 2], g1 = tok2gate[t * 2 + 1];
    const float4* H = (const float4*)(h + t * DIMn);
    const float4* SH = (const float4*)(sh + t * DIMn);
    const float4* E0 = (const float4*)(eo + (long)r0 * DIMn);
    const float4* E1 = (const float4*)(eo + (long)r1 * DIMn);
    float4* O = (float4*)(out + t * DIMn);
    for (int i = threadIdx.x; i < DIMn / 4; i += blockDim.x) {
        float4 a = H[i], b = SH[i], c = E0[i], d = E1[i];
        float4 o;
        o.x = a.x + b.x + g0 * c.x + g1 * d.x;
        o.y = a.y + b.y + g0 * c.y + g1 * d.y;
        o.z = a.z + b.z + g0 * c.z + g1 * d.z;
        o.w = a.w + b.w + g0 * c.w + g1 * d.w;
        O[i] = o;
    }
}

// ---------------- host ----------------
#define SYM(p, s) do { void* _q = nullptr; cudaGetSymbolAddress(&_q, s); p = (decltype(p))_q; } while (0)

static void launch_hgemm(int tnw, const __half* A, const __half* B, void* C,
                         int M, int N, int K, int lda, int ldb, int ldc,
                         long sA0, long sA1, long sB0, long sB1, long sC0, long sC1,
                         int ZH, int Z, const int* tileExpert, long wStride,
                         const float* rowscale, long rsStride, int flags)
{
    dim3 grid((N + tnw - 1) / tnw, M / 128, Z);
    int smem = 3 * (128 * AROWB + tnw * AROWB);
    if (tnw == 128)
        hgemm_k<128><<<grid, 256, smem>>>(A, B, C, M, N, K, lda, ldb, ldc,
            sA0, sA1, sB0, sB1, sC0, sC1, ZH, tileExpert, wStride, rowscale, rsStride, flags);
    else
        hgemm_k<256><<<grid, 256, smem>>>(A, B, C, M, N, K, lda, ldb, ldc,
            sA0, sA1, sB0, sB1, sC0, sC1, ZH, tileExpert, wStride, rowscale, rsStride, flags);
}

static void launch_cvt(const float* src, __half* dst, long n)
{
    long n2 = n / 2;
    cvth_k<<<(int)((n2 + 255) / 256), 256>>>((const float2*)src, (__half2*)dst, n2);
}

extern "C" void kernel_launch(void* const* d_in, const int* in_sizes, int n_in,
                              void* d_out, int out_size)
{
    cudaFuncSetAttribute(hgemm_k<128>, cudaFuncAttributeMaxDynamicSharedMemorySize,
                         3 * (128 * AROWB + 128 * AROWB));
    cudaFuncSetAttribute(hgemm_k<256>, cudaFuncAttributeMaxDynamicSharedMemorySize,
                         3 * (128 * AROWB + 256 * AROWB));

    const float* x       = (const float*)d_in[0];
    const float* fcos    = (const float*)d_in[1];
    const float* fsin    = (const float*)d_in[2];
    const float* attn_w  = (const float*)d_in[3];
    const float* wq      = (const float*)d_in[4];
    const float* wkv_a   = (const float*)d_in[5];
    const float* kv_w    = (const float*)d_in[6];
    const float* wkv_b   = (const float*)d_in[7];
    const float* wo      = (const float*)d_in[8];
    const float* ffn_w   = (const float*)d_in[9];
    const float* rw      = (const float*)d_in[10];
    const float* e_w1    = (const float*)d_in[11];
    const float* e_w3    = (const float*)d_in[12];
    const float* e_w2    = (const float*)d_in[13];
    const float* s_w1    = (const float*)d_in[14];
    const float* s_w3    = (const float*)d_in[15];
    const float* s_w2    = (const float*)d_in[16];
    float* out = (float*)d_out;

    float *q, *kv, *kpe, *kvb, *scores, *inv, *h, *eo, *sh;
    __half *nx_h, *ckv_h, *qh, *kcat, *vT, *ph, *attn_h, *nh_h, *xg, *t1h, *t3h, *s1h, *s3h;
    __half *wq_h, *wkva_h, *wkvb_h, *wo_h, *ew1_h, *ew3_h, *ew2_h, *sw1_h, *sw3_h, *sw2_h;
    int *counts, *off, *tile_expert, *bucket_ts, *flat_tok, *tok2row;
    float *bucket_gate, *tok2gate;
    SYM(q, g_q); SYM(kv, g_kv); SYM(kpe, g_kpe); SYM(kvb, g_kvb);
    SYM(scores, g_scores); SYM(inv, g_inv); SYM(h, g_h); SYM(eo, g_eo); SYM(sh, g_sh);
    SYM(nx_h, g_nx_h); SYM(ckv_h, g_ckv_h); SYM(qh, g_qh); SYM(kcat, g_kcat_h);
    SYM(vT, g_vT_h); SYM(ph, g_ph); SYM(attn_h, g_attn_h); SYM(nh_h, g_nh_h);
    SYM(xg, g_xg_h); SYM(t1h, g_t1h); SYM(t3h, g_t3h); SYM(s1h, g_s1h); SYM(s3h, g_s3h);
    SYM(wq_h, g_wq_h); SYM(wkva_h, g_wkva_h); SYM(wkvb_h, g_wkvb_h); SYM(wo_h, g_wo_h);
    SYM(ew1_h, g_ew1_h); SYM(ew3_h, g_ew3_h); SYM(ew2_h, g_ew2_h);
    SYM(sw1_h, g_sw1_h); SYM(sw3_h, g_sw3_h); SYM(sw2_h, g_sw2_h);
    SYM(counts, g_counts); SYM(off, g_off); SYM(tile_expert, g_tile_expert);
    SYM(bucket_ts, g_bucket_ts); SYM(bucket_gate, g_bucket_gate);
    SYM(flat_tok, g_flat_tok); SYM(tok2row, g_tok2row); SYM(tok2gate, g_tok2gate);

    const long SS = (long)Sn * Sn;

    // 0. weight conversion
    launch_cvt(wq, wq_h, (long)QPROJ * DIMn);
    launch_cvt(wkv_a, wkva_h, (long)KVAP * DIMn);
    launch_cvt(wkv_b, wkvb_h, (long)KVBP * KVRn);
    launch_cvt(wo, wo_h, (long)DIMn * DIMn);
    launch_cvt(e_w1, ew1_h, (long)NEn * MINTERn * DIMn);
    launch_cvt(e_w3, ew3_h, (long)NEn * MINTERn * DIMn);
    launch_cvt(e_w2, ew2_h, (long)NEn * DIMn * MINTERn);
    launch_cvt(s_w1, sw1_h, (long)SHIn * DIMn);
    launch_cvt(s_w3, sw3_h, (long)SHIn * DIMn);
    launch_cvt(s_w2, sw2_h, (long)DIMn * SHIn);

    // 1. attention-input rmsnorm -> fp16
    rmsnorm_h<<<Tn, 256>>>(x, attn_w, nx_h, DIMn, DIMn, DIMn);
    // 2. q projection (fp32 out)
    launch_hgemm(256, nx_h, wq_h, q, Tn, QPROJ, DIMn, DIMn, DIMn, QPROJ,
                 0, 0, 0, 0, 0, 0, 1, 1, nullptr, 0, nullptr, 0, 0);
    // 3. kv_a projection (fp32 out)
    launch_hgemm(256, nx_h, wkva_h, kv, Tn, KVAP, DIMn, DIMn, DIMn, KVAP,
                 0, 0, 0, 0, 0, 0, 1, 1, nullptr, 0, nullptr, 0, 0);
    // 4. c_kv rmsnorm -> fp16
    rmsnorm_h<<<Tn, 256>>>(kv, kv_w, ckv_h, KVRn, KVAP, KVRn);
    // 5. rope k_pe (fp32)
    rope_kpe_k<<<Tn, 32>>>(kv, fcos, fsin, kpe);
    // 6. kv_b projection (fp32 out)
    launch_hgemm(256, ckv_h, wkvb_h, kvb, Tn, KVBP, KVRn, KVRn, KVRn, KVBP,
                 0, 0, 0, 0, 0, 0, 1, 1, nullptr, 0, nullptr, 0, 0);
    // 7. rope + scale q -> fp16
    ropescale_qh<<<Tn * NHn, 96>>>(q, fcos, fsin, qh);
    // 8. kcat + vT -> fp16
    { dim3 g(Sn, ZSn); kcat_h<<<g, QDn>>>(kvb, kpe, kcat); }
    { dim3 g(Sn / 32, VHn / 32, ZSn); dim3 b(32, 8); vtrans_h<<<g, b>>>(kvb, vT); }
    // 9. scores = q @ kcat^T (K=192, causal skip, fp32 out)
    launch_hgemm(256, qh, kcat, scores, Sn, Sn, QDn, QPROJ, QDn, Sn,
                 (long)Sn * QPROJ, QDn, 16L * Sn * QDn, (long)Sn * QDn, 16 * SS, SS,
                 16, 32, nullptr, 0, nullptr, 0, 2);
    // 10. softmax -> fp16 P + invsum
    softmax2_h<<<32 * Sn, 256>>>(scores, ph, inv);
    // 11. attn = (P @ V) * invsum -> fp16 (K-limit)
    launch_hgemm(128, ph, vT, attn_h, Sn, VHn, Sn, Sn, Sn, DIMn,
                 16 * SS, SS, 16L * VHn * Sn, (long)VHn * Sn, (long)Sn * DIMn, VHn,
                 16, 32, nullptr, 0, inv, Sn, 4 | 8);
    // 12. h = x + attn @ wo^T
    cudaMemcpyAsync(h, x, (size_t)Tn * DIMn * sizeof(float), cudaMemcpyDeviceToDevice, 0);
    launch_hgemm(256, attn_h, wo_h, h, Tn, DIMn, DIMn, DIMn, DIMn, DIMn,
                 0, 0, 0, 0, 0, 0, 1, 1, nullptr, 0, nullptr, 0, 1);
    // 13. ffn rmsnorm -> fp16
    rmsnorm_h<<<Tn, 256>>>(h, ffn_w, nh_h, DIMn, DIMn, DIMn);
    // 14. routing
    cudaMemsetAsync(counts, 0, NEn * sizeof(int), 0);
    cudaMemsetAsync(flat_tok, 0xFF, MOE_ROWS * sizeof(int), 0);
    router_h<<<Tn, 256>>>(nh_h, rw, counts, bucket_ts, bucket_gate);
    offsets_k<<<1, 1>>>(counts, off, tile_expert);
    compact_k<<<NEn, 256>>>(counts, off, bucket_ts, bucket_gate, flat_tok, tok2row, tok2gate);
    gather_h<<<MOE_ROWS, 256>>>(nh_h, flat_tok, xg);
    // 15. expert FFN (grouped, fp16 intermediates)
    launch_hgemm(256, xg, ew1_h, t1h, MOE_ROWS, MINTERn, DIMn, DIMn, DIMn, MINTERn,
                 0, 0, 0, 0, 0, 0, 1, 1, tile_expert, (long)MINTERn * DIMn, nullptr, 0, 8);
    launch_hgemm(256, xg, ew3_h, t3h, MOE_ROWS, MINTERn, DIMn, DIMn, DIMn, MINTERn,
                 0, 0, 0, 0, 0, 0, 1, 1, tile_expert, (long)MINTERn * DIMn, nullptr, 0, 8);
    {
        long n2 = (long)MOE_ROWS * MINTERn / 2;
        silumul_h<<<(int)((n2 + 255) / 256), 256>>>((__half2*)t1h, (const __half2*)t3h, n2);
    }
    launch_hgemm(256, t1h, ew2_h, eo, MOE_ROWS, DIMn, MINTERn, MINTERn, MINTERn, DIMn,
                 0, 0, 0, 0, 0, 0, 1, 1, tile_expert, (long)DIMn * MINTERn, nullptr, 0, 0);
    // 16. shared FFN (fp16 intermediates)
    launch_hgemm(256, nh_h, sw1_h, s1h, Tn, SHIn, DIMn, DIMn, DIMn, SHIn,
                 0, 0, 0, 0, 0, 0, 1, 1, nullptr, 0, nullptr, 0, 8);
    launch_hgemm(256, nh_h, sw3_h, s3h, Tn, SHIn, DIMn, DIMn, DIMn, SHIn,
                 0, 0, 0, 0, 0, 0, 1, 1, nullptr, 0, nullptr, 0, 8);
    {
        long n2 = (long)Tn * SHIn / 2;
        silumul_h<<<(int)((n2 + 255) / 256), 256>>>((__half2*)s1h, (const __half2*)s3h, n2);
    }
    launch_hgemm(256, s1h, sw2_h, sh, Tn, DIMn, SHIn, SHIn, SHIn, DIMn,
                 0, 0, 0, 0, 0, 0, 1, 1, nullptr, 0, nullptr, 0, 0);
    // 17. combine
    combine_k<<<Tn, 256>>>(h, sh, eo, tok2row, tok2gate, out);
}

// round 7
// speedup vs baseline: 5.4907x; 1.0890x over previous
#include <cuda_runtime.h>
#include <cuda_fp16.h>
#include <math.h>
#include <stdint.h>

// ---------------- problem constants ----------------
#define Tn     4096
#define Sn     2048
#define DIMn   2048
#define NHn    16
#define NOPEn  128
#define ROPEn  64
#define QDn    192
#define VHn    128
#define KVRn   512
#define NEn    8
#define MINTERn 1408
#define SHIn   2816
#define QPROJ  3072
#define KVAP   576
#define KVBP   4096
#define MOE_ROWS 9216
#define MOE_TILES 72
#define ZSn    32

// ---------------- fp32 scratch ----------------
__device__ float g_q[(size_t)Tn*QPROJ];
__device__ float g_kv[(size_t)Tn*KVAP];
__device__ float g_kpe[(size_t)Tn*ROPEn];
__device__ float g_kvb[(size_t)Tn*KVBP];
__device__ float g_scores[(size_t)ZSn*Sn*Sn];
__device__ float g_inv[ZSn*Sn];
__device__ float g_h[(size_t)Tn*DIMn];
__device__ float g_eo[(size_t)MOE_ROWS*DIMn];
__device__ float g_sh[(size_t)Tn*DIMn];
__device__ int   g_counts[NEn];
__device__ int   g_off[NEn+1];
__device__ int   g_tile_expert[MOE_TILES];
__device__ int   g_bucket_ts[NEn*Tn];
__device__ float g_bucket_gate[NEn*Tn];
__device__ int   g_flat_tok[MOE_ROWS];
__device__ int   g_tok2row[Tn*2];
__device__ float g_tok2gate[Tn*2];
// ---------------- fp16 scratch ----------------
__device__ __half g_nx_h[(size_t)Tn*DIMn];
__device__ __half g_ckv_h[(size_t)Tn*KVRn];
__device__ __half g_qh[(size_t)Tn*QPROJ];
__device__ __half g_kcat_h[(size_t)ZSn*Sn*QDn];
__device__ __half g_vT_h[(size_t)ZSn*VHn*Sn];
__device__ __half g_ph[(size_t)ZSn*Sn*Sn];
__device__ __half g_attn_h[(size_t)Tn*DIMn];
__device__ __half g_nh_h[(size_t)Tn*DIMn];
__device__ __half g_xg_h[(size_t)MOE_ROWS*DIMn];
__device__ __half g_t1h[(size_t)MOE_ROWS*MINTERn];
__device__ __half g_t3h[(size_t)MOE_ROWS*MINTERn];
__device__ __half g_s1h[(size_t)Tn*SHIn];
__device__ __half g_s3h[(size_t)Tn*SHIn];
// fp16 weight copies
__device__ __half g_wq_h[(size_t)QPROJ*DIMn];
__device__ __half g_wkva_h[(size_t)KVAP*DIMn];
__device__ __half g_wkvb_h[(size_t)KVBP*KVRn];
__device__ __half g_wo_h[(size_t)DIMn*DIMn];
__device__ __half g_ew1_h[(size_t)NEn*MINTERn*DIMn];
__device__ __half g_ew3_h[(size_t)NEn*MINTERn*DIMn];
__device__ __half g_ew2_h[(size_t)NEn*DIMn*MINTERn];
__device__ __half g_sw1_h[(size_t)SHIn*DIMn];
__device__ __half g_sw3_h[(size_t)SHIn*DIMn];
__device__ __half g_sw2_h[(size_t)DIMn*SHIn];

// ---------------- helpers ----------------
__device__ __forceinline__ void mma16(float* c, const uint32_t* a, const uint32_t* b) {
    asm volatile("mma.sync.aligned.m16n8k16.row.col.f32.f16.f16.f32 "
        "{%0,%1,%2,%3}, {%4,%5,%6,%7}, {%8,%9}, {%0,%1,%2,%3};"
        : "+f"(c[0]), "+f"(c[1]), "+f"(c[2]), "+f"(c[3])
        : "r"(a[0]), "r"(a[1]), "r"(a[2]), "r"(a[3]), "r"(b[0]), "r"(b[1]));
}
__device__ __forceinline__ void ldsm4(uint32_t* r, uint32_t addr) {
    asm volatile("ldmatrix.sync.aligned.m8n8.x4.shared.b16 {%0,%1,%2,%3}, [%4];"
        : "=r"(r[0]), "=r"(r[1]), "=r"(r[2]), "=r"(r[3]) : "r"(addr));
}
__device__ __forceinline__ void cpasync16(uint32_t dst, const void* src, int sz) {
    asm volatile("cp.async.cg.shared.global [%0], [%1], 16, %2;"
                 :: "r"(dst), "l"(src), "r"(sz));
}
__device__ __forceinline__ void cpcommit() { asm volatile("cp.async.commit_group;"); }
__device__ __forceinline__ void cpwait1() { asm volatile("cp.async.wait_group 1;"); }

// ---------------- generic fp16 tensor GEMM (cp.async 3-stage, ldmatrix) ----------------
// C[M,N] = A[M,K] @ B[N,K]^T, K-major fp16, fp32 accumulate. M%128==0, K%32==0.
// flags: 1 accumulate(fp32 out), 2 causal tile skip, 4 causal K-limit, 8 fp16 out
#define LDPH 20                      // uint32 per SMEM row (16 data + 4 pad)
#define AROWB (LDPH*4)               // 80 bytes

template<int TNW>
__global__ __launch_bounds__(256) void hgemm_k(
    const __half* __restrict__ A, const __half* __restrict__ B, void* __restrict__ Cv,
    int M, int N, int K, int lda, int ldb, int ldc,
    long sA0, long sA1, long sB0, long sB1, long sC0, long sC1, int ZH,
    const int* __restrict__ tileExpert, long wStride,
    const float* __restrict__ rowscale, long rsStride, int flags)
{
    constexpr int NTT = TNW / 32;
    constexpr int ABY = 128 * AROWB;
    constexpr int BBY = TNW * AROWB;
    constexpr int STG = ABY + BBY;
    constexpr int BCH = TNW / 64;

    int bx = blockIdx.x, by = blockIdx.y, z = blockIdx.z;
    if ((flags & 2) && (long)bx * TNW > (long)by * 128 + 127) return;
    if (tileExpert) { int te = tileExpert[by]; if (te < 0) return; B += (long)te * wStride; }
    int zb = z / ZH, zh = z - zb * ZH;
    A += zb * sA0 + (long)zh * sA1;
    B += zb * sB0 + (long)zh * sB1;
    int Keff = K;
    if (flags & 4) { int kl = (by + 1) * 128; if (kl < Keff) Keff = kl; }
    int NT = Keff >> 5;

    extern __shared__ char smraw[];
    uint32_t sb = (uint32_t)__cvta_generic_to_shared(smraw);

    int tid = threadIdx.x;
    int wid = tid >> 5, lane = tid & 31;
    int wy = wid & 1, wx = wid >> 1;
    int lr = lane >> 2, lk = lane & 3;
    (void)lr; (void)lk;

    // ldmatrix per-lane offsets
    int grp = lane >> 3, lrow = lane & 7;
    uint32_t aoff = (uint32_t)((wy * 64 + (grp & 1) * 8 + lrow) * AROWB + (grp >> 1) * 16);
    uint32_t boff = (uint32_t)((wx * (TNW / 4) + (grp >> 1) * 8 + lrow) * AROWB + (grp & 1) * 16);

    // cp.async mapping: 16B = 8 halves; 4 chunks per 32-half row
    int ar0 = tid >> 2, ac0 = tid & 3;
    int bsz[BCH];
#pragma unroll
    for (int ch = 0; ch < BCH; ch++) {
        int row = (tid + ch * 256) >> 2;
        bsz[ch] = ((bx * TNW + row) < N) ? 16 : 0;
    }
    const __half* bsrc0 = B;

    auto issue = [&](int s, int k0) {
        uint32_t Ab = sb + s * STG;
        uint32_t Bb = Ab + ABY;
#pragma unroll
        for (int ch = 0; ch < 2; ch++) {
            int row = ar0 + ch * 64;
            const __half* src = A + (long)(by * 128 + row) * lda + k0 + ac0 * 8;
            cpasync16(Ab + row * AROWB + ac0 * 16, src, 16);
        }
#pragma unroll
        for (int ch = 0; ch < BCH; ch++) {
            int idx = tid + ch * 256;
            int row = idx >> 2, cq = idx & 3;
            const __half* src = bsz[ch] ? (B + (long)(bx * TNW + row) * ldb + k0 + cq * 8) : bsrc0;
            cpasync16(Bb + row * AROWB + cq * 16, src, bsz[ch]);
        }
    };

#pragma unroll
    for (int s = 0; s < 2; s++) {
        if (s < NT) issue(s, s * 32);
        cpcommit();
    }

    float acc[4][NTT][4];
#pragma unroll
    for (int mt = 0; mt < 4; mt++)
#pragma unroll
        for (int nt = 0; nt < NTT; nt++)
#pragma unroll
            for (int i = 0; i < 4; i++) acc[mt][nt][i] = 0.f;

    for (int it = 0; it < NT; ++it) {
        cpwait1();
        __syncthreads();
        if (it + 2 < NT) issue((it + 2) % 3, (it + 2) * 32);
        cpcommit();

        int st = it % 3;
        uint32_t Abase = sb + st * STG + aoff;
        uint32_t Bbase = sb + st * STG + ABY + boff;
#pragma unroll
        for (int ks = 0; ks < 2; ks++) {
            uint32_t af[4][4], bf[NTT][2];
#pragma unroll
            for (int mt = 0; mt < 4; mt++)
                ldsm4(af[mt], Abase + mt * (16 * AROWB) + ks * 32);
#pragma unroll
            for (int p = 0; p < NTT / 2; p++) {
                uint32_t r[4];
                ldsm4(r, Bbase + p * (16 * AROWB) + ks * 32);
                bf[2 * p][0] = r[0]; bf[2 * p][1] = r[1];
                bf[2 * p + 1][0] = r[2]; bf[2 * p + 1][1] = r[3];
            }
#pragma unroll
            for (int mt = 0; mt < 4; mt++)
#pragma unroll
                for (int nt = 0; nt < NTT; nt++)
                    mma16(acc[mt][nt], af[mt], bf[nt]);
        }
        __syncthreads();
    }

    // epilogue
    bool doacc = (flags & 1) != 0;
    bool outh = (flags & 8) != 0;
    long zr = (long)z * rsStride;
    float* Cf = (float*)Cv + zb * sC0 + (long)zh * sC1;
    __half* Ch = (__half*)Cv + zb * sC0 + (long)zh * sC1;
    int elr = lane >> 2, elk = lane & 3;
#pragma unroll
    for (int mt = 0; mt < 4; mt++) {
        int m0 = by * 128 + wy * 64 + mt * 16 + elr;
        float rs0 = 1.f, rs1 = 1.f;
        if (rowscale) { rs0 = rowscale[zr + m0]; rs1 = rowscale[zr + m0 + 8]; }
#pragma unroll
        for (int nt = 0; nt < NTT; nt++) {
            int c0 = bx * TNW + wx * (TNW / 4) + nt * 8 + 2 * elk;
            if (c0 < N) {
                float2 v0 = make_float2(acc[mt][nt][0] * rs0, acc[mt][nt][1] * rs0);
                float2 v1 = make_float2(acc[mt][nt][2] * rs1, acc[mt][nt][3] * rs1);
                if (outh) {
                    *(__half2*)(Ch + (long)m0 * ldc + c0) = __float22half2_rn(v0);
                    *(__half2*)(Ch + (long)(m0 + 8) * ldc + c0) = __float22half2_rn(v1);
                } else {
                    float* p0 = Cf + (long)m0 * ldc + c0;
                    float* p1 = Cf + (long)(m0 + 8) * ldc + c0;
                    if (doacc) {
                        float2 o0 = *(const float2*)p0, o1 = *(const float2*)p1;
                        v0.x += o0.x; v0.y += o0.y; v1.x += o1.x; v1.y += o1.y;
                    }
                    *(float2*)p0 = v0;
                    *(float2*)p1 = v1;
                }
            }
        }
    }
}

// ---------------- weight fp32 -> fp16 ----------------
__global__ void cvth_k(const float2* __restrict__ src, __half2* __restrict__ dst, long n2)
{
    long i = (long)blockIdx.x * blockDim.x + threadIdx.x;
    if (i < n2) dst[i] = __float22half2_rn(src[i]);
}

// ---------------- reductions ----------------
__device__ __forceinline__ float warpSum(float v) {
#pragma unroll
    for (int o = 16; o; o >>= 1) v += __shfl_xor_sync(0xffffffffu, v, o);
    return v;
}
__device__ __forceinline__ float warpMax(float v) {
#pragma unroll
    for (int o = 16; o; o >>= 1) v = fmaxf(v, __shfl_xor_sync(0xffffffffu, v, o));
    return v;
}

// ---------------- rmsnorm: fp32 in -> fp16 out ----------------
__global__ void rmsnorm_h(const float* __restrict__ x, const float* __restrict__ w,
                          __half* __restrict__ y, int D, int ldx, int ldy)
{
    long t = blockIdx.x;
    const float* xr = x + t * ldx;
    __half* yr = y + t * ldy;
    float s = 0.f;
    for (int d = threadIdx.x; d < D; d += blockDim.x) { float v = xr[d]; s += v * v; }
    __shared__ float sh[32];
    __shared__ float bc;
    s = warpSum(s);
    int lane = threadIdx.x & 31, wp = threadIdx.x >> 5;
    if (!lane) sh[wp] = s;
    __syncthreads();
    if (threadIdx.x < 32) {
        float r = (threadIdx.x < (blockDim.x >> 5)) ? sh[threadIdx.x] : 0.f;
        r = warpSum(r);
        if (!threadIdx.x) bc = rsqrtf(r / D + 1e-6f);
    }
    __syncthreads();
    float sc = bc;
    for (int d = threadIdx.x; d < D; d += blockDim.x)
        yr[d] = __float2half_rn(xr[d] * sc * w[d]);
}

// ---------------- rope on k_pe (fp32) ----------------
__global__ void rope_kpe_k(const float* __restrict__ kv, const float* __restrict__ fc,
                           const float* __restrict__ fs, float* __restrict__ kpe)
{
    long t = blockIdx.x;
    int j = threadIdx.x;
    int pos = (int)(t % Sn);
    float x1 = kv[t * KVAP + KVRn + 2 * j];
    float x2 = kv[t * KVAP + KVRn + 2 * j + 1];
    float c = fc[pos * 32 + j], s = fs[pos * 32 + j];
    kpe[t * ROPEn + 2 * j]     = x1 * c - x2 * s;
    kpe[t * ROPEn + 2 * j + 1] = x1 * s + x2 * c;
}

// ---------------- rope + scale on q: fp32 in -> fp16 out ----------------
__global__ void ropescale_qh(const float* __restrict__ q, const float* __restrict__ fc,
                             const float* __restrict__ fs, __half* __restrict__ qh)
{
    long th = blockIdx.x;
    int pos = (int)((th >> 4) % Sn);
    const float* r = q + th * QDn;
    __half* o = qh + th * QDn;
    int i = threadIdx.x;
    const float sc = 0.07216878364870322f;   // 1/sqrt(192)
    if (i < 64) {
        o[2 * i]     = __float2half_rn(r[2 * i] * sc);
        o[2 * i + 1] = __float2half_rn(r[2 * i + 1] * sc);
    } else {
        int j = i - 64;
        float x1 = r[128 + 2 * j], x2 = r[128 + 2 * j + 1];
        float c = fc[pos * 32 + j], s = fs[pos * 32 + j];
        o[128 + 2 * j]     = __float2half_rn((x1 * c - x2 * s) * sc);
        o[128 + 2 * j + 1] = __float2half_rn((x1 * s + x2 * c) * sc);
    }
}

// ---------------- [k_nope | k_pe] concat -> fp16 ----------------
__global__ void kcat_h(const float* __restrict__ kvb, const float* __restrict__ kpe,
                       __half* __restrict__ kcat)
{
    int s = blockIdx.x, z = blockIdx.y, j = threadIdx.x;
    long t = (long)(z >> 4) * Sn + s;
    float v = (j < NOPEn) ? kvb[t * KVBP + (z & 15) * 256 + j]
                          : kpe[t * ROPEn + (j - NOPEn)];
    kcat[((long)z * Sn + s) * QDn + j] = __float2half_rn(v);
}

// ---------------- transpose V -> vT fp16 ----------------
__global__ void vtrans_h(const float* __restrict__ kvb, __half* __restrict__ vT)
{
    __shared__ float tsm[32][33];
    int z = blockIdx.z, zb = z >> 4, zh = z & 15;
    int kt = blockIdx.x * 32, dt = blockIdx.y * 32;
    int tx = threadIdx.x, ty = threadIdx.y;
#pragma unroll
    for (int i = 0; i < 4; i++) {
        int k = kt + ty + i * 8;
        tsm[ty + i * 8][tx] = kvb[((long)zb * Sn + k) * KVBP + zh * 256 + NOPEn + dt + tx];
    }
    __syncthreads();
#pragma unroll
    for (int i = 0; i < 4; i++) {
        int d = dt + ty + i * 8;
        vT[((long)z * VHn + d) * Sn + kt + tx] = __float2half_rn(tsm[tx][ty + i * 8]);
    }
}

// ---------------- softmax: fp32 scores -> fp16 P (unnormalized) + invsum ----------------
__global__ void softmax2_h(const float* __restrict__ scores, __half* __restrict__ ph,
                           float* __restrict__ inv)
{
    long rowi = blockIdx.x;
    int q = (int)(rowi % Sn);
    const float* p = scores + rowi * Sn;
    __half* po = ph + rowi * Sn;
    int n = q + 1;
    float m = -3.4e38f;
    for (int k = threadIdx.x; k < n; k += blockDim.x) m = fmaxf(m, p[k]);
    __shared__ float shm[32];
    __shared__ float bc0;
    m = warpMax(m);
    int lane = threadIdx.x & 31, wp = threadIdx.x >> 5;
    if (!lane) shm[wp] = m;
    __syncthreads();
    if (threadIdx.x < 32) {
        float r = (threadIdx.x < (blockDim.x >> 5)) ? shm[threadIdx.x] : -3.4e38f;
        r = warpMax(r);
        if (!threadIdx.x) bc0 = r;
    }
    __syncthreads();
    m = bc0;
    float sum = 0.f;
    for (int k = threadIdx.x; k < n; k += blockDim.x) {
        float e = expf(p[k] - m);
        po[k] = __float2half_rn(e);
        sum += e;
    }
    __syncthreads();
    sum = warpSum(sum);
    if (!lane) shm[wp] = sum;
    __syncthreads();
    if (threadIdx.x < 32) {
        float r = (threadIdx.x < (blockDim.x >> 5)) ? shm[threadIdx.x] : 0.f;
        r = warpSum(r);
        if (!threadIdx.x) inv[rowi] = 1.f / r;
    }
    int kend = ((q >> 7) + 1) << 7;
    for (int k = n + threadIdx.x; k < kend; k += blockDim.x) po[k] = __half(0.f);
}

// ---------------- router (reads fp16 nh) ----------------
__global__ void router_h(const __half* __restrict__ nh, const float* __restrict__ rw,
                         int* __restrict__ counts, int* __restrict__ bucket_ts,
                         float* __restrict__ bucket_gate)
{
    long t = blockIdx.x;
    int wp = threadIdx.x >> 5, lane = threadIdx.x & 31;
    const __half* xr = nh + t * DIMn;
    float s = 0.f;
    for (int d = lane; d < DIMn; d += 32) s += __half2float(xr[d]) * rw[(long)wp * DIMn + d];
    s = warpSum(s);
    __shared__ float logit[NEn];
    if (!lane) logit[wp] = s;
    __syncthreads();
    if (threadIdx.x == 0) {
        float mx = logit[0];
#pragma unroll
        for (int e = 1; e < NEn; e++) mx = fmaxf(mx, logit[e]);
        float p[NEn];
#pragma unroll
        for (int e = 0; e < NEn; e++) p[e] = expf(logit[e] - mx);
        int i0 = 0;
#pragma unroll
        for (int e = 1; e < NEn; e++) if (p[e] > p[i0]) i0 = e;
        int i1 = (i0 == 0) ? 1 : 0;
#pragma unroll
        for (int e = 0; e < NEn; e++) if (e != i0 && p[e] > p[i1]) i1 = e;
        float denom = p[i0] + p[i1];
        float g0 = p[i0] / denom, g1 = p[i1] / denom;
        int pos0 = atomicAdd(&counts[i0], 1);
        bucket_ts[i0 * Tn + pos0] = (int)(t * 2);
        bucket_gate[i0 * Tn + pos0] = g0;
        int pos1 = atomicAdd(&counts[i1], 1);
        bucket_ts[i1 * Tn + pos1] = (int)(t * 2 + 1);
        bucket_gate[i1 * Tn + pos1] = g1;
    }
}

__global__ void offsets_k(const int* __restrict__ counts, int* __restrict__ off,
                          int* __restrict__ tile_expert)
{
    for (int tl = 0; tl < MOE_TILES; tl++) tile_expert[tl] = -1;
    int o = 0;
    for (int e = 0; e < NEn; e++) {
        off[e] = o;
        int nt = (counts[e] + 127) >> 7;
        for (int i = 0; i < nt; i++) tile_expert[(o >> 7) + i] = e;
        o += nt * 128;
    }
    off[NEn] = o;
}

__global__ void compact_k(const int* __restrict__ counts, const int* __restrict__ off,
                          const int* __restrict__ bucket_ts, const float* __restrict__ bucket_gate,
                          int* __restrict__ flat_tok, int* __restrict__ tok2row,
                          float* __restrict__ tok2gate)
{
    int e = blockIdx.x;
    int cnt = counts[e], base = off[e];
    for (int i = threadIdx.x; i < cnt; i += blockDim.x) {
        int ts = bucket_ts[e * Tn + i];
        int r = base + i;
        flat_tok[r] = ts >> 1;
        tok2row[ts] = r;
        tok2gate[ts] = bucket_gate[e * Tn + i];
    }
}

// ---------------- gather fp16 rows ----------------
__global__ void gather_h(const __half* __restrict__ nh, const int* __restrict__ flat_tok,
                         __half* __restrict__ xg)
{
    long r = blockIdx.x;
    int t = flat_tok[r];
    uint4* dst = (uint4*)(xg + r * DIMn);
    int nch = DIMn / 8;
    if (t < 0) {
        uint4 zz = make_uint4(0u, 0u, 0u, 0u);
        for (int i = threadIdx.x; i < nch; i += blockDim.x) dst[i] = zz;
    } else {
        const uint4* src = (const uint4*)(nh + (long)t * DIMn);
        for (int i = threadIdx.x; i < nch; i += blockDim.x) dst[i] = src[i];
    }
}

// ---------------- silu(a)*b fp16 ----------------
__global__ void silumul_h(__half2* __restrict__ a, const __half2* __restrict__ b, long n2)
{
    long i = (long)blockIdx.x * blockDim.x + threadIdx.x;
    if (i < n2) {
        float2 x = __half22float2(a[i]);
        float2 y = __half22float2(b[i]);
        float s0 = x.x / (1.f + expf(-x.x));
        float s1 = x.y / (1.f + expf(-x.y));
        a[i] = __float22half2_rn(make_float2(s0 * y.x, s1 * y.y));
    }
}

// ---------------- combine ----------------
__global__ void combine_k(const float* __restrict__ h, const float* __restrict__ sh,
                          const float* __restrict__ eo, const int* __restrict__ tok2row,
                          const float* __restrict__ tok2gate, float* __restrict__ out)
{
    long t = blockIdx.x;
    int r0 = tok2row[t * 2], r1 = tok2row[t * 2 + 1];
    float g0 = tok2gate[t * 2], g1 = tok2gate[t * 2 + 1];
    const float4* H = (const float4*)(h + t * DIMn);
    const float4* SH = (const float4*)(sh + t * DIMn);
    const float4* E0 = (const float4*)(eo + (long)r0 * DIMn);
    const float4* E1 = (const float4*)(eo + (long)r1 * DIMn);
    float4* O = (float4*)(out + t * DIMn);
    for (int i = threadIdx.x; i < DIMn / 4; i += blockDim.x) {
        float4 a = H[i], b = SH[i], c = E0[i], d = E1[i];
        float4 o;
        o.x = a.x + b.x + g0 * c.x + g1 * d.x;
        o.y = a.y + b.y + g0 * c.y + g1 * d.y;
        o.z = a.z + b.z + g0 * c.z + g1 * d.z;
        o.w = a.w + b.w + g0 * c.w + g1 * d.w;
        O[i] = o;
    }
}

// ---------------- host ----------------
#define SYM(p, s) do { void* _q = nullptr; cudaGetSymbolAddress(&_q, s); p = (decltype(p))_q; } while (0)

static void launch_hgemm(int tnw, const __half* A, const __half* B, void* C,
                         int M, int N, int K, int lda, int ldb, int ldc,
                         long sA0, long sA1, long sB0, long sB1, long sC0, long sC1,
                         int ZH, int Z, const int* tileExpert, long wStride,
                         const float* rowscale, long rsStride, int flags)
{
    dim3 grid((N + tnw - 1) / tnw, M / 128, Z);
    int smem = 3 * (128 * AROWB + tnw * AROWB);
    if (tnw == 128)
        hgemm_k<128><<<grid, 256, smem>>>(A, B, C, M, N, K, lda, ldb, ldc,
            sA0, sA1, sB0, sB1, sC0, sC1, ZH, tileExpert, wStride, rowscale, rsStride, flags);
    else
        hgemm_k<256><<<grid, 256, smem>>>(A, B, C, M, N, K, lda, ldb, ldc,
            sA0, sA1, sB0, sB1, sC0, sC1, ZH, tileExpert, wStride, rowscale, rsStride, flags);
}

static void launch_cvt(const float* src, __half* dst, long n)
{
    long n2 = n / 2;
    cvth_k<<<(int)((n2 + 255) / 256), 256>>>((const float2*)src, (__half2*)dst, n2);
}

extern "C" void kernel_launch(void* const* d_in, const int* in_sizes, int n_in,
                              void* d_out, int out_size)
{
    cudaFuncSetAttribute(hgemm_k<128>, cudaFuncAttributeMaxDynamicSharedMemorySize,
                         3 * (128 * AROWB + 128 * AROWB));
    cudaFuncSetAttribute(hgemm_k<256>, cudaFuncAttributeMaxDynamicSharedMemorySize,
                         3 * (128 * AROWB + 256 * AROWB));

    const float* x       = (const float*)d_in[0];
    const float* fcos    = (const float*)d_in[1];
    const float* fsin    = (const float*)d_in[2];
    const float* attn_w  = (const float*)d_in[3];
    const float* wq      = (const float*)d_in[4];
    const float* wkv_a   = (const float*)d_in[5];
    const float* kv_w    = (const float*)d_in[6];
    const float* wkv_b   = (const float*)d_in[7];
    const float* wo      = (const float*)d_in[8];
    const float* ffn_w   = (const float*)d_in[9];
    const float* rw      = (const float*)d_in[10];
    const float* e_w1    = (const float*)d_in[11];
    const float* e_w3    = (const float*)d_in[12];
    const float* e_w2    = (const float*)d_in[13];
    const float* s_w1    = (const float*)d_in[14];
    const float* s_w3    = (const float*)d_in[15];
    const float* s_w2    = (const float*)d_in[16];
    float* out = (float*)d_out;

    float *q, *kv, *kpe, *kvb, *scores, *inv, *h, *eo, *sh;
    __half *nx_h, *ckv_h, *qh, *kcat, *vT, *ph, *attn_h, *nh_h, *xg, *t1h, *t3h, *s1h, *s3h;
    __half *wq_h, *wkva_h, *wkvb_h, *wo_h, *ew1_h, *ew3_h, *ew2_h, *sw1_h, *sw3_h, *sw2_h;
    int *counts, *off, *tile_expert, *bucket_ts, *flat_tok, *tok2row;
    float *bucket_gate, *tok2gate;
    SYM(q, g_q); SYM(kv, g_kv); SYM(kpe, g_kpe); SYM(kvb, g_kvb);
    SYM(scores, g_scores); SYM(inv, g_inv); SYM(h, g_h); SYM(eo, g_eo); SYM(sh, g_sh);
    SYM(nx_h, g_nx_h); SYM(ckv_h, g_ckv_h); SYM(qh, g_qh); SYM(kcat, g_kcat_h);
    SYM(vT, g_vT_h); SYM(ph, g_ph); SYM(attn_h, g_attn_h); SYM(nh_h, g_nh_h);
    SYM(xg, g_xg_h); SYM(t1h, g_t1h); SYM(t3h, g_t3h); SYM(s1h, g_s1h); SYM(s3h, g_s3h);
    SYM(wq_h, g_wq_h); SYM(wkva_h, g_wkva_h); SYM(wkvb_h, g_wkvb_h); SYM(wo_h, g_wo_h);
    SYM(ew1_h, g_ew1_h); SYM(ew3_h, g_ew3_h); SYM(ew2_h, g_ew2_h);
    SYM(sw1_h, g_sw1_h); SYM(sw3_h, g_sw3_h); SYM(sw2_h, g_sw2_h);
    SYM(counts, g_counts); SYM(off, g_off); SYM(tile_expert, g_tile_expert);
    SYM(bucket_ts, g_bucket_ts); SYM(bucket_gate, g_bucket_gate);
    SYM(flat_tok, g_flat_tok); SYM(tok2row, g_tok2row); SYM(tok2gate, g_tok2gate);

    const long SS = (long)Sn * Sn;

    // 0. weight conversion
    launch_cvt(wq, wq_h, (long)QPROJ * DIMn);
    launch_cvt(wkv_a, wkva_h, (long)KVAP * DIMn);
    launch_cvt(wkv_b, wkvb_h, (long)KVBP * KVRn);
    launch_cvt(wo, wo_h, (long)DIMn * DIMn);
    launch_cvt(e_w1, ew1_h, (long)NEn * MINTERn * DIMn);
    launch_cvt(e_w3, ew3_h, (long)NEn * MINTERn * DIMn);
    launch_cvt(e_w2, ew2_h, (long)NEn * DIMn * MINTERn);
    launch_cvt(s_w1, sw1_h, (long)SHIn * DIMn);
    launch_cvt(s_w3, sw3_h, (long)SHIn * DIMn);
    launch_cvt(s_w2, sw2_h, (long)DIMn * SHIn);

    // 1. attention-input rmsnorm -> fp16
    rmsnorm_h<<<Tn, 256>>>(x, attn_w, nx_h, DIMn, DIMn, DIMn);
    // 2. q projection (fp32 out)
    launch_hgemm(256, nx_h, wq_h, q, Tn, QPROJ, DIMn, DIMn, DIMn, QPROJ,
                 0, 0, 0, 0, 0, 0, 1, 1, nullptr, 0, nullptr, 0, 0);
    // 3. kv_a projection (fp32 out)
    launch_hgemm(256, nx_h, wkva_h, kv, Tn, KVAP, DIMn, DIMn, DIMn, KVAP,
                 0, 0, 0, 0, 0, 0, 1, 1, nullptr, 0, nullptr, 0, 0);
    // 4. c_kv rmsnorm -> fp16
    rmsnorm_h<<<Tn, 256>>>(kv, kv_w, ckv_h, KVRn, KVAP, KVRn);
    // 5. rope k_pe (fp32)
    rope_kpe_k<<<Tn, 32>>>(kv, fcos, fsin, kpe);
    // 6. kv_b projection (fp32 out)
    launch_hgemm(256, ckv_h, wkvb_h, kvb, Tn, KVBP, KVRn, KVRn, KVRn, KVBP,
                 0, 0, 0, 0, 0, 0, 1, 1, nullptr, 0, nullptr, 0, 0);
    // 7. rope + scale q -> fp16
    ropescale_qh<<<Tn * NHn, 96>>>(q, fcos, fsin, qh);
    // 8. kcat + vT -> fp16
    { dim3 g(Sn, ZSn); kcat_h<<<g, QDn>>>(kvb, kpe, kcat); }
    { dim3 g(Sn / 32, VHn / 32, ZSn); dim3 b(32, 8); vtrans_h<<<g, b>>>(kvb, vT); }
    // 9. scores = q @ kcat^T (K=192, causal skip, fp32 out)
    launch_hgemm(256, qh, kcat, scores, Sn, Sn, QDn, QPROJ, QDn, Sn,
                 (long)Sn * QPROJ, QDn, 16L * Sn * QDn, (long)Sn * QDn, 16 * SS, SS,
                 16, 32, nullptr, 0, nullptr, 0, 2);
    // 10. softmax -> fp16 P + invsum
    softmax2_h<<<32 * Sn, 256>>>(scores, ph, inv);
    // 11. attn = (P @ V) * invsum -> fp16 (K-limit)
    launch_hgemm(128, ph, vT, attn_h, Sn, VHn, Sn, Sn, Sn, DIMn,
                 16 * SS, SS, 16L * VHn * Sn, (long)VHn * Sn, (long)Sn * DIMn, VHn,
                 16, 32, nullptr, 0, inv, Sn, 4 | 8);
    // 12. h = x + attn @ wo^T
    cudaMemcpyAsync(h, x, (size_t)Tn * DIMn * sizeof(float), cudaMemcpyDeviceToDevice, 0);
    launch_hgemm(256, attn_h, wo_h, h, Tn, DIMn, DIMn, DIMn, DIMn, DIMn,
                 0, 0, 0, 0, 0, 0, 1, 1, nullptr, 0, nullptr, 0, 1);
    // 13. ffn rmsnorm -> fp16
    rmsnorm_h<<<Tn, 256>>>(h, ffn_w, nh_h, DIMn, DIMn, DIMn);
    // 14. routing
    cudaMemsetAsync(counts, 0, NEn * sizeof(int), 0);
    cudaMemsetAsync(flat_tok, 0xFF, MOE_ROWS * sizeof(int), 0);
    router_h<<<Tn, 256>>>(nh_h, rw, counts, bucket_ts, bucket_gate);
    offsets_k<<<1, 1>>>(counts, off, tile_expert);
    compact_k<<<NEn, 256>>>(counts, off, bucket_ts, bucket_gate, flat_tok, tok2row, tok2gate);
    gather_h<<<MOE_ROWS, 256>>>(nh_h, flat_tok, xg);
    // 15. expert FFN (grouped, fp16 intermediates)
    launch_hgemm(256, xg, ew1_h, t1h, MOE_ROWS, MINTERn, DIMn, DIMn, DIMn, MINTERn,
                 0, 0, 0, 0, 0, 0, 1, 1, tile_expert, (long)MINTERn * DIMn, nullptr, 0, 8);
    launch_hgemm(256, xg, ew3_h, t3h, MOE_ROWS, MINTERn, DIMn, DIMn, DIMn, MINTERn,
                 0, 0, 0, 0, 0, 0, 1, 1, tile_expert, (long)MINTERn * DIMn, nullptr, 0, 8);
    {
        long n2 = (long)MOE_ROWS * MINTERn / 2;
        silumul_h<<<(int)((n2 + 255) / 256), 256>>>((__half2*)t1h, (const __half2*)t3h, n2);
    }
    launch_hgemm(256, t1h, ew2_h, eo, MOE_ROWS, DIMn, MINTERn, MINTERn, MINTERn, DIMn,
                 0, 0, 0, 0, 0, 0, 1, 1, tile_expert, (long)DIMn * MINTERn, nullptr, 0, 0);
    // 16. shared FFN (fp16 intermediates)
    launch_hgemm(256, nh_h, sw1_h, s1h, Tn, SHIn, DIMn, DIMn, DIMn, SHIn,
                 0, 0, 0, 0, 0, 0, 1, 1, nullptr, 0, nullptr, 0, 8);
    launch_hgemm(256, nh_h, sw3_h, s3h, Tn, SHIn, DIMn, DIMn, DIMn, SHIn,
                 0, 0, 0, 0, 0, 0, 1, 1, nullptr, 0, nullptr, 0, 8);
    {
        long n2 = (long)Tn * SHIn / 2;
        silumul_h<<<(int)((n2 + 255) / 256), 256>>>((__half2*)s1h, (const __half2*)s3h, n2);
    }
    launch_hgemm(256, s1h, sw2_h, sh, Tn, DIMn, SHIn, SHIn, SHIn, DIMn,
                 0, 0, 0, 0, 0, 0, 1, 1, nullptr, 0, nullptr, 0, 0);
    // 17. combine
    combine_k<<<Tn, 256>>>(h, sh, eo, tok2row, tok2gate, out);
}

// round 9
// speedup vs baseline: 6.8053x; 1.2394x over previous
#include <cuda_runtime.h>
#include <cuda_fp16.h>
#include <math.h>
#include <stdint.h>

// ---------------- problem constants ----------------
#define Tn     4096
#define Sn     2048
#define DIMn   2048
#define NHn    16
#define NOPEn  128
#define ROPEn  64
#define QDn    192
#define VHn    128
#define KVRn   512
#define NEn    8
#define MINTERn 1408
#define SHIn   2816
#define QPROJ  3072
#define KVAP   576
#define KVBP   4096
#define MOE_ROWS 9216
#define MOE_TILES 72
#define ZSn    32

// ---------------- fp32 scratch ----------------
__device__ float g_q[(size_t)Tn*QPROJ];
__device__ float g_kv[(size_t)Tn*KVAP];
__device__ float g_kpe[(size_t)Tn*ROPEn];
__device__ float g_kvb[(size_t)Tn*KVBP];
__device__ float g_scores[(size_t)ZSn*Sn*Sn];
__device__ float g_inv[ZSn*Sn];
__device__ float g_h[(size_t)Tn*DIMn];
__device__ float g_eo[(size_t)MOE_ROWS*DIMn];
__device__ float g_sh[(size_t)Tn*DIMn];
__device__ int   g_counts[NEn];
__device__ int   g_off[NEn+1];
__device__ int   g_tile_expert[MOE_TILES];
__device__ int   g_bucket_ts[NEn*Tn];
__device__ float g_bucket_gate[NEn*Tn];
__device__ int   g_flat_tok[MOE_ROWS];
__device__ int   g_tok2row[Tn*2];
__device__ float g_tok2gate[Tn*2];
// ---------------- fp16 scratch ----------------
__device__ __half g_nx_h[(size_t)Tn*DIMn];
__device__ __half g_ckv_h[(size_t)Tn*KVRn];
__device__ __half g_qh[(size_t)Tn*QPROJ];
__device__ __half g_kcat_h[(size_t)ZSn*Sn*QDn];
__device__ __half g_vT_h[(size_t)ZSn*VHn*Sn];
__device__ __half g_ph[(size_t)ZSn*Sn*Sn];
__device__ __half g_attn_h[(size_t)Tn*DIMn];
__device__ __half g_nh_h[(size_t)Tn*DIMn];
__device__ __half g_xg_h[(size_t)MOE_ROWS*DIMn];
__device__ __half g_t1h[(size_t)MOE_ROWS*MINTERn];
__device__ __half g_t3h[(size_t)MOE_ROWS*MINTERn];
__device__ __half g_s1h[(size_t)Tn*SHIn];
__device__ __half g_s3h[(size_t)Tn*SHIn];
// fp16 weight copies
__device__ __half g_wq_h[(size_t)QPROJ*DIMn];
__device__ __half g_wkva_h[(size_t)KVAP*DIMn];
__device__ __half g_wkvb_h[(size_t)KVBP*KVRn];
__device__ __half g_wo_h[(size_t)DIMn*DIMn];
__device__ __half g_ew1_h[(size_t)NEn*MINTERn*DIMn];
__device__ __half g_ew3_h[(size_t)NEn*MINTERn*DIMn];
__device__ __half g_ew2_h[(size_t)NEn*DIMn*MINTERn];
__device__ __half g_sw1_h[(size_t)SHIn*DIMn];
__device__ __half g_sw3_h[(size_t)SHIn*DIMn];
__device__ __half g_sw2_h[(size_t)DIMn*SHIn];

// ---------------- helpers ----------------
__device__ __forceinline__ void mma16(float* c, const uint32_t* a, const uint32_t* b) {
    asm volatile("mma.sync.aligned.m16n8k16.row.col.f32.f16.f16.f32 "
        "{%0,%1,%2,%3}, {%4,%5,%6,%7}, {%8,%9}, {%0,%1,%2,%3};"
        : "+f"(c[0]), "+f"(c[1]), "+f"(c[2]), "+f"(c[3])
        : "r"(a[0]), "r"(a[1]), "r"(a[2]), "r"(a[3]), "r"(b[0]), "r"(b[1]));
}
__device__ __forceinline__ void ldsm4(uint32_t* r, uint32_t addr) {
    asm volatile("ldmatrix.sync.aligned.m8n8.x4.shared.b16 {%0,%1,%2,%3}, [%4];"
        : "=r"(r[0]), "=r"(r[1]), "=r"(r[2]), "=r"(r[3]) : "r"(addr));
}
__device__ __forceinline__ void cpasync16(uint32_t dst, const void* src, int sz) {
    asm volatile("cp.async.cg.shared.global [%0], [%1], 16, %2;"
                 :: "r"(dst), "l"(src), "r"(sz));
}
__device__ __forceinline__ void cpcommit() { asm volatile("cp.async.commit_group;"); }
__device__ __forceinline__ void cpwait1() { asm volatile("cp.async.wait_group 1;"); }

// ---------------- fp16 tensor GEMM, 128x128 CTA, 2 CTAs/SM ----------------
// C[M,N] = A[M,K] @ B[N,K]^T, K-major fp16, fp32 accumulate. M%128==0, K%32==0.
// flags: 1 accumulate(fp32 out), 2 causal tile skip, 4 causal K-limit, 8 fp16 out
#define LDPH 20                      // uint32 per SMEM row (16 data + 4 pad)
#define AROWB (LDPH*4)               // 80 bytes
#define TNW 128
#define NTT 4
#define ABY (128*AROWB)
#define STG (2*ABY)
#define HG_SMEM (3*STG)              // 61440 B

__global__ __launch_bounds__(256, 2) void hgemm_k(
    const __half* __restrict__ A, const __half* __restrict__ B, void* __restrict__ Cv,
    int M, int N, int K, int lda, int ldb, int ldc,
    long sA0, long sA1, long sB0, long sB1, long sC0, long sC1, int ZH,
    const int* __restrict__ tileExpert, long wStride,
    const float* __restrict__ rowscale, long rsStride, int flags)
{
    int bx = blockIdx.x, by = blockIdx.y, z = blockIdx.z;
    if ((flags & 2) && bx > by) return;
    if (tileExpert) { int te = tileExpert[by]; if (te < 0) return; B += (long)te * wStride; }
    int zb = z / ZH, zh = z - zb * ZH;
    A += zb * sA0 + (long)zh * sA1;
    B += zb * sB0 + (long)zh * sB1;
    int Keff = K;
    if (flags & 4) { int kl = (by + 1) * 128; if (kl < Keff) Keff = kl; }
    int NT = Keff >> 5;

    extern __shared__ char smraw[];
    uint32_t sb = (uint32_t)__cvta_generic_to_shared(smraw);

    int tid = threadIdx.x;
    int wid = tid >> 5, lane = tid & 31;
    int wy = wid & 1, wx = wid >> 1;

    // ldmatrix per-lane offsets
    int grp = lane >> 3, lrow = lane & 7;
    uint32_t aoff = (uint32_t)((wy * 64 + (grp & 1) * 8 + lrow) * AROWB + (grp >> 1) * 16);
    uint32_t boff = (uint32_t)((wx * 32 + (grp >> 1) * 8 + lrow) * AROWB + (grp & 1) * 16);

    // cp.async mapping: 16B = 8 halves; 4 chunks per 32-half row; 2 chunks each of A,B
    int ar0 = tid >> 2, ac0 = tid & 3;
    int bsz[2];
#pragma unroll
    for (int ch = 0; ch < 2; ch++) {
        int row = ar0 + ch * 64;
        bsz[ch] = ((bx * TNW + row) < N) ? 16 : 0;
    }
    const __half* bsrc0 = B;

    auto issue = [&](int s, int k0) {
        uint32_t Ab = sb + s * STG;
        uint32_t Bb = Ab + ABY;
#pragma unroll
        for (int ch = 0; ch < 2; ch++) {
            int row = ar0 + ch * 64;
            const __half* src = A + (long)(by * 128 + row) * lda + k0 + ac0 * 8;
            cpasync16(Ab + row * AROWB + ac0 * 16, src, 16);
        }
#pragma unroll
        for (int ch = 0; ch < 2; ch++) {
            int row = ar0 + ch * 64;
            const __half* src = bsz[ch] ? (B + (long)(bx * TNW + row) * ldb + k0 + ac0 * 8) : bsrc0;
            cpasync16(Bb + row * AROWB + ac0 * 16, src, bsz[ch]);
        }
    };

#pragma unroll
    for (int s = 0; s < 2; s++) {
        if (s < NT) issue(s, s * 32);
        cpcommit();
    }

    float acc[4][NTT][4];
#pragma unroll
    for (int mt = 0; mt < 4; mt++)
#pragma unroll
        for (int nt = 0; nt < NTT; nt++)
#pragma unroll
            for (int i = 0; i < 4; i++) acc[mt][nt][i] = 0.f;

    for (int it = 0; it < NT; ++it) {
        cpwait1();
        __syncthreads();
        if (it + 2 < NT) issue((it + 2) % 3, (it + 2) * 32);
        cpcommit();

        int st = it % 3;
        uint32_t Abase = sb + st * STG + aoff;
        uint32_t Bbase = sb + st * STG + ABY + boff;
#pragma unroll
        for (int ks = 0; ks < 2; ks++) {
            uint32_t af[4][4], bf[NTT][2];
#pragma unroll
            for (int mt = 0; mt < 4; mt++)
                ldsm4(af[mt], Abase + mt * (16 * AROWB) + ks * 32);
#pragma unroll
            for (int p = 0; p < NTT / 2; p++) {
                uint32_t r[4];
                ldsm4(r, Bbase + p * (16 * AROWB) + ks * 32);
                bf[2 * p][0] = r[0]; bf[2 * p][1] = r[1];
                bf[2 * p + 1][0] = r[2]; bf[2 * p + 1][1] = r[3];
            }
#pragma unroll
            for (int mt = 0; mt < 4; mt++)
#pragma unroll
                for (int nt = 0; nt < NTT; nt++)
                    mma16(acc[mt][nt], af[mt], bf[nt]);
        }
        __syncthreads();
    }

    // epilogue
    bool doacc = (flags & 1) != 0;
    bool outh = (flags & 8) != 0;
    long zr = (long)z * rsStride;
    float* Cf = (float*)Cv + zb * sC0 + (long)zh * sC1;
    __half* Ch = (__half*)Cv + zb * sC0 + (long)zh * sC1;
    int elr = lane >> 2, elk = lane & 3;
#pragma unroll
    for (int mt = 0; mt < 4; mt++) {
        int m0 = by * 128 + wy * 64 + mt * 16 + elr;
        float rs0 = 1.f, rs1 = 1.f;
        if (rowscale) { rs0 = rowscale[zr + m0]; rs1 = rowscale[zr + m0 + 8]; }
#pragma unroll
        for (int nt = 0; nt < NTT; nt++) {
            int c0 = bx * TNW + wx * 32 + nt * 8 + 2 * elk;
            if (c0 < N) {
                float2 v0 = make_float2(acc[mt][nt][0] * rs0, acc[mt][nt][1] * rs0);
                float2 v1 = make_float2(acc[mt][nt][2] * rs1, acc[mt][nt][3] * rs1);
                if (outh) {
                    *(__half2*)(Ch + (long)m0 * ldc + c0) = __float22half2_rn(v0);
                    *(__half2*)(Ch + (long)(m0 + 8) * ldc + c0) = __float22half2_rn(v1);
                } else {
                    float* p0 = Cf + (long)m0 * ldc + c0;
                    float* p1 = Cf + (long)(m0 + 8) * ldc + c0;
                    if (doacc) {
                        float2 o0 = *(const float2*)p0, o1 = *(const float2*)p1;
                        v0.x += o0.x; v0.y += o0.y; v1.x += o1.x; v1.y += o1.y;
                    }
                    *(float2*)p0 = v0;
                    *(float2*)p1 = v1;
                }
            }
        }
    }
}

// ---------------- weight fp32 -> fp16 ----------------
__global__ void cvth_k(const float2* __restrict__ src, __half2* __restrict__ dst, long n2)
{
    long i = (long)blockIdx.x * blockDim.x + threadIdx.x;
    if (i < n2) dst[i] = __float22half2_rn(src[i]);
}

// ---------------- reductions ----------------
__device__ __forceinline__ float warpSum(float v) {
#pragma unroll
    for (int o = 16; o; o >>= 1) v += __shfl_xor_sync(0xffffffffu, v, o);
    return v;
}
__device__ __forceinline__ float warpMax(float v) {
#pragma unroll
    for (int o = 16; o; o >>= 1) v = fmaxf(v, __shfl_xor_sync(0xffffffffu, v, o));
    return v;
}

// ---------------- rmsnorm: fp32 in -> fp16 out ----------------
__global__ void rmsnorm_h(const float* __restrict__ x, const float* __restrict__ w,
                          __half* __restrict__ y, int D, int ldx, int ldy)
{
    long t = blockIdx.x;
    const float* xr = x + t * ldx;
    __half* yr = y + t * ldy;
    float s = 0.f;
    for (int d = threadIdx.x; d < D; d += blockDim.x) { float v = xr[d]; s += v * v; }
    __shared__ float sh[32];
    __shared__ float bc;
    s = warpSum(s);
    int lane = threadIdx.x & 31, wp = threadIdx.x >> 5;
    if (!lane) sh[wp] = s;
    __syncthreads();
    if (threadIdx.x < 32) {
        float r = (threadIdx.x < (blockDim.x >> 5)) ? sh[threadIdx.x] : 0.f;
        r = warpSum(r);
        if (!threadIdx.x) bc = rsqrtf(r / D + 1e-6f);
    }
    __syncthreads();
    float sc = bc;
    for (int d = threadIdx.x; d < D; d += blockDim.x)
        yr[d] = __float2half_rn(xr[d] * sc * w[d]);
}

// ---------------- rope on k_pe (fp32) ----------------
__global__ void rope_kpe_k(const float* __restrict__ kv, const float* __restrict__ fc,
                           const float* __restrict__ fs, float* __restrict__ kpe)
{
    long t = blockIdx.x;
    int j = threadIdx.x;
    int pos = (int)(t % Sn);
    float x1 = kv[t * KVAP + KVRn + 2 * j];
    float x2 = kv[t * KVAP + KVRn + 2 * j + 1];
    float c = fc[pos * 32 + j], s = fs[pos * 32 + j];
    kpe[t * ROPEn + 2 * j]     = x1 * c - x2 * s;
    kpe[t * ROPEn + 2 * j + 1] = x1 * s + x2 * c;
}

// ---------------- rope + scale on q: fp32 in -> fp16 out ----------------
__global__ void ropescale_qh(const float* __restrict__ q, const float* __restrict__ fc,
                             const float* __restrict__ fs, __half* __restrict__ qh)
{
    long th = blockIdx.x;
    int pos = (int)((th >> 4) % Sn);
    const float* r = q + th * QDn;
    __half* o = qh + th * QDn;
    int i = threadIdx.x;
    const float sc = 0.07216878364870322f;   // 1/sqrt(192)
    if (i < 64) {
        o[2 * i]     = __float2half_rn(r[2 * i] * sc);
        o[2 * i + 1] = __float2half_rn(r[2 * i + 1] * sc);
    } else {
        int j = i - 64;
        float x1 = r[128 + 2 * j], x2 = r[128 + 2 * j + 1];
        float c = fc[pos * 32 + j], s = fs[pos * 32 + j];
        o[128 + 2 * j]     = __float2half_rn((x1 * c - x2 * s) * sc);
        o[128 + 2 * j + 1] = __float2half_rn((x1 * s + x2 * c) * sc);
    }
}

// ---------------- [k_nope | k_pe] concat -> fp16 ----------------
__global__ void kcat_h(const float* __restrict__ kvb, const float* __restrict__ kpe,
                       __half* __restrict__ kcat)
{
    int s = blockIdx.x, z = blockIdx.y, j = threadIdx.x;
    long t = (long)(z >> 4) * Sn + s;
    float v = (j < NOPEn) ? kvb[t * KVBP + (z & 15) * 256 + j]
                          : kpe[t * ROPEn + (j - NOPEn)];
    kcat[((long)z * Sn + s) * QDn + j] = __float2half_rn(v);
}

// ---------------- transpose V -> vT fp16 ----------------
__global__ void vtrans_h(const float* __restrict__ kvb, __half* __restrict__ vT)
{
    __shared__ float tsm[32][33];
    int z = blockIdx.z, zb = z >> 4, zh = z & 15;
    int kt = blockIdx.x * 32, dt = blockIdx.y * 32;
    int tx = threadIdx.x, ty = threadIdx.y;
#pragma unroll
    for (int i = 0; i < 4; i++) {
        int k = kt + ty + i * 8;
        tsm[ty + i * 8][tx] = kvb[((long)zb * Sn + k) * KVBP + zh * 256 + NOPEn + dt + tx];
    }
    __syncthreads();
#pragma unroll
    for (int i = 0; i < 4; i++) {
        int d = dt + ty + i * 8;
        vT[((long)z * VHn + d) * Sn + kt + tx] = __float2half_rn(tsm[tx][ty + i * 8]);
    }
}

// ---------------- softmax: fp32 scores -> fp16 P (unnormalized) + invsum ----------------
__global__ void softmax2_h(const float* __restrict__ scores, __half* __restrict__ ph,
                           float* __restrict__ inv)
{
    long rowi = blockIdx.x;
    int q = (int)(rowi % Sn);
    const float* p = scores + rowi * Sn;
    __half* po = ph + rowi * Sn;
    int n = q + 1;
    float m = -3.4e38f;
    for (int k = threadIdx.x; k < n; k += blockDim.x) m = fmaxf(m, p[k]);
    __shared__ float shm[32];
    __shared__ float bc0;
    m = warpMax(m);
    int lane = threadIdx.x & 31, wp = threadIdx.x >> 5;
    if (!lane) shm[wp] = m;
    __syncthreads();
    if (threadIdx.x < 32) {
        float r = (threadIdx.x < (blockDim.x >> 5)) ? shm[threadIdx.x] : -3.4e38f;
        r = warpMax(r);
        if (!threadIdx.x) bc0 = r;
    }
    __syncthreads();
    m = bc0;
    float sum = 0.f;
    for (int k = threadIdx.x; k < n; k += blockDim.x) {
        float e = expf(p[k] - m);
        po[k] = __float2half_rn(e);
        sum += e;
    }
    __syncthreads();
    sum = warpSum(sum);
    if (!lane) shm[wp] = sum;
    __syncthreads();
    if (threadIdx.x < 32) {
        float r = (threadIdx.x < (blockDim.x >> 5)) ? shm[threadIdx.x] : 0.f;
        r = warpSum(r);
        if (!threadIdx.x) inv[rowi] = 1.f / r;
    }
    int kend = ((q >> 7) + 1) << 7;
    for (int k = n + threadIdx.x; k < kend; k += blockDim.x) po[k] = __half(0.f);
}

// ---------------- router (reads fp16 nh) ----------------
__global__ void router_h(const __half* __restrict__ nh, const float* __restrict__ rw,
                         int* __restrict__ counts, int* __restrict__ bucket_ts,
                         float* __restrict__ bucket_gate)
{
    long t = blockIdx.x;
    int wp = threadIdx.x >> 5, lane = threadIdx.x & 31;
    const __half* xr = nh + t * DIMn;
    float s = 0.f;
    for (int d = lane; d < DIMn; d += 32) s += __half2float(xr[d]) * rw[(long)wp * DIMn + d];
    s = warpSum(s);
    __shared__ float logit[NEn];
    if (!lane) logit[wp] = s;
    __syncthreads();
    if (threadIdx.x == 0) {
        float mx = logit[0];
#pragma unroll
        for (int e = 1; e < NEn; e++) mx = fmaxf(mx, logit[e]);
        float p[NEn];
#pragma unroll
        for (int e = 0; e < NEn; e++) p[e] = expf(logit[e] - mx);
        int i0 = 0;
#pragma unroll
        for (int e = 1; e < NEn; e++) if (p[e] > p[i0]) i0 = e;
        int i1 = (i0 == 0) ? 1 : 0;
#pragma unroll
        for (int e = 0; e < NEn; e++) if (e != i0 && p[e] > p[i1]) i1 = e;
        float denom = p[i0] + p[i1];
        float g0 = p[i0] / denom, g1 = p[i1] / denom;
        int pos0 = atomicAdd(&counts[i0], 1);
        bucket_ts[i0 * Tn + pos0] = (int)(t * 2);
        bucket_gate[i0 * Tn + pos0] = g0;
        int pos1 = atomicAdd(&counts[i1], 1);
        bucket_ts[i1 * Tn + pos1] = (int)(t * 2 + 1);
        bucket_gate[i1 * Tn + pos1] = g1;
    }
}

__global__ void offsets_k(const int* __restrict__ counts, int* __restrict__ off,
                          int* __restrict__ tile_expert)
{
    for (int tl = 0; tl < MOE_TILES; tl++) tile_expert[tl] = -1;
    int o = 0;
    for (int e = 0; e < NEn; e++) {
        off[e] = o;
        int nt = (counts[e] + 127) >> 7;
        for (int i = 0; i < nt; i++) tile_expert[(o >> 7) + i] = e;
        o += nt * 128;
    }
    off[NEn] = o;
}

__global__ void compact_k(const int* __restrict__ counts, const int* __restrict__ off,
                          const int* __restrict__ bucket_ts, const float* __restrict__ bucket_gate,
                          int* __restrict__ flat_tok, int* __restrict__ tok2row,
                          float* __restrict__ tok2gate)
{
    int e = blockIdx.x;
    int cnt = counts[e], base = off[e];
    for (int i = threadIdx.x; i < cnt; i += blockDim.x) {
        int ts = bucket_ts[e * Tn + i];
        int r = base + i;
        flat_tok[r] = ts >> 1;
        tok2row[ts] = r;
        tok2gate[ts] = bucket_gate[e * Tn + i];
    }
}

// ---------------- gather fp16 rows ----------------
__global__ void gather_h(const __half* __restrict__ nh, const int* __restrict__ flat_tok,
                         __half* __restrict__ xg)
{
    long r = blockIdx.x;
    int t = flat_tok[r];
    uint4* dst = (uint4*)(xg + r * DIMn);
    int nch = DIMn / 8;
    if (t < 0) {
        uint4 zz = make_uint4(0u, 0u, 0u, 0u);
        for (int i = threadIdx.x; i < nch; i += blockDim.x) dst[i] = zz;
    } else {
        const uint4* src = (const uint4*)(nh + (long)t * DIMn);
        for (int i = threadIdx.x; i < nch; i += blockDim.x) dst[i] = src[i];
    }
}

// ---------------- silu(a)*b fp16 ----------------
__global__ void silumul_h(__half2* __restrict__ a, const __half2* __restrict__ b, long n2)
{
    long i = (long)blockIdx.x * blockDim.x + threadIdx.x;
    if (i < n2) {
        float2 x = __half22float2(a[i]);
        float2 y = __half22float2(b[i]);
        float s0 = x.x / (1.f + expf(-x.x));
        float s1 = x.y / (1.f + expf(-x.y));
        a[i] = __float22half2_rn(make_float2(s0 * y.x, s1 * y.y));
    }
}

// ---------------- combine ----------------
__global__ void combine_k(const float* __restrict__ h, const float* __restrict__ sh,
                          const float* __restrict__ eo, const int* __restrict__ tok2row,
                          const float* __restrict__ tok2gate, float* __restrict__ out)
{
    long t = blockIdx.x;
    int r0 = tok2row[t * 2], r1 = tok2row[t * 2 + 1];
    float g0 = tok2gate[t * 2], g1 = tok2gate[t * 2 + 1];
    const float4* H = (const float4*)(h + t * DIMn);
    const float4* SH = (const float4*)(sh + t * DIMn);
    const float4* E0 = (const float4*)(eo + (long)r0 * DIMn);
    const float4* E1 = (const float4*)(eo + (long)r1 * DIMn);
    float4* O = (float4*)(out + t * DIMn);
    for (int i = threadIdx.x; i < DIMn / 4; i += blockDim.x) {
        float4 a = H[i], b = SH[i], c = E0[i], d = E1[i];
        float4 o;
        o.x = a.x + b.x + g0 * c.x + g1 * d.x;
        o.y = a.y + b.y + g0 * c.y + g1 * d.y;
        o.z = a.z + b.z + g0 * c.z + g1 * d.z;
        o.w = a.w + b.w + g0 * c.w + g1 * d.w;
        O[i] = o;
    }
}

// ---------------- host ----------------
#define SYM(p, s) do { void* _q = nullptr; cudaGetSymbolAddress(&_q, s); p = (decltype(p))_q; } while (0)

static void launch_hgemm(const __half* A, const __half* B, void* C,
                         int M, int N, int K, int lda, int ldb, int ldc,
                         long sA0, long sA1, long sB0, long sB1, long sC0, long sC1,
                         int ZH, int Z, const int* tileExpert, long wStride,
                         const float* rowscale, long rsStride, int flags)
{
    dim3 grid((N + TNW - 1) / TNW, M / 128, Z);
    hgemm_k<<<grid, 256, HG_SMEM>>>(A, B, C, M, N, K, lda, ldb, ldc,
        sA0, sA1, sB0, sB1, sC0, sC1, ZH, tileExpert, wStride, rowscale, rsStride, flags);
}

static void launch_cvt(const float* src, __half* dst, long n)
{
    long n2 = n / 2;
    cvth_k<<<(int)((n2 + 255) / 256), 256>>>((const float2*)src, (__half2*)dst, n2);
}

extern "C" void kernel_launch(void* const* d_in, const int* in_sizes, int n_in,
                              void* d_out, int out_size)
{
    cudaFuncSetAttribute(hgemm_k, cudaFuncAttributeMaxDynamicSharedMemorySize, HG_SMEM);

    const float* x       = (const float*)d_in[0];
    const float* fcos    = (const float*)d_in[1];
    const float* fsin    = (const float*)d_in[2];
    const float* attn_w  = (const float*)d_in[3];
    const float* wq      = (const float*)d_in[4];
    const float* wkv_a   = (const float*)d_in[5];
    const float* kv_w    = (const float*)d_in[6];
    const float* wkv_b   = (const float*)d_in[7];
    const float* wo      = (const float*)d_in[8];
    const float* ffn_w   = (const float*)d_in[9];
    const float* rw      = (const float*)d_in[10];
    const float* e_w1    = (const float*)d_in[11];
    const float* e_w3    = (const float*)d_in[12];
    const float* e_w2    = (const float*)d_in[13];
    const float* s_w1    = (const float*)d_in[14];
    const float* s_w3    = (const float*)d_in[15];
    const float* s_w2    = (const float*)d_in[16];
    float* out = (float*)d_out;

    float *q, *kv, *kpe, *kvb, *scores, *inv, *h, *eo, *sh;
    __half *nx_h, *ckv_h, *qh, *kcat, *vT, *ph, *attn_h, *nh_h, *xg, *t1h, *t3h, *s1h, *s3h;
    __half *wq_h, *wkva_h, *wkvb_h, *wo_h, *ew1_h, *ew3_h, *ew2_h, *sw1_h, *sw3_h, *sw2_h;
    int *counts, *off, *tile_expert, *bucket_ts, *flat_tok, *tok2row;
    float *bucket_gate, *tok2gate;
    SYM(q, g_q); SYM(kv, g_kv); SYM(kpe, g_kpe); SYM(kvb, g_kvb);
    SYM(scores, g_scores); SYM(inv, g_inv); SYM(h, g_h); SYM(eo, g_eo); SYM(sh, g_sh);
    SYM(nx_h, g_nx_h); SYM(ckv_h, g_ckv_h); SYM(qh, g_qh); SYM(kcat, g_kcat_h);
    SYM(vT, g_vT_h); SYM(ph, g_ph); SYM(attn_h, g_attn_h); SYM(nh_h, g_nh_h);
    SYM(xg, g_xg_h); SYM(t1h, g_t1h); SYM(t3h, g_t3h); SYM(s1h, g_s1h); SYM(s3h, g_s3h);
    SYM(wq_h, g_wq_h); SYM(wkva_h, g_wkva_h); SYM(wkvb_h, g_wkvb_h); SYM(wo_h, g_wo_h);
    SYM(ew1_h, g_ew1_h); SYM(ew3_h, g_ew3_h); SYM(ew2_h, g_ew2_h);
    SYM(sw1_h, g_sw1_h); SYM(sw3_h, g_sw3_h); SYM(sw2_h, g_sw2_h);
    SYM(counts, g_counts); SYM(off, g_off); SYM(tile_expert, g_tile_expert);
    SYM(bucket_ts, g_bucket_ts); SYM(bucket_gate, g_bucket_gate);
    SYM(flat_tok, g_flat_tok); SYM(tok2row, g_tok2row); SYM(tok2gate, g_tok2gate);

    const long SS = (long)Sn * Sn;

    // 0. weight conversion
    launch_cvt(wq, wq_h, (long)QPROJ * DIMn);
    launch_cvt(wkv_a, wkva_h, (long)KVAP * DIMn);
    launch_cvt(wkv_b, wkvb_h, (long)KVBP * KVRn);
    launch_cvt(wo, wo_h, (long)DIMn * DIMn);
    launch_cvt(e_w1, ew1_h, (long)NEn * MINTERn * DIMn);
    launch_cvt(e_w3, ew3_h, (long)NEn * MINTERn * DIMn);
    launch_cvt(e_w2, ew2_h, (long)NEn * DIMn * MINTERn);
    launch_cvt(s_w1, sw1_h, (long)SHIn * DIMn);
    launch_cvt(s_w3, sw3_h, (long)SHIn * DIMn);
    launch_cvt(s_w2, sw2_h, (long)DIMn * SHIn);

    // 1. attention-input rmsnorm -> fp16
    rmsnorm_h<<<Tn, 256>>>(x, attn_w, nx_h, DIMn, DIMn, DIMn);
    // 2. q projection (fp32 out)
    launch_hgemm(nx_h, wq_h, q, Tn, QPROJ, DIMn, DIMn, DIMn, QPROJ,
                 0, 0, 0, 0, 0, 0, 1, 1, nullptr, 0, nullptr, 0, 0);
    // 3. kv_a projection (fp32 out)
    launch_hgemm(nx_h, wkva_h, kv, Tn, KVAP, DIMn, DIMn, DIMn, KVAP,
                 0, 0, 0, 0, 0, 0, 1, 1, nullptr, 0, nullptr, 0, 0);
    // 4. c_kv rmsnorm -> fp16
    rmsnorm_h<<<Tn, 256>>>(kv, kv_w, ckv_h, KVRn, KVAP, KVRn);
    // 5. rope k_pe (fp32)
    rope_kpe_k<<<Tn, 32>>>(kv, fcos, fsin, kpe);
    // 6. kv_b projection (fp32 out)
    launch_hgemm(ckv_h, wkvb_h, kvb, Tn, KVBP, KVRn, KVRn, KVRn, KVBP,
                 0, 0, 0, 0, 0, 0, 1, 1, nullptr, 0, nullptr, 0, 0);
    // 7. rope + scale q -> fp16
    ropescale_qh<<<Tn * NHn, 96>>>(q, fcos, fsin, qh);
    // 8. kcat + vT -> fp16
    { dim3 g(Sn, ZSn); kcat_h<<<g, QDn>>>(kvb, kpe, kcat); }
    { dim3 g(Sn / 32, VHn / 32, ZSn); dim3 b(32, 8); vtrans_h<<<g, b>>>(kvb, vT); }
    // 9. scores = q @ kcat^T (K=192, causal skip, fp32 out)
    launch_hgemm(qh, kcat, scores, Sn, Sn, QDn, QPROJ, QDn, Sn,
                 (long)Sn * QPROJ, QDn, 16L * Sn * QDn, (long)Sn * QDn, 16 * SS, SS,
                 16, 32, nullptr, 0, nullptr, 0, 2);
    // 10. softmax -> fp16 P + invsum
    softmax2_h<<<32 * Sn, 256>>>(scores, ph, inv);
    // 11. attn = (P @ V) * invsum -> fp16 (K-limit)
    launch_hgemm(ph, vT, attn_h, Sn, VHn, Sn, Sn, Sn, DIMn,
                 16 * SS, SS, 16L * VHn * Sn, (long)VHn * Sn, (long)Sn * DIMn, VHn,
                 16, 32, nullptr, 0, inv, Sn, 4 | 8);
    // 12. h = x + attn @ wo^T
    cudaMemcpyAsync(h, x, (size_t)Tn * DIMn * sizeof(float), cudaMemcpyDeviceToDevice, 0);
    launch_hgemm(attn_h, wo_h, h, Tn, DIMn, DIMn, DIMn, DIMn, DIMn,
                 0, 0, 0, 0, 0, 0, 1, 1, nullptr, 0, nullptr, 0, 1);
    // 13. ffn rmsnorm -> fp16
    rmsnorm_h<<<Tn, 256>>>(h, ffn_w, nh_h, DIMn, DIMn, DIMn);
    // 14. routing
    cudaMemsetAsync(counts, 0, NEn * sizeof(int), 0);
    cudaMemsetAsync(flat_tok, 0xFF, MOE_ROWS * sizeof(int), 0);
    router_h<<<Tn, 256>>>(nh_h, rw, counts, bucket_ts, bucket_gate);
    offsets_k<<<1, 1>>>(counts, off, tile_expert);
    compact_k<<<NEn, 256>>>(counts, off, bucket_ts, bucket_gate, flat_tok, tok2row, tok2gate);
    gather_h<<<MOE_ROWS, 256>>>(nh_h, flat_tok, xg);
    // 15. expert FFN (grouped, fp16 intermediates)
    launch_hgemm(xg, ew1_h, t1h, MOE_ROWS, MINTERn, DIMn, DIMn, DIMn, MINTERn,
                 0, 0, 0, 0, 0, 0, 1, 1, tile_expert, (long)MINTERn * DIMn, nullptr, 0, 8);
    launch_hgemm(xg, ew3_h, t3h, MOE_ROWS, MINTERn, DIMn, DIMn, DIMn, MINTERn,
                 0, 0, 0, 0, 0, 0, 1, 1, tile_expert, (long)MINTERn * DIMn, nullptr, 0, 8);
    {
        long n2 = (long)MOE_ROWS * MINTERn / 2;
        silumul_h<<<(int)((n2 + 255) / 256), 256>>>((__half2*)t1h, (const __half2*)t3h, n2);
    }
    launch_hgemm(t1h, ew2_h, eo, MOE_ROWS, DIMn, MINTERn, MINTERn, MINTERn, DIMn,
                 0, 0, 0, 0, 0, 0, 1, 1, tile_expert, (long)DIMn * MINTERn, nullptr, 0, 0);
    // 16. shared FFN (fp16 intermediates)
    launch_hgemm(nh_h, sw1_h, s1h, Tn, SHIn, DIMn, DIMn, DIMn, SHIn,
                 0, 0, 0, 0, 0, 0, 1, 1, nullptr, 0, nullptr, 0, 8);
    launch_hgemm(nh_h, sw3_h, s3h, Tn, SHIn, DIMn, DIMn, DIMn, SHIn,
                 0, 0, 0, 0, 0, 0, 1, 1, nullptr, 0, nullptr, 0, 8);
    {
        long n2 = (long)Tn * SHIn / 2;
        silumul_h<<<(int)((n2 + 255) / 256), 256>>>((__half2*)s1h, (const __half2*)s3h, n2);
    }
    launch_hgemm(s1h, sw2_h, sh, Tn, DIMn, SHIn, SHIn, SHIn, DIMn,
                 0, 0, 0, 0, 0, 0, 1, 1, nullptr, 0, nullptr, 0, 0);
    // 17. combine
    combine_k<<<Tn, 256>>>(h, sh, eo, tok2row, tok2gate, out);
}

// round 10
// speedup vs baseline: 7.0720x; 1.0392x over previous
#include <cuda_runtime.h>
#include <cuda_fp16.h>
#include <math.h>
#include <stdint.h>

// ---------------- problem constants ----------------
#define Tn     4096
#define Sn     2048
#define DIMn   2048
#define NHn    16
#define NOPEn  128
#define ROPEn  64
#define QDn    192
#define VHn    128
#define KVRn   512
#define NEn    8
#define MINTERn 1408
#define SHIn   2816
#define QPROJ  3072
#define KVAP   576
#define KVBP   4096
#define MOE_ROWS 9216
#define MOE_TILES 72
#define ZSn    32

// ---------------- fp32 scratch ----------------
__device__ float g_q[(size_t)Tn*QPROJ];
__device__ float g_kv[(size_t)Tn*KVAP];
__device__ float g_kpe[(size_t)Tn*ROPEn];
__device__ float g_kvb[(size_t)Tn*KVBP];
__device__ float g_scores[(size_t)ZSn*Sn*Sn];
__device__ float g_inv[ZSn*Sn];
__device__ float g_h[(size_t)Tn*DIMn];
__device__ float g_eo[(size_t)MOE_ROWS*DIMn];
__device__ float g_sh[(size_t)Tn*DIMn];
__device__ int   g_counts[NEn];
__device__ int   g_off[NEn+1];
__device__ int   g_tile_expert[MOE_TILES];
__device__ int   g_bucket_ts[NEn*Tn];
__device__ float g_bucket_gate[NEn*Tn];
__device__ int   g_flat_tok[MOE_ROWS];
__device__ int   g_tok2row[Tn*2];
__device__ float g_tok2gate[Tn*2];
// ---------------- fp16 scratch ----------------
__device__ __half g_nx_h[(size_t)Tn*DIMn];
__device__ __half g_ckv_h[(size_t)Tn*KVRn];
__device__ __half g_qh[(size_t)Tn*QPROJ];
__device__ __half g_kcat_h[(size_t)ZSn*Sn*QDn];
__device__ __half g_vT_h[(size_t)ZSn*VHn*Sn];
__device__ __half g_ph[(size_t)ZSn*Sn*Sn];
__device__ __half g_attn_h[(size_t)Tn*DIMn];
__device__ __half g_nh_h[(size_t)Tn*DIMn];
__device__ __half g_xg_h[(size_t)MOE_ROWS*DIMn];
__device__ __half g_t13h[(size_t)MOE_ROWS*2*MINTERn];
__device__ __half g_t1h[(size_t)MOE_ROWS*MINTERn];
__device__ __half g_s13h[(size_t)Tn*2*SHIn];
__device__ __half g_s1h[(size_t)Tn*SHIn];
// fp16 weight copies
__device__ __half g_wq_h[(size_t)QPROJ*DIMn];
__device__ __half g_wkva_h[(size_t)KVAP*DIMn];
__device__ __half g_wkvb_h[(size_t)KVBP*KVRn];
__device__ __half g_wo_h[(size_t)DIMn*DIMn];
__device__ __half g_ew13_h[(size_t)NEn*2*MINTERn*DIMn];
__device__ __half g_ew2_h[(size_t)NEn*DIMn*MINTERn];
__device__ __half g_sw13_h[(size_t)2*SHIn*DIMn];
__device__ __half g_sw2_h[(size_t)DIMn*SHIn];

// ---------------- helpers ----------------
__device__ __forceinline__ void mma16(float* c, const uint32_t* a, const uint32_t* b) {
    asm volatile("mma.sync.aligned.m16n8k16.row.col.f32.f16.f16.f32 "
        "{%0,%1,%2,%3}, {%4,%5,%6,%7}, {%8,%9}, {%0,%1,%2,%3};"
        : "+f"(c[0]), "+f"(c[1]), "+f"(c[2]), "+f"(c[3])
        : "r"(a[0]), "r"(a[1]), "r"(a[2]), "r"(a[3]), "r"(b[0]), "r"(b[1]));
}
__device__ __forceinline__ void ldsm4(uint32_t* r, uint32_t addr) {
    asm volatile("ldmatrix.sync.aligned.m8n8.x4.shared.b16 {%0,%1,%2,%3}, [%4];"
        : "=r"(r[0]), "=r"(r[1]), "=r"(r[2]), "=r"(r[3]) : "r"(addr));
}
__device__ __forceinline__ void cpasync16(uint32_t dst, const void* src, int sz) {
    asm volatile("cp.async.cg.shared.global [%0], [%1], 16, %2;"
                 :: "r"(dst), "l"(src), "r"(sz));
}
__device__ __forceinline__ void cpcommit() { asm volatile("cp.async.commit_group;"); }
__device__ __forceinline__ void cpwait2() { asm volatile("cp.async.wait_group 2;"); }

// ---------------- fp16 tensor GEMM, 128x128 CTA, 4-stage, 2 CTAs/SM ----------------
// C[M,N] = A[M,K] @ B[N,K]^T, K-major fp16, fp32 accumulate. M%128==0, K%32==0.
// flags: 1 add addend(fp32 out), 2 causal tile skip, 4 causal K-limit, 8 fp16 out
#define LDPH 20                      // uint32 per SMEM row (16 data + 4 pad)
#define AROWB (LDPH*4)               // 80 bytes
#define TNW 128
#define NTT 4
#define ABY (128*AROWB)
#define STG (2*ABY)
#define HG_SMEM (4*STG)              // 81920 B

__global__ __launch_bounds__(256, 2) void hgemm_k(
    const __half* __restrict__ A, const __half* __restrict__ B, void* __restrict__ Cv,
    const float* __restrict__ addend,
    int M, int N, int K, int lda, int ldb, int ldc,
    long sA0, long sA1, long sB0, long sB1, long sC0, long sC1, int ZH,
    const int* __restrict__ tileExpert, long wStride,
    const float* __restrict__ rowscale, long rsStride, int flags)
{
    int bx = blockIdx.x, by = blockIdx.y, z = blockIdx.z;
    if ((flags & 2) && bx > by) return;
    if (tileExpert) { int te = tileExpert[by]; if (te < 0) return; B += (long)te * wStride; }
    int zb = z / ZH, zh = z - zb * ZH;
    A += zb * sA0 + (long)zh * sA1;
    B += zb * sB0 + (long)zh * sB1;
    int Keff = K;
    if (flags & 4) { int kl = (by + 1) * 128; if (kl < Keff) Keff = kl; }
    int NT = Keff >> 5;

    extern __shared__ char smraw[];
    uint32_t sb = (uint32_t)__cvta_generic_to_shared(smraw);

    int tid = threadIdx.x;
    int wid = tid >> 5, lane = tid & 31;
    int wy = wid & 1, wx = wid >> 1;

    // ldmatrix per-lane offsets
    int grp = lane >> 3, lrow = lane & 7;
    uint32_t aoff = (uint32_t)((wy * 64 + (grp & 1) * 8 + lrow) * AROWB + (grp >> 1) * 16);
    uint32_t boff = (uint32_t)((wx * 32 + (grp >> 1) * 8 + lrow) * AROWB + (grp & 1) * 16);

    // cp.async mapping: 2 chunks each of A,B
    int ar0 = tid >> 2, ac0 = tid & 3;
    int bsz[2];
#pragma unroll
    for (int ch = 0; ch < 2; ch++) {
        int row = ar0 + ch * 64;
        bsz[ch] = ((bx * TNW + row) < N) ? 16 : 0;
    }
    const __half* bsrc0 = B;

    auto issue = [&](int s, int k0) {
        uint32_t Ab = sb + s * STG;
        uint32_t Bb = Ab + ABY;
#pragma unroll
        for (int ch = 0; ch < 2; ch++) {
            int row = ar0 + ch * 64;
            const __half* src = A + (long)(by * 128 + row) * lda + k0 + ac0 * 8;
            cpasync16(Ab + row * AROWB + ac0 * 16, src, 16);
        }
#pragma unroll
        for (int ch = 0; ch < 2; ch++) {
            int row = ar0 + ch * 64;
            const __half* src = bsz[ch] ? (B + (long)(bx * TNW + row) * ldb + k0 + ac0 * 8) : bsrc0;
            cpasync16(Bb + row * AROWB + ac0 * 16, src, bsz[ch]);
        }
    };

#pragma unroll
    for (int s = 0; s < 3; s++) {
        if (s < NT) issue(s, s * 32);
        cpcommit();
    }

    float acc[4][NTT][4];
#pragma unroll
    for (int mt = 0; mt < 4; mt++)
#pragma unroll
        for (int nt = 0; nt < NTT; nt++)
#pragma unroll
            for (int i = 0; i < 4; i++) acc[mt][nt][i] = 0.f;

    for (int it = 0; it < NT; ++it) {
        cpwait2();
        __syncthreads();
        if (it + 3 < NT) issue((it + 3) & 3, (it + 3) * 32);
        cpcommit();

        int st = it & 3;
        uint32_t Abase = sb + st * STG + aoff;
        uint32_t Bbase = sb + st * STG + ABY + boff;
#pragma unroll
        for (int ks = 0; ks < 2; ks++) {
            uint32_t af[4][4], bf[NTT][2];
#pragma unroll
            for (int mt = 0; mt < 4; mt++)
                ldsm4(af[mt], Abase + mt * (16 * AROWB) + ks * 32);
#pragma unroll
            for (int p = 0; p < NTT / 2; p++) {
                uint32_t r[4];
                ldsm4(r, Bbase + p * (16 * AROWB) + ks * 32);
                bf[2 * p][0] = r[0]; bf[2 * p][1] = r[1];
                bf[2 * p + 1][0] = r[2]; bf[2 * p + 1][1] = r[3];
            }
#pragma unroll
            for (int mt = 0; mt < 4; mt++)
#pragma unroll
                for (int nt = 0; nt < NTT; nt++)
                    mma16(acc[mt][nt], af[mt], bf[nt]);
        }
        __syncthreads();
    }

    // epilogue
    bool doadd = (flags & 1) != 0;
    bool outh = (flags & 8) != 0;
    long zr = (long)z * rsStride;
    float* Cf = (float*)Cv + zb * sC0 + (long)zh * sC1;
    __half* Ch = (__half*)Cv + zb * sC0 + (long)zh * sC1;
    const float* Af = addend ? (addend + zb * sC0 + (long)zh * sC1) : nullptr;
    int elr = lane >> 2, elk = lane & 3;
#pragma unroll
    for (int mt = 0; mt < 4; mt++) {
        int m0 = by * 128 + wy * 64 + mt * 16 + elr;
        float rs0 = 1.f, rs1 = 1.f;
        if (rowscale) { rs0 = rowscale[zr + m0]; rs1 = rowscale[zr + m0 + 8]; }
#pragma unroll
        for (int nt = 0; nt < NTT; nt++) {
            int c0 = bx * TNW + wx * 32 + nt * 8 + 2 * elk;
            if (c0 < N) {
                float2 v0 = make_float2(acc[mt][nt][0] * rs0, acc[mt][nt][1] * rs0);
                float2 v1 = make_float2(acc[mt][nt][2] * rs1, acc[mt][nt][3] * rs1);
                if (outh) {
                    *(__half2*)(Ch + (long)m0 * ldc + c0) = __float22half2_rn(v0);
                    *(__half2*)(Ch + (long)(m0 + 8) * ldc + c0) = __float22half2_rn(v1);
                } else {
                    if (doadd) {
                        float2 o0 = *(const float2*)(Af + (long)m0 * ldc + c0);
                        float2 o1 = *(const float2*)(Af + (long)(m0 + 8) * ldc + c0);
                        v0.x += o0.x; v0.y += o0.y; v1.x += o1.x; v1.y += o1.y;
                    }
                    *(float2*)(Cf + (long)m0 * ldc + c0) = v0;
                    *(float2*)(Cf + (long)(m0 + 8) * ldc + c0) = v1;
                }
            }
        }
    }
}

// ---------------- weight fp32 -> fp16 ----------------
__global__ void cvth_k(const float2* __restrict__ src, __half2* __restrict__ dst, long n2)
{
    long i = (long)blockIdx.x * blockDim.x + threadIdx.x;
    if (i < n2) dst[i] = __float22half2_rn(src[i]);
}

// expert-aware convert: dst[e*dstStride2 + dstOff2 + r] = src[e*perExp2 + r]
__global__ void cvtmoe_k(const float2* __restrict__ src, __half2* __restrict__ dst,
                         long perExp2, long dstStride2, long dstOff2, long total2)
{
    long i = (long)blockIdx.x * blockDim.x + threadIdx.x;
    if (i < total2) {
        long e = i / perExp2, r = i - e * perExp2;
        dst[e * dstStride2 + dstOff2 + r] = __float22half2_rn(src[i]);
    }
}

// ---------------- reductions ----------------
__device__ __forceinline__ float warpSum(float v) {
#pragma unroll
    for (int o = 16; o; o >>= 1) v += __shfl_xor_sync(0xffffffffu, v, o);
    return v;
}
__device__ __forceinline__ float warpMax(float v) {
#pragma unroll
    for (int o = 16; o; o >>= 1) v = fmaxf(v, __shfl_xor_sync(0xffffffffu, v, o));
    return v;
}

// ---------------- rmsnorm: fp32 in -> fp16 out ----------------
__global__ void rmsnorm_h(const float* __restrict__ x, const float* __restrict__ w,
                          __half* __restrict__ y, int D, int ldx, int ldy)
{
    long t = blockIdx.x;
    const float* xr = x + t * ldx;
    __half* yr = y + t * ldy;
    float s = 0.f;
    for (int d = threadIdx.x; d < D; d += blockDim.x) { float v = xr[d]; s += v * v; }
    __shared__ float sh[32];
    __shared__ float bc;
    s = warpSum(s);
    int lane = threadIdx.x & 31, wp = threadIdx.x >> 5;
    if (!lane) sh[wp] = s;
    __syncthreads();
    if (threadIdx.x < 32) {
        float r = (threadIdx.x < (blockDim.x >> 5)) ? sh[threadIdx.x] : 0.f;
        r = warpSum(r);
        if (!threadIdx.x) bc = rsqrtf(r / D + 1e-6f);
    }
    __syncthreads();
    float sc = bc;
    for (int d = threadIdx.x; d < D; d += blockDim.x)
        yr[d] = __float2half_rn(xr[d] * sc * w[d]);
}

// ---------------- rope on k_pe (fp32) ----------------
__global__ void rope_kpe_k(const float* __restrict__ kv, const float* __restrict__ fc,
                           const float* __restrict__ fs, float* __restrict__ kpe)
{
    long t = blockIdx.x;
    int j = threadIdx.x;
    int pos = (int)(t % Sn);
    float x1 = kv[t * KVAP + KVRn + 2 * j];
    float x2 = kv[t * KVAP + KVRn + 2 * j + 1];
    float c = fc[pos * 32 + j], s = fs[pos * 32 + j];
    kpe[t * ROPEn + 2 * j]     = x1 * c - x2 * s;
    kpe[t * ROPEn + 2 * j + 1] = x1 * s + x2 * c;
}

// ---------------- rope + scale on q: fp32 in -> fp16 out ----------------
__global__ void ropescale_qh(const float* __restrict__ q, const float* __restrict__ fc,
                             const float* __restrict__ fs, __half* __restrict__ qh)
{
    long th = blockIdx.x;
    int pos = (int)((th >> 4) % Sn);
    const float* r = q + th * QDn;
    __half* o = qh + th * QDn;
    int i = threadIdx.x;
    const float sc = 0.07216878364870322f;   // 1/sqrt(192)
    if (i < 64) {
        o[2 * i]     = __float2half_rn(r[2 * i] * sc);
        o[2 * i + 1] = __float2half_rn(r[2 * i + 1] * sc);
    } else {
        int j = i - 64;
        float x1 = r[128 + 2 * j], x2 = r[128 + 2 * j + 1];
        float c = fc[pos * 32 + j], s = fs[pos * 32 + j];
        o[128 + 2 * j]     = __float2half_rn((x1 * c - x2 * s) * sc);
        o[128 + 2 * j + 1] = __float2half_rn((x1 * s + x2 * c) * sc);
    }
}

// ---------------- [k_nope | k_pe] concat -> fp16 ----------------
__global__ void kcat_h(const float* __restrict__ kvb, const float* __restrict__ kpe,
                       __half* __restrict__ kcat)
{
    int s = blockIdx.x, z = blockIdx.y, j = threadIdx.x;
    long t = (long)(z >> 4) * Sn + s;
    float v = (j < NOPEn) ? kvb[t * KVBP + (z & 15) * 256 + j]
                          : kpe[t * ROPEn + (j - NOPEn)];
    kcat[((long)z * Sn + s) * QDn + j] = __float2half_rn(v);
}

// ---------------- transpose V -> vT fp16 ----------------
__global__ void vtrans_h(const float* __restrict__ kvb, __half* __restrict__ vT)
{
    __shared__ float tsm[32][33];
    int z = blockIdx.z, zb = z >> 4, zh = z & 15;
    int kt = blockIdx.x * 32, dt = blockIdx.y * 32;
    int tx = threadIdx.x, ty = threadIdx.y;
#pragma unroll
    for (int i = 0; i < 4; i++) {
        int k = kt + ty + i * 8;
        tsm[ty + i * 8][tx] = kvb[((long)zb * Sn + k) * KVBP + zh * 256 + NOPEn + dt + tx];
    }
    __syncthreads();
#pragma unroll
    for (int i = 0; i < 4; i++) {
        int d = dt + ty + i * 8;
        vT[((long)z * VHn + d) * Sn + kt + tx] = __float2half_rn(tsm[tx][ty + i * 8]);
    }
}

// ---------------- softmax: row cached in SMEM; fp16 P (unnormalized) + invsum ----------------
__global__ void softmax3_h(const float* __restrict__ scores, __half* __restrict__ ph,
                           float* __restrict__ inv)
{
    __shared__ float row[Sn];
    long rowi = blockIdx.x;
    int q = (int)(rowi % Sn);
    const float* p = scores + rowi * Sn;
    __half* po = ph + rowi * Sn;
    int n = q + 1;
    float m = -3.4e38f;
    for (int k = threadIdx.x; k < n; k += blockDim.x) {
        float v = p[k];
        row[k] = v;
        m = fmaxf(m, v);
    }
    __shared__ float shm[32];
    __shared__ float bc0;
    m = warpMax(m);
    int lane = threadIdx.x & 31, wp = threadIdx.x >> 5;
    if (!lane) shm[wp] = m;
    __syncthreads();
    if (threadIdx.x < 32) {
        float r = (threadIdx.x < (blockDim.x >> 5)) ? shm[threadIdx.x] : -3.4e38f;
        r = warpMax(r);
        if (!threadIdx.x) bc0 = r;
    }
    __syncthreads();
    m = bc0;
    float sum = 0.f;
    for (int k = threadIdx.x; k < n; k += blockDim.x) {
        float e = expf(row[k] - m);
        po[k] = __float2half_rn(e);
        sum += e;
    }
    sum = warpSum(sum);
    if (!lane) shm[wp] = sum;
    __syncthreads();
    if (threadIdx.x < 32) {
        float r = (threadIdx.x < (blockDim.x >> 5)) ? shm[threadIdx.x] : 0.f;
        r = warpSum(r);
        if (!threadIdx.x) inv[rowi] = 1.f / r;
    }
    int kend = ((q >> 7) + 1) << 7;
    for (int k = n + threadIdx.x; k < kend; k += blockDim.x) po[k] = __half(0.f);
}

// ---------------- router (reads fp16 nh) ----------------
__global__ void router_h(const __half* __restrict__ nh, const float* __restrict__ rw,
                         int* __restrict__ counts, int* __restrict__ bucket_ts,
                         float* __restrict__ bucket_gate)
{
    long t = blockIdx.x;
    int wp = threadIdx.x >> 5, lane = threadIdx.x & 31;
    const __half* xr = nh + t * DIMn;
    float s = 0.f;
    for (int d = lane; d < DIMn; d += 32) s += __half2float(xr[d]) * rw[(long)wp * DIMn + d];
    s = warpSum(s);
    __shared__ float logit[NEn];
    if (!lane) logit[wp] = s;
    __syncthreads();
    if (threadIdx.x == 0) {
        float mx = logit[0];
#pragma unroll
        for (int e = 1; e < NEn; e++) mx = fmaxf(mx, logit[e]);
        float p[NEn];
#pragma unroll
        for (int e = 0; e < NEn; e++) p[e] = expf(logit[e] - mx);
        int i0 = 0;
#pragma unroll
        for (int e = 1; e < NEn; e++) if (p[e] > p[i0]) i0 = e;
        int i1 = (i0 == 0) ? 1 : 0;
#pragma unroll
        for (int e = 0; e < NEn; e++) if (e != i0 && p[e] > p[i1]) i1 = e;
        float denom = p[i0] + p[i1];
        float g0 = p[i0] / denom, g1 = p[i1] / denom;
        int pos0 = atomicAdd(&counts[i0], 1);
        bucket_ts[i0 * Tn + pos0] = (int)(t * 2);
        bucket_gate[i0 * Tn + pos0] = g0;
        int pos1 = atomicAdd(&counts[i1], 1);
        bucket_ts[i1 * Tn + pos1] = (int)(t * 2 + 1);
        bucket_gate[i1 * Tn + pos1] = g1;
    }
}

__global__ void offsets_k(const int* __restrict__ counts, int* __restrict__ off,
                          int* __restrict__ tile_expert)
{
    for (int tl = 0; tl < MOE_TILES; tl++) tile_expert[tl] = -1;
    int o = 0;
    for (int e = 0; e < NEn; e++) {
        off[e] = o;
        int nt = (counts[e] + 127) >> 7;
        for (int i = 0; i < nt; i++) tile_expert[(o >> 7) + i] = e;
        o += nt * 128;
    }
    off[NEn] = o;
}

__global__ void compact_k(const int* __restrict__ counts, const int* __restrict__ off,
                          const int* __restrict__ bucket_ts, const float* __restrict__ bucket_gate,
                          int* __restrict__ flat_tok, int* __restrict__ tok2row,
                          float* __restrict__ tok2gate)
{
    int e = blockIdx.x;
    int cnt = counts[e], base = off[e];
    for (int i = threadIdx.x; i < cnt; i += blockDim.x) {
        int ts = bucket_ts[e * Tn + i];
        int r = base + i;
        flat_tok[r] = ts >> 1;
        tok2row[ts] = r;
        tok2gate[ts] = bucket_gate[e * Tn + i];
    }
}

// ---------------- gather fp16 rows ----------------
__global__ void gather_h(const __half* __restrict__ nh, const int* __restrict__ flat_tok,
                         __half* __restrict__ xg)
{
    long r = blockIdx.x;
    int t = flat_tok[r];
    uint4* dst = (uint4*)(xg + r * DIMn);
    int nch = DIMn / 8;
    if (t < 0) {
        uint4 zz = make_uint4(0u, 0u, 0u, 0u);
        for (int i = threadIdx.x; i < nch; i += blockDim.x) dst[i] = zz;
    } else {
        const uint4* src = (const uint4*)(nh + (long)t * DIMn);
        for (int i = threadIdx.x; i < nch; i += blockDim.x) dst[i] = src[i];
    }
}

// ---------------- fused silu(w1)*w3 from concatenated t13 ----------------
__global__ void silumul2_h(const __half* __restrict__ t13, __half* __restrict__ outp,
                           int inter, long rows)
{
    long h2pr = inter / 2;
    long i = (long)blockIdx.x * blockDim.x + threadIdx.x;
    if (i < rows * h2pr) {
        long r = i / h2pr, j = i - r * h2pr;
        const __half2* pa = (const __half2*)(t13 + (size_t)r * 2 * inter);
        const __half2* pb = (const __half2*)(t13 + (size_t)r * 2 * inter + inter);
        float2 x = __half22float2(pa[j]);
        float2 y = __half22float2(pb[j]);
        float s0 = x.x / (1.f + expf(-x.x));
        float s1 = x.y / (1.f + expf(-x.y));
        ((__half2*)(outp + (size_t)r * inter))[j] =
            __float22half2_rn(make_float2(s0 * y.x, s1 * y.y));
    }
}

// ---------------- combine ----------------
__global__ void combine_k(const float* __restrict__ h, const float* __restrict__ sh,
                          const float* __restrict__ eo, const int* __restrict__ tok2row,
                          const float* __restrict__ tok2gate, float* __restrict__ out)
{
    long t = blockIdx.x;
    int r0 = tok2row[t * 2], r1 = tok2row[t * 2 + 1];
    float g0 = tok2gate[t * 2], g1 = tok2gate[t * 2 + 1];
    const float4* H = (const float4*)(h + t * DIMn);
    const float4* SH = (const float4*)(sh + t * DIMn);
    const float4* E0 = (const float4*)(eo + (long)r0 * DIMn);
    const float4* E1 = (const float4*)(eo + (long)r1 * DIMn);
    float4* O = (float4*)(out + t * DIMn);
    for (int i = threadIdx.x; i < DIMn / 4; i += blockDim.x) {
        float4 a = H[i], b = SH[i], c = E0[i], d = E1[i];
        float4 o;
        o.x = a.x + b.x + g0 * c.x + g1 * d.x;
        o.y = a.y + b.y + g0 * c.y + g1 * d.y;
        o.z = a.z + b.z + g0 * c.z + g1 * d.z;
        o.w = a.w + b.w + g0 * c.w + g1 * d.w;
        O[i] = o;
    }
}

// ---------------- host ----------------
#define SYM(p, s) do { void* _q = nullptr; cudaGetSymbolAddress(&_q, s); p = (decltype(p))_q; } while (0)

static void launch_hgemm(const __half* A, const __half* B, void* C, const float* addend,
                         int M, int N, int K, int lda, int ldb, int ldc,
                         long sA0, long sA1, long sB0, long sB1, long sC0, long sC1,
                         int ZH, int Z, const int* tileExpert, long wStride,
                         const float* rowscale, long rsStride, int flags)
{
    dim3 grid((N + TNW - 1) / TNW, M / 128, Z);
    hgemm_k<<<grid, 256, HG_SMEM>>>(A, B, C, addend, M, N, K, lda, ldb, ldc,
        sA0, sA1, sB0, sB1, sC0, sC1, ZH, tileExpert, wStride, rowscale, rsStride, flags);
}

static void launch_cvt(const float* src, __half* dst, long n)
{
    long n2 = n / 2;
    cvth_k<<<(int)((n2 + 255) / 256), 256>>>((const float2*)src, (__half2*)dst, n2);
}

extern "C" void kernel_launch(void* const* d_in, const int* in_sizes, int n_in,
                              void* d_out, int out_size)
{
    cudaFuncSetAttribute(hgemm_k, cudaFuncAttributeMaxDynamicSharedMemorySize, HG_SMEM);

    const float* x       = (const float*)d_in[0];
    const float* fcos    = (const float*)d_in[1];
    const float* fsin    = (const float*)d_in[2];
    const float* attn_w  = (const float*)d_in[3];
    const float* wq      = (const float*)d_in[4];
    const float* wkv_a   = (const float*)d_in[5];
    const float* kv_w    = (const float*)d_in[6];
    const float* wkv_b   = (const float*)d_in[7];
    const float* wo      = (const float*)d_in[8];
    const float* ffn_w   = (const float*)d_in[9];
    const float* rw      = (const float*)d_in[10];
    const float* e_w1    = (const float*)d_in[11];
    const float* e_w3    = (const float*)d_in[12];
    const float* e_w2    = (const float*)d_in[13];
    const float* s_w1    = (const float*)d_in[14];
    const float* s_w3    = (const float*)d_in[15];
    const float* s_w2    = (const float*)d_in[16];
    float* out = (float*)d_out;

    float *q, *kv, *kpe, *kvb, *scores, *inv, *h, *eo, *sh;
    __half *nx_h, *ckv_h, *qh, *kcat, *vT, *ph, *attn_h, *nh_h, *xg, *t13h, *t1h, *s13h, *s1h;
    __half *wq_h, *wkva_h, *wkvb_h, *wo_h, *ew13_h, *ew2_h, *sw13_h, *sw2_h;
    int *counts, *off, *tile_expert, *bucket_ts, *flat_tok, *tok2row;
    float *bucket_gate, *tok2gate;
    SYM(q, g_q); SYM(kv, g_kv); SYM(kpe, g_kpe); SYM(kvb, g_kvb);
    SYM(scores, g_scores); SYM(inv, g_inv); SYM(h, g_h); SYM(eo, g_eo); SYM(sh, g_sh);
    SYM(nx_h, g_nx_h); SYM(ckv_h, g_ckv_h); SYM(qh, g_qh); SYM(kcat, g_kcat_h);
    SYM(vT, g_vT_h); SYM(ph, g_ph); SYM(attn_h, g_attn_h); SYM(nh_h, g_nh_h);
    SYM(xg, g_xg_h); SYM(t13h, g_t13h); SYM(t1h, g_t1h); SYM(s13h, g_s13h); SYM(s1h, g_s1h);
    SYM(wq_h, g_wq_h); SYM(wkva_h, g_wkva_h); SYM(wkvb_h, g_wkvb_h); SYM(wo_h, g_wo_h);
    SYM(ew13_h, g_ew13_h); SYM(ew2_h, g_ew2_h); SYM(sw13_h, g_sw13_h); SYM(sw2_h, g_sw2_h);
    SYM(counts, g_counts); SYM(off, g_off); SYM(tile_expert, g_tile_expert);
    SYM(bucket_ts, g_bucket_ts); SYM(bucket_gate, g_bucket_gate);
    SYM(flat_tok, g_flat_tok); SYM(tok2row, g_tok2row); SYM(tok2gate, g_tok2gate);

    const long SS = (long)Sn * Sn;
    const long PE2 = (long)MINTERn * DIMn / 2;       // half2 per expert for w1/w3

    // 0. weight conversion
    launch_cvt(wq, wq_h, (long)QPROJ * DIMn);
    launch_cvt(wkv_a, wkva_h, (long)KVAP * DIMn);
    launch_cvt(wkv_b, wkvb_h, (long)KVBP * KVRn);
    launch_cvt(wo, wo_h, (long)DIMn * DIMn);
    {
        long tot2 = (long)NEn * PE2;
        int blocks = (int)((tot2 + 255) / 256);
        cvtmoe_k<<<blocks, 256>>>((const float2*)e_w1, (__half2*)ew13_h, PE2, 2 * PE2, 0, tot2);
        cvtmoe_k<<<blocks, 256>>>((const float2*)e_w3, (__half2*)ew13_h, PE2, 2 * PE2, PE2, tot2);
    }
    launch_cvt(e_w2, ew2_h, (long)NEn * DIMn * MINTERn);
    launch_cvt(s_w1, sw13_h, (long)SHIn * DIMn);
    launch_cvt(s_w3, sw13_h + (size_t)SHIn * DIMn, (long)SHIn * DIMn);
    launch_cvt(s_w2, sw2_h, (long)DIMn * SHIn);

    // 1. attention-input rmsnorm -> fp16
    rmsnorm_h<<<Tn, 256>>>(x, attn_w, nx_h, DIMn, DIMn, DIMn);
    // 2. q projection (fp32 out)
    launch_hgemm(nx_h, wq_h, q, nullptr, Tn, QPROJ, DIMn, DIMn, DIMn, QPROJ,
                 0, 0, 0, 0, 0, 0, 1, 1, nullptr, 0, nullptr, 0, 0);
    // 3. kv_a projection (fp32 out)
    launch_hgemm(nx_h, wkva_h, kv, nullptr, Tn, KVAP, DIMn, DIMn, DIMn, KVAP,
                 0, 0, 0, 0, 0, 0, 1, 1, nullptr, 0, nullptr, 0, 0);
    // 4. c_kv rmsnorm -> fp16
    rmsnorm_h<<<Tn, 256>>>(kv, kv_w, ckv_h, KVRn, KVAP, KVRn);
    // 5. rope k_pe (fp32)
    rope_kpe_k<<<Tn, 32>>>(kv, fcos, fsin, kpe);
    // 6. kv_b projection (fp32 out)
    launch_hgemm(ckv_h, wkvb_h, kvb, nullptr, Tn, KVBP, KVRn, KVRn, KVRn, KVBP,
                 0, 0, 0, 0, 0, 0, 1, 1, nullptr, 0, nullptr, 0, 0);
    // 7. rope + scale q -> fp16
    ropescale_qh<<<Tn * NHn, 96>>>(q, fcos, fsin, qh);
    // 8. kcat + vT -> fp16
    { dim3 g(Sn, ZSn); kcat_h<<<g, QDn>>>(kvb, kpe, kcat); }
    { dim3 g(Sn / 32, VHn / 32, ZSn); dim3 b(32, 8); vtrans_h<<<g, b>>>(kvb, vT); }
    // 9. scores = q @ kcat^T (K=192, causal skip, fp32 out)
    launch_hgemm(qh, kcat, scores, nullptr, Sn, Sn, QDn, QPROJ, QDn, Sn,
                 (long)Sn * QPROJ, QDn, 16L * Sn * QDn, (long)Sn * QDn, 16 * SS, SS,
                 16, 32, nullptr, 0, nullptr, 0, 2);
    // 10. softmax (row in SMEM) -> fp16 P + invsum
    softmax3_h<<<32 * Sn, 256>>>(scores, ph, inv);
    // 11. attn = (P @ V) * invsum -> fp16 (K-limit)
    launch_hgemm(ph, vT, attn_h, nullptr, Sn, VHn, Sn, Sn, Sn, DIMn,
                 16 * SS, SS, 16L * VHn * Sn, (long)VHn * Sn, (long)Sn * DIMn, VHn,
                 16, 32, nullptr, 0, inv, Sn, 4 | 8);
    // 12. h = x + attn @ wo^T (addend = x, no memcpy)
    launch_hgemm(attn_h, wo_h, h, x, Tn, DIMn, DIMn, DIMn, DIMn, DIMn,
                 0, 0, 0, 0, 0, 0, 1, 1, nullptr, 0, nullptr, 0, 1);
    // 13. ffn rmsnorm -> fp16
    rmsnorm_h<<<Tn, 256>>>(h, ffn_w, nh_h, DIMn, DIMn, DIMn);
    // 14. routing
    cudaMemsetAsync(counts, 0, NEn * sizeof(int), 0);
    cudaMemsetAsync(flat_tok, 0xFF, MOE_ROWS * sizeof(int), 0);
    router_h<<<Tn, 256>>>(nh_h, rw, counts, bucket_ts, bucket_gate);
    offsets_k<<<1, 1>>>(counts, off, tile_expert);
    compact_k<<<NEn, 256>>>(counts, off, bucket_ts, bucket_gate, flat_tok, tok2row, tok2gate);
    gather_h<<<MOE_ROWS, 256>>>(nh_h, flat_tok, xg);
    // 15. expert FFN (grouped, fused w1||w3)
    launch_hgemm(xg, ew13_h, t13h, nullptr, MOE_ROWS, 2 * MINTERn, DIMn,
                 DIMn, DIMn, 2 * MINTERn,
                 0, 0, 0, 0, 0, 0, 1, 1, tile_expert, 2L * MINTERn * DIMn, nullptr, 0, 8);
    {
        long n2 = (long)MOE_ROWS * MINTERn / 2;
        silumul2_h<<<(int)((n2 + 255) / 256), 256>>>(t13h, t1h, MINTERn, MOE_ROWS);
    }
    launch_hgemm(t1h, ew2_h, eo, nullptr, MOE_ROWS, DIMn, MINTERn, MINTERn, MINTERn, DIMn,
                 0, 0, 0, 0, 0, 0, 1, 1, tile_expert, (long)DIMn * MINTERn, nullptr, 0, 0);
    // 16. shared FFN (fused w1||w3)
    launch_hgemm(nh_h, sw13_h, s13h, nullptr, Tn, 2 * SHIn, DIMn, DIMn, DIMn, 2 * SHIn,
                 0, 0, 0, 0, 0, 0, 1, 1, nullptr, 0, nullptr, 0, 8);
    {
        long n2 = (long)Tn * SHIn / 2;
        silumul2_h<<<(int)((n2 + 255) / 256), 256>>>(s13h, s1h, SHIn, Tn);
    }
    launch_hgemm(s1h, sw2_h, sh, nullptr, Tn, DIMn, SHIn, SHIn, SHIn, DIMn,
                 0, 0, 0, 0, 0, 0, 1, 1, nullptr, 0, nullptr, 0, 0);
    // 17. combine
    combine_k<<<Tn, 256>>>(h, sh, eo, tok2row, tok2gate, out);
}

// round 11
// speedup vs baseline: 7.3908x; 1.0451x over previous
#include <cuda_runtime.h>
#include <cuda_fp16.h>
#include <math.h>
#include <stdint.h>

// ---------------- problem constants ----------------
#define Tn     4096
#define Sn     2048
#define DIMn   2048
#define NHn    16
#define NOPEn  128
#define ROPEn  64
#define QDn    192
#define VHn    128
#define KVRn   512
#define NEn    8
#define MINTERn 1408
#define SHIn   2816
#define QPROJ  3072
#define KVAP   576
#define KVBP   4096
#define MOE_ROWS 9216
#define MOE_TILES 72
#define ZSn    32

// ---------------- fp32 scratch ----------------
__device__ float g_q[(size_t)Tn*QPROJ];
__device__ float g_kv[(size_t)Tn*KVAP];
__device__ float g_kpe[(size_t)Tn*ROPEn];
__device__ float g_kvb[(size_t)Tn*KVBP];
__device__ float g_h[(size_t)Tn*DIMn];
__device__ float g_eo[(size_t)MOE_ROWS*DIMn];
__device__ float g_sh[(size_t)Tn*DIMn];
__device__ int   g_counts[NEn];
__device__ int   g_off[NEn+1];
__device__ int   g_tile_expert[MOE_TILES];
__device__ int   g_bucket_ts[NEn*Tn];
__device__ float g_bucket_gate[NEn*Tn];
__device__ int   g_flat_tok[MOE_ROWS];
__device__ int   g_tok2row[Tn*2];
__device__ float g_tok2gate[Tn*2];
// ---------------- fp16 scratch ----------------
__device__ __half g_nx_h[(size_t)Tn*DIMn];
__device__ __half g_ckv_h[(size_t)Tn*KVRn];
__device__ __half g_qh[(size_t)Tn*QPROJ];
__device__ __half g_kcat_h[(size_t)ZSn*Sn*QDn];
__device__ __half g_vT_h[(size_t)ZSn*VHn*Sn];
__device__ __half g_attn_h[(size_t)Tn*DIMn];
__device__ __half g_nh_h[(size_t)Tn*DIMn];
__device__ __half g_xg_h[(size_t)MOE_ROWS*DIMn];
__device__ __half g_t13h[(size_t)MOE_ROWS*2*MINTERn];
__device__ __half g_t1h[(size_t)MOE_ROWS*MINTERn];
__device__ __half g_s13h[(size_t)Tn*2*SHIn];
__device__ __half g_s1h[(size_t)Tn*SHIn];
// fp16 weight copies
__device__ __half g_wq_h[(size_t)QPROJ*DIMn];
__device__ __half g_wkva_h[(size_t)KVAP*DIMn];
__device__ __half g_wkvb_h[(size_t)KVBP*KVRn];
__device__ __half g_wo_h[(size_t)DIMn*DIMn];
__device__ __half g_ew13_h[(size_t)NEn*2*MINTERn*DIMn];
__device__ __half g_ew2_h[(size_t)NEn*DIMn*MINTERn];
__device__ __half g_sw13_h[(size_t)2*SHIn*DIMn];
__device__ __half g_sw2_h[(size_t)DIMn*SHIn];

// ---------------- helpers ----------------
__device__ __forceinline__ void mma16(float* c, const uint32_t* a, const uint32_t* b) {
    asm volatile("mma.sync.aligned.m16n8k16.row.col.f32.f16.f16.f32 "
        "{%0,%1,%2,%3}, {%4,%5,%6,%7}, {%8,%9}, {%0,%1,%2,%3};"
        : "+f"(c[0]), "+f"(c[1]), "+f"(c[2]), "+f"(c[3])
        : "r"(a[0]), "r"(a[1]), "r"(a[2]), "r"(a[3]), "r"(b[0]), "r"(b[1]));
}
__device__ __forceinline__ void ldsm4(uint32_t* r, uint32_t addr) {
    asm volatile("ldmatrix.sync.aligned.m8n8.x4.shared.b16 {%0,%1,%2,%3}, [%4];"
        : "=r"(r[0]), "=r"(r[1]), "=r"(r[2]), "=r"(r[3]) : "r"(addr));
}
__device__ __forceinline__ void cpasync16(uint32_t dst, const void* src, int sz) {
    asm volatile("cp.async.cg.shared.global [%0], [%1], 16, %2;"
                 :: "r"(dst), "l"(src), "r"(sz));
}
__device__ __forceinline__ void cpcommit() { asm volatile("cp.async.commit_group;"); }
__device__ __forceinline__ void cpwait1() { asm volatile("cp.async.wait_group 1;"); }
__device__ __forceinline__ void cpwait2() { asm volatile("cp.async.wait_group 2;"); }

// ---------------- fp16 tensor GEMM, 128x128 CTA, 4-stage, 2 CTAs/SM ----------------
// flags: 1 add addend(fp32 out), 8 fp16 out
#define LDPH 20
#define AROWB (LDPH*4)               // 80 bytes
#define TNW 128
#define NTT 4
#define ABY (128*AROWB)
#define STG (2*ABY)
#define HG_SMEM (4*STG)              // 81920 B

__global__ __launch_bounds__(256, 2) void hgemm_k(
    const __half* __restrict__ A, const __half* __restrict__ B, void* __restrict__ Cv,
    const float* __restrict__ addend,
    int M, int N, int K, int lda, int ldb, int ldc,
    long sA0, long sA1, long sB0, long sB1, long sC0, long sC1, int ZH,
    const int* __restrict__ tileExpert, long wStride, int flags)
{
    int bx = blockIdx.x, by = blockIdx.y, z = blockIdx.z;
    if (tileExpert) { int te = tileExpert[by]; if (te < 0) return; B += (long)te * wStride; }
    int zb = z / ZH, zh = z - zb * ZH;
    A += zb * sA0 + (long)zh * sA1;
    B += zb * sB0 + (long)zh * sB1;
    int NT = K >> 5;

    extern __shared__ char smraw[];
    uint32_t sb = (uint32_t)__cvta_generic_to_shared(smraw);

    int tid = threadIdx.x;
    int wid = tid >> 5, lane = tid & 31;
    int wy = wid & 1, wx = wid >> 1;

    int grp = lane >> 3, lrow = lane & 7;
    uint32_t aoff = (uint32_t)((wy * 64 + (grp & 1) * 8 + lrow) * AROWB + (grp >> 1) * 16);
    uint32_t boff = (uint32_t)((wx * 32 + (grp >> 1) * 8 + lrow) * AROWB + (grp & 1) * 16);

    int ar0 = tid >> 2, ac0 = tid & 3;
    int bsz[2];
#pragma unroll
    for (int ch = 0; ch < 2; ch++) {
        int row = ar0 + ch * 64;
        bsz[ch] = ((bx * TNW + row) < N) ? 16 : 0;
    }
    const __half* bsrc0 = B;

    auto issue = [&](int s, int k0) {
        uint32_t Ab = sb + s * STG;
        uint32_t Bb = Ab + ABY;
#pragma unroll
        for (int ch = 0; ch < 2; ch++) {
            int row = ar0 + ch * 64;
            const __half* src = A + (long)(by * 128 + row) * lda + k0 + ac0 * 8;
            cpasync16(Ab + row * AROWB + ac0 * 16, src, 16);
        }
#pragma unroll
        for (int ch = 0; ch < 2; ch++) {
            int row = ar0 + ch * 64;
            const __half* src = bsz[ch] ? (B + (long)(bx * TNW + row) * ldb + k0 + ac0 * 8) : bsrc0;
            cpasync16(Bb + row * AROWB + ac0 * 16, src, bsz[ch]);
        }
    };

#pragma unroll
    for (int s = 0; s < 3; s++) {
        if (s < NT) issue(s, s * 32);
        cpcommit();
    }

    float acc[4][NTT][4];
#pragma unroll
    for (int mt = 0; mt < 4; mt++)
#pragma unroll
        for (int nt = 0; nt < NTT; nt++)
#pragma unroll
            for (int i = 0; i < 4; i++) acc[mt][nt][i] = 0.f;

    for (int it = 0; it < NT; ++it) {
        cpwait2();
        __syncthreads();
        if (it + 3 < NT) issue((it + 3) & 3, (it + 3) * 32);
        cpcommit();

        int st = it & 3;
        uint32_t Abase = sb + st * STG + aoff;
        uint32_t Bbase = sb + st * STG + ABY + boff;
#pragma unroll
        for (int ks = 0; ks < 2; ks++) {
            uint32_t af[4][4], bf[NTT][2];
#pragma unroll
            for (int mt = 0; mt < 4; mt++)
                ldsm4(af[mt], Abase + mt * (16 * AROWB) + ks * 32);
#pragma unroll
            for (int p = 0; p < NTT / 2; p++) {
                uint32_t r[4];
                ldsm4(r, Bbase + p * (16 * AROWB) + ks * 32);
                bf[2 * p][0] = r[0]; bf[2 * p][1] = r[1];
                bf[2 * p + 1][0] = r[2]; bf[2 * p + 1][1] = r[3];
            }
#pragma unroll
            for (int mt = 0; mt < 4; mt++)
#pragma unroll
                for (int nt = 0; nt < NTT; nt++)
                    mma16(acc[mt][nt], af[mt], bf[nt]);
        }
        __syncthreads();
    }

    bool doadd = (flags & 1) != 0;
    bool outh = (flags & 8) != 0;
    float* Cf = (float*)Cv + zb * sC0 + (long)zh * sC1;
    __half* Ch = (__half*)Cv + zb * sC0 + (long)zh * sC1;
    const float* Af = addend ? (addend + zb * sC0 + (long)zh * sC1) : nullptr;
    int elr = lane >> 2, elk = lane & 3;
#pragma unroll
    for (int mt = 0; mt < 4; mt++) {
        int m0 = by * 128 + wy * 64 + mt * 16 + elr;
#pragma unroll
        for (int nt = 0; nt < NTT; nt++) {
            int c0 = bx * TNW + wx * 32 + nt * 8 + 2 * elk;
            if (c0 < N) {
                float2 v0 = make_float2(acc[mt][nt][0], acc[mt][nt][1]);
                float2 v1 = make_float2(acc[mt][nt][2], acc[mt][nt][3]);
                if (outh) {
                    *(__half2*)(Ch + (long)m0 * ldc + c0) = __float22half2_rn(v0);
                    *(__half2*)(Ch + (long)(m0 + 8) * ldc + c0) = __float22half2_rn(v1);
                } else {
                    if (doadd) {
                        float2 o0 = *(const float2*)(Af + (long)m0 * ldc + c0);
                        float2 o1 = *(const float2*)(Af + (long)(m0 + 8) * ldc + c0);
                        v0.x += o0.x; v0.y += o0.y; v1.x += o1.x; v1.y += o1.y;
                    }
                    *(float2*)(Cf + (long)m0 * ldc + c0) = v0;
                    *(float2*)(Cf + (long)(m0 + 8) * ldc + c0) = v1;
                }
            }
        }
    }
}

// ---------------- fused flash attention ----------------
// grid (16, 32): x -> reversed Q row-block, y -> z=(batch,head). 256 thr.
#define QROWB 400                    // 192*2 + 16 pad
#define VROWB 272                    // 128*2 + 16 pad
#define FA_QS 0
#define FA_KS (128*QROWB)
#define FA_VS (2*128*QROWB)
#define FA_PS (FA_VS + 128*VROWB)
#define FA_RA (FA_PS + 128*VROWB)
#define FA_RB (FA_RA + 2048)
#define FA_SMEM (FA_RB + 2048)       // 176128 B

__global__ __launch_bounds__(256) void fattn_k(
    const __half* __restrict__ qh, const __half* __restrict__ kcat,
    const __half* __restrict__ vT, __half* __restrict__ attn)
{
    int by = (int)gridDim.x - 1 - blockIdx.x;   // heavy tiles first
    int z = blockIdx.y;
    int zb = z >> 4, zh = z & 15;

    extern __shared__ char smraw[];
    uint32_t sb = (uint32_t)__cvta_generic_to_shared(smraw);
    float* rowA = (float*)(smraw + FA_RA);      // [4 wx][128 rows]
    float* rowB = (float*)(smraw + FA_RB);

    int tid = threadIdx.x;
    int wid = tid >> 5, lane = tid & 31;
    int wy = wid & 1, wx = wid >> 1;
    int grp = lane >> 3, lrow = lane & 7;
    int elr = lane >> 2, elk = lane & 3;

    uint32_t aoffQ = (uint32_t)((wy * 64 + (grp & 1) * 8 + lrow) * QROWB + (grp >> 1) * 16);
    uint32_t boffK = (uint32_t)((wx * 32 + (grp >> 1) * 8 + lrow) * QROWB + (grp & 1) * 16);
    uint32_t aoffP = (uint32_t)((wy * 64 + (grp & 1) * 8 + lrow) * VROWB + (grp >> 1) * 16);
    uint32_t boffV = (uint32_t)((wx * 32 + (grp >> 1) * 8 + lrow) * VROWB + (grp & 1) * 16);

    const __half* Qg = qh + ((long)zb * Sn + (long)by * 128) * QPROJ + zh * QDn;
    const __half* Kg = kcat + (long)z * Sn * QDn;
    const __half* Vg = vT + (long)z * VHn * Sn;

    auto issueK = [&](int kb) {
#pragma unroll
        for (int ch = 0; ch < 12; ch++) {
            int idx = tid + ch * 256;
            int row = idx / 24, cq = idx - row * 24;
            cpasync16(sb + FA_KS + row * QROWB + cq * 16,
                      Kg + ((long)kb * 128 + row) * QDn + cq * 8, 16);
        }
    };
    auto issueV = [&](int kb) {
#pragma unroll
        for (int ch = 0; ch < 8; ch++) {
            int idx = tid + ch * 256;
            int row = idx >> 4, cq = idx & 15;
            cpasync16(sb + FA_VS + row * VROWB + cq * 16,
                      Vg + (long)row * Sn + kb * 128 + cq * 8, 16);
        }
    };

    // prologue: Q, K0, V0
#pragma unroll
    for (int ch = 0; ch < 12; ch++) {
        int idx = tid + ch * 256;
        int row = idx / 24, cq = idx - row * 24;
        cpasync16(sb + FA_QS + row * QROWB + cq * 16, Qg + (long)row * QPROJ + cq * 8, 16);
    }
    cpcommit();
    issueK(0); cpcommit();
    issueV(0); cpcommit();

    float accO[4][4][4];
    float mold[4][2], lrun[4][2];
#pragma unroll
    for (int mt = 0; mt < 4; mt++) {
#pragma unroll
        for (int nt = 0; nt < 4; nt++)
#pragma unroll
            for (int i = 0; i < 4; i++) accO[mt][nt][i] = 0.f;
        mold[mt][0] = -3.4e38f; mold[mt][1] = -3.4e38f;
        lrun[mt][0] = 0.f; lrun[mt][1] = 0.f;
    }

    for (int kb = 0; kb <= by; kb++) {
        cpwait1();            // K_kb (and Q on first iter) ready
        __syncthreads();

        // ---- S = Q @ K^T ----
        float accS[4][4][4];
#pragma unroll
        for (int mt = 0; mt < 4; mt++)
#pragma unroll
            for (int nt = 0; nt < 4; nt++)
#pragma unroll
                for (int i = 0; i < 4; i++) accS[mt][nt][i] = 0.f;
#pragma unroll
        for (int ks = 0; ks < 12; ks++) {
            uint32_t af[4][4], bf[4][2];
#pragma unroll
            for (int mt = 0; mt < 4; mt++)
                ldsm4(af[mt], sb + FA_QS + aoffQ + mt * (16 * QROWB) + ks * 32);
#pragma unroll
            for (int p = 0; p < 2; p++) {
                uint32_t r[4];
                ldsm4(r, sb + FA_KS + boffK + p * (16 * QROWB) + ks * 32);
                bf[2 * p][0] = r[0]; bf[2 * p][1] = r[1];
                bf[2 * p + 1][0] = r[2]; bf[2 * p + 1][1] = r[3];
            }
#pragma unroll
            for (int mt = 0; mt < 4; mt++)
#pragma unroll
                for (int nt = 0; nt < 4; nt++)
                    mma16(accS[mt][nt], af[mt], bf[nt]);
        }
        // ---- causal mask on diagonal tile ----
        if (kb == by) {
#pragma unroll
            for (int mt = 0; mt < 4; mt++) {
                int r0 = wy * 64 + mt * 16 + elr, r1 = r0 + 8;
#pragma unroll
                for (int nt = 0; nt < 4; nt++) {
                    int c = wx * 32 + nt * 8 + 2 * elk;
                    if (c > r0)     accS[mt][nt][0] = -3.4e38f;
                    if (c + 1 > r0) accS[mt][nt][1] = -3.4e38f;
                    if (c > r1)     accS[mt][nt][2] = -3.4e38f;
                    if (c + 1 > r1) accS[mt][nt][3] = -3.4e38f;
                }
            }
        }
        // ---- row max (local -> elk shuffle -> SMEM cross-warp) ----
        float lmax[4][2];
#pragma unroll
        for (int mt = 0; mt < 4; mt++) {
            float a = -3.4e38f, b = -3.4e38f;
#pragma unroll
            for (int nt = 0; nt < 4; nt++) {
                a = fmaxf(a, fmaxf(accS[mt][nt][0], accS[mt][nt][1]));
                b = fmaxf(b, fmaxf(accS[mt][nt][2], accS[mt][nt][3]));
            }
            lmax[mt][0] = a; lmax[mt][1] = b;
        }
#pragma unroll
        for (int off = 1; off <= 2; off <<= 1)
#pragma unroll
            for (int mt = 0; mt < 4; mt++) {
                lmax[mt][0] = fmaxf(lmax[mt][0], __shfl_xor_sync(0xffffffffu, lmax[mt][0], off));
                lmax[mt][1] = fmaxf(lmax[mt][1], __shfl_xor_sync(0xffffffffu, lmax[mt][1], off));
            }
        if (elk == 0) {
#pragma unroll
            for (int mt = 0; mt < 4; mt++) {
                int m = wy * 64 + mt * 16 + elr;
                rowA[wx * 128 + m] = lmax[mt][0];
                rowA[wx * 128 + m + 8] = lmax[mt][1];
            }
        }
        __syncthreads();
        if (kb + 1 <= by) issueK(kb + 1);
        cpcommit();

        float mnew[4][2];
#pragma unroll
        for (int mt = 0; mt < 4; mt++) {
#pragma unroll
            for (int hf = 0; hf < 2; hf++) {
                int m = wy * 64 + mt * 16 + elr + hf * 8;
                float v = fmaxf(fmaxf(rowA[m], rowA[128 + m]),
                                fmaxf(rowA[256 + m], rowA[384 + m]));
                mnew[mt][hf] = fmaxf(mold[mt][hf], v);
            }
        }
        // ---- P = exp(S - mnew), store fp16 to Ps, local sums ----
        float lsum[4][2];
#pragma unroll
        for (int mt = 0; mt < 4; mt++) { lsum[mt][0] = 0.f; lsum[mt][1] = 0.f; }
#pragma unroll
        for (int mt = 0; mt < 4; mt++) {
            int r0 = wy * 64 + mt * 16 + elr;
#pragma unroll
            for (int nt = 0; nt < 4; nt++) {
                int c = wx * 32 + nt * 8 + 2 * elk;
                float p0 = __expf(accS[mt][nt][0] - mnew[mt][0]);
                float p1 = __expf(accS[mt][nt][1] - mnew[mt][0]);
                float p2 = __expf(accS[mt][nt][2] - mnew[mt][1]);
                float p3 = __expf(accS[mt][nt][3] - mnew[mt][1]);
                lsum[mt][0] += p0 + p1;
                lsum[mt][1] += p2 + p3;
                *(__half2*)(smraw + FA_PS + r0 * VROWB + c * 2) =
                    __float22half2_rn(make_float2(p0, p1));
                *(__half2*)(smraw + FA_PS + (r0 + 8) * VROWB + c * 2) =
                    __float22half2_rn(make_float2(p2, p3));
            }
        }
#pragma unroll
        for (int off = 1; off <= 2; off <<= 1)
#pragma unroll
            for (int mt = 0; mt < 4; mt++) {
                lsum[mt][0] += __shfl_xor_sync(0xffffffffu, lsum[mt][0], off);
                lsum[mt][1] += __shfl_xor_sync(0xffffffffu, lsum[mt][1], off);
            }
        if (elk == 0) {
#pragma unroll
            for (int mt = 0; mt < 4; mt++) {
                int m = wy * 64 + mt * 16 + elr;
                rowB[wx * 128 + m] = lsum[mt][0];
                rowB[wx * 128 + m + 8] = lsum[mt][1];
            }
        }
        cpwait1();            // V_kb ready
        __syncthreads();      // rowB + Ps + Vs visible

        // ---- online update of l, rescale O ----
#pragma unroll
        for (int mt = 0; mt < 4; mt++) {
#pragma unroll
            for (int hf = 0; hf < 2; hf++) {
                int m = wy * 64 + mt * 16 + elr + hf * 8;
                float rs = rowB[m] + rowB[128 + m] + rowB[256 + m] + rowB[384 + m];
                float fsc = __expf(mold[mt][hf] - mnew[mt][hf]);
                lrun[mt][hf] = lrun[mt][hf] * fsc + rs;
                mold[mt][hf] = mnew[mt][hf];
#pragma unroll
                for (int nt = 0; nt < 4; nt++) {
                    accO[mt][nt][hf * 2 + 0] *= fsc;
                    accO[mt][nt][hf * 2 + 1] *= fsc;
                }
            }
        }
        // ---- O += P @ V ----
#pragma unroll
        for (int ks = 0; ks < 8; ks++) {
            uint32_t af[4][4], bf[4][2];
#pragma unroll
            for (int mt = 0; mt < 4; mt++)
                ldsm4(af[mt], sb + FA_PS + aoffP + mt * (16 * VROWB) + ks * 32);
#pragma unroll
            for (int p = 0; p < 2; p++) {
                uint32_t r[4];
                ldsm4(r, sb + FA_VS + boffV + p * (16 * VROWB) + ks * 32);
                bf[2 * p][0] = r[0]; bf[2 * p][1] = r[1];
                bf[2 * p + 1][0] = r[2]; bf[2 * p + 1][1] = r[3];
            }
#pragma unroll
            for (int mt = 0; mt < 4; mt++)
#pragma unroll
                for (int nt = 0; nt < 4; nt++)
                    mma16(accO[mt][nt], af[mt], bf[nt]);
        }
        __syncthreads();      // Vs/Ps consumed
        if (kb + 1 <= by) issueV(kb + 1);
        cpcommit();
    }

    // ---- write normalized O (fp16) ----
    __half* Og = attn + (long)zb * Sn * DIMn + zh * VHn;
#pragma unroll
    for (int mt = 0; mt < 4; mt++) {
        float i0 = 1.f / lrun[mt][0], i1 = 1.f / lrun[mt][1];
        int m = by * 128 + wy * 64 + mt * 16 + elr;
#pragma unroll
        for (int nt = 0; nt < 4; nt++) {
            int d = wx * 32 + nt * 8 + 2 * elk;
            *(__half2*)(Og + (long)m * DIMn + d) =
                __float22half2_rn(make_float2(accO[mt][nt][0] * i0, accO[mt][nt][1] * i0));
            *(__half2*)(Og + (long)(m + 8) * DIMn + d) =
                __float22half2_rn(make_float2(accO[mt][nt][2] * i1, accO[mt][nt][3] * i1));
        }
    }
}

// ---------------- weight fp32 -> fp16 ----------------
__global__ void cvth_k(const float2* __restrict__ src, __half2* __restrict__ dst, long n2)
{
    long i = (long)blockIdx.x * blockDim.x + threadIdx.x;
    if (i < n2) dst[i] = __float22half2_rn(src[i]);
}
__global__ void cvtmoe_k(const float2* __restrict__ src, __half2* __restrict__ dst,
                         long perExp2, long dstStride2, long dstOff2, long total2)
{
    long i = (long)blockIdx.x * blockDim.x + threadIdx.x;
    if (i < total2) {
        long e = i / perExp2, r = i - e * perExp2;
        dst[e * dstStride2 + dstOff2 + r] = __float22half2_rn(src[i]);
    }
}

// ---------------- reductions ----------------
__device__ __forceinline__ float warpSum(float v) {
#pragma unroll
    for (int o = 16; o; o >>= 1) v += __shfl_xor_sync(0xffffffffu, v, o);
    return v;
}

// ---------------- rmsnorm: fp32 in -> fp16 out ----------------
__global__ void rmsnorm_h(const float* __restrict__ x, const float* __restrict__ w,
                          __half* __restrict__ y, int D, int ldx, int ldy)
{
    long t = blockIdx.x;
    const float* xr = x + t * ldx;
    __half* yr = y + t * ldy;
    float s = 0.f;
    for (int d = threadIdx.x; d < D; d += blockDim.x) { float v = xr[d]; s += v * v; }
    __shared__ float sh[32];
    __shared__ float bc;
    s = warpSum(s);
    int lane = threadIdx.x & 31, wp = threadIdx.x >> 5;
    if (!lane) sh[wp] = s;
    __syncthreads();
    if (threadIdx.x < 32) {
        float r = (threadIdx.x < (blockDim.x >> 5)) ? sh[threadIdx.x] : 0.f;
        r = warpSum(r);
        if (!threadIdx.x) bc = rsqrtf(r / D + 1e-6f);
    }
    __syncthreads();
    float sc = bc;
    for (int d = threadIdx.x; d < D; d += blockDim.x)
        yr[d] = __float2half_rn(xr[d] * sc * w[d]);
}

// ---------------- rope on k_pe (fp32) ----------------
__global__ void rope_kpe_k(const float* __restrict__ kv, const float* __restrict__ fc,
                           const float* __restrict__ fs, float* __restrict__ kpe)
{
    long t = blockIdx.x;
    int j = threadIdx.x;
    int pos = (int)(t % Sn);
    float x1 = kv[t * KVAP + KVRn + 2 * j];
    float x2 = kv[t * KVAP + KVRn + 2 * j + 1];
    float c = fc[pos * 32 + j], s = fs[pos * 32 + j];
    kpe[t * ROPEn + 2 * j]     = x1 * c - x2 * s;
    kpe[t * ROPEn + 2 * j + 1] = x1 * s + x2 * c;
}

// ---------------- rope + scale on q: fp32 in -> fp16 out ----------------
__global__ void ropescale_qh(const float* __restrict__ q, const float* __restrict__ fc,
                             const float* __restrict__ fs, __half* __restrict__ qh)
{
    long th = blockIdx.x;
    int pos = (int)((th >> 4) % Sn);
    const float* r = q + th * QDn;
    __half* o = qh + th * QDn;
    int i = threadIdx.x;
    const float sc = 0.07216878364870322f;   // 1/sqrt(192)
    if (i < 64) {
        o[2 * i]     = __float2half_rn(r[2 * i] * sc);
        o[2 * i + 1] = __float2half_rn(r[2 * i + 1] * sc);
    } else {
        int j = i - 64;
        float x1 = r[128 + 2 * j], x2 = r[128 + 2 * j + 1];
        float c = fc[pos * 32 + j], s = fs[pos * 32 + j];
        o[128 + 2 * j]     = __float2half_rn((x1 * c - x2 * s) * sc);
        o[128 + 2 * j + 1] = __float2half_rn((x1 * s + x2 * c) * sc);
    }
}

// ---------------- [k_nope | k_pe] concat -> fp16 ----------------
__global__ void kcat_h(const float* __restrict__ kvb, const float* __restrict__ kpe,
                       __half* __restrict__ kcat)
{
    int s = blockIdx.x, z = blockIdx.y, j = threadIdx.x;
    long t = (long)(z >> 4) * Sn + s;
    float v = (j < NOPEn) ? kvb[t * KVBP + (z & 15) * 256 + j]
                          : kpe[t * ROPEn + (j - NOPEn)];
    kcat[((long)z * Sn + s) * QDn + j] = __float2half_rn(v);
}

// ---------------- transpose V -> vT fp16 ----------------
__global__ void vtrans_h(const float* __restrict__ kvb, __half* __restrict__ vT)
{
    __shared__ float tsm[32][33];
    int z = blockIdx.z, zb = z >> 4, zh = z & 15;
    int kt = blockIdx.x * 32, dt = blockIdx.y * 32;
    int tx = threadIdx.x, ty = threadIdx.y;
#pragma unroll
    for (int i = 0; i < 4; i++) {
        int k = kt + ty + i * 8;
        tsm[ty + i * 8][tx] = kvb[((long)zb * Sn + k) * KVBP + zh * 256 + NOPEn + dt + tx];
    }
    __syncthreads();
#pragma unroll
    for (int i = 0; i < 4; i++) {
        int d = dt + ty + i * 8;
        vT[((long)z * VHn + d) * Sn + kt + tx] = __float2half_rn(tsm[tx][ty + i * 8]);
    }
}

// ---------------- router (reads fp16 nh) ----------------
__global__ void router_h(const __half* __restrict__ nh, const float* __restrict__ rw,
                         int* __restrict__ counts, int* __restrict__ bucket_ts,
                         float* __restrict__ bucket_gate)
{
    long t = blockIdx.x;
    int wp = threadIdx.x >> 5, lane = threadIdx.x & 31;
    const __half* xr = nh + t * DIMn;
    float s = 0.f;
    for (int d = lane; d < DIMn; d += 32) s += __half2float(xr[d]) * rw[(long)wp * DIMn + d];
    s = warpSum(s);
    __shared__ float logit[NEn];
    if (!lane) logit[wp] = s;
    __syncthreads();
    if (threadIdx.x == 0) {
        float mx = logit[0];
#pragma unroll
        for (int e = 1; e < NEn; e++) mx = fmaxf(mx, logit[e]);
        float p[NEn];
#pragma unroll
        for (int e = 0; e < NEn; e++) p[e] = expf(logit[e] - mx);
        int i0 = 0;
#pragma unroll
        for (int e = 1; e < NEn; e++) if (p[e] > p[i0]) i0 = e;
        int i1 = (i0 == 0) ? 1 : 0;
#pragma unroll
        for (int e = 0; e < NEn; e++) if (e != i0 && p[e] > p[i1]) i1 = e;
        float denom = p[i0] + p[i1];
        float g0 = p[i0] / denom, g1 = p[i1] / denom;
        int pos0 = atomicAdd(&counts[i0], 1);
        bucket_ts[i0 * Tn + pos0] = (int)(t * 2);
        bucket_gate[i0 * Tn + pos0] = g0;
        int pos1 = atomicAdd(&counts[i1], 1);
        bucket_ts[i1 * Tn + pos1] = (int)(t * 2 + 1);
        bucket_gate[i1 * Tn + pos1] = g1;
    }
}

__global__ void offsets_k(const int* __restrict__ counts, int* __restrict__ off,
                          int* __restrict__ tile_expert)
{
    for (int tl = 0; tl < MOE_TILES; tl++) tile_expert[tl] = -1;
    int o = 0;
    for (int e = 0; e < NEn; e++) {
        off[e] = o;
        int nt = (counts[e] + 127) >> 7;
        for (int i = 0; i < nt; i++) tile_expert[(o >> 7) + i] = e;
        o += nt * 128;
    }
    off[NEn] = o;
}

__global__ void compact_k(const int* __restrict__ counts, const int* __restrict__ off,
                          const int* __restrict__ bucket_ts, const float* __restrict__ bucket_gate,
                          int* __restrict__ flat_tok, int* __restrict__ tok2row,
                          float* __restrict__ tok2gate)
{
    int e = blockIdx.x;
    int cnt = counts[e], base = off[e];
    for (int i = threadIdx.x; i < cnt; i += blockDim.x) {
        int ts = bucket_ts[e * Tn + i];
        int r = base + i;
        flat_tok[r] = ts >> 1;
        tok2row[ts] = r;
        tok2gate[ts] = bucket_gate[e * Tn + i];
    }
}

__global__ void gather_h(const __half* __restrict__ nh, const int* __restrict__ flat_tok,
                         __half* __restrict__ xg)
{
    long r = blockIdx.x;
    int t = flat_tok[r];
    uint4* dst = (uint4*)(xg + r * DIMn);
    int nch = DIMn / 8;
    if (t < 0) {
        uint4 zz = make_uint4(0u, 0u, 0u, 0u);
        for (int i = threadIdx.x; i < nch; i += blockDim.x) dst[i] = zz;
    } else {
        const uint4* src = (const uint4*)(nh + (long)t * DIMn);
        for (int i = threadIdx.x; i < nch; i += blockDim.x) dst[i] = src[i];
    }
}

__global__ void silumul2_h(const __half* __restrict__ t13, __half* __restrict__ outp,
                           int inter, long rows)
{
    long h2pr = inter / 2;
    long i = (long)blockIdx.x * blockDim.x + threadIdx.x;
    if (i < rows * h2pr) {
        long r = i / h2pr, j = i - r * h2pr;
        const __half2* pa = (const __half2*)(t13 + (size_t)r * 2 * inter);
        const __half2* pb = (const __half2*)(t13 + (size_t)r * 2 * inter + inter);
        float2 x = __half22float2(pa[j]);
        float2 y = __half22float2(pb[j]);
        float s0 = x.x / (1.f + expf(-x.x));
        float s1 = x.y / (1.f + expf(-x.y));
        ((__half2*)(outp + (size_t)r * inter))[j] =
            __float22half2_rn(make_float2(s0 * y.x, s1 * y.y));
    }
}

__global__ void combine_k(const float* __restrict__ h, const float* __restrict__ sh,
                          const float* __restrict__ eo, const int* __restrict__ tok2row,
                          const float* __restrict__ tok2gate, float* __restrict__ out)
{
    long t = blockIdx.x;
    int r0 = tok2row[t * 2], r1 = tok2row[t * 2 + 1];
    float g0 = tok2gate[t * 2], g1 = tok2gate[t * 2 + 1];
    const float4* H = (const float4*)(h + t * DIMn);
    const float4* SH = (const float4*)(sh + t * DIMn);
    const float4* E0 = (const float4*)(eo + (long)r0 * DIMn);
    const float4* E1 = (const float4*)(eo + (long)r1 * DIMn);
    float4* O = (float4*)(out + t * DIMn);
    for (int i = threadIdx.x; i < DIMn / 4; i += blockDim.x) {
        float4 a = H[i], b = SH[i], c = E0[i], d = E1[i];
        float4 o;
        o.x = a.x + b.x + g0 * c.x + g1 * d.x;
        o.y = a.y + b.y + g0 * c.y + g1 * d.y;
        o.z = a.z + b.z + g0 * c.z + g1 * d.z;
        o.w = a.w + b.w + g0 * c.w + g1 * d.w;
        O[i] = o;
    }
}

// ---------------- host ----------------
#define SYM(p, s) do { void* _q = nullptr; cudaGetSymbolAddress(&_q, s); p = (decltype(p))_q; } while (0)

static void launch_hgemm(const __half* A, const __half* B, void* C, const float* addend,
                         int M, int N, int K, int lda, int ldb, int ldc,
                         long sA0, long sA1, long sB0, long sB1, long sC0, long sC1,
                         int ZH, int Z, const int* tileExpert, long wStride, int flags)
{
    dim3 grid((N + TNW - 1) / TNW, M / 128, Z);
    hgemm_k<<<grid, 256, HG_SMEM>>>(A, B, C, addend, M, N, K, lda, ldb, ldc,
        sA0, sA1, sB0, sB1, sC0, sC1, ZH, tileExpert, wStride, flags);
}

static void launch_cvt(const float* src, __half* dst, long n)
{
    long n2 = n / 2;
    cvth_k<<<(int)((n2 + 255) / 256), 256>>>((const float2*)src, (__half2*)dst, n2);
}

extern "C" void kernel_launch(void* const* d_in, const int* in_sizes, int n_in,
                              void* d_out, int out_size)
{
    cudaFuncSetAttribute(hgemm_k, cudaFuncAttributeMaxDynamicSharedMemorySize, HG_SMEM);
    cudaFuncSetAttribute(fattn_k, cudaFuncAttributeMaxDynamicSharedMemorySize, FA_SMEM);

    const float* x       = (const float*)d_in[0];
    const float* fcos    = (const float*)d_in[1];
    const float* fsin    = (const float*)d_in[2];
    const float* attn_w  = (const float*)d_in[3];
    const float* wq      = (const float*)d_in[4];
    const float* wkv_a   = (const float*)d_in[5];
    const float* kv_w    = (const float*)d_in[6];
    const float* wkv_b   = (const float*)d_in[7];
    const float* wo      = (const float*)d_in[8];
    const float* ffn_w   = (const float*)d_in[9];
    const float* rw      = (const float*)d_in[10];
    const float* e_w1    = (const float*)d_in[11];
    const float* e_w3    = (const float*)d_in[12];
    const float* e_w2    = (const float*)d_in[13];
    const float* s_w1    = (const float*)d_in[14];
    const float* s_w3    = (const float*)d_in[15];
    const float* s_w2    = (const float*)d_in[16];
    float* out = (float*)d_out;

    float *q, *kv, *kpe, *kvb, *h, *eo, *sh;
    __half *nx_h, *ckv_h, *qh, *kcat, *vT, *attn_h, *nh_h, *xg, *t13h, *t1h, *s13h, *s1h;
    __half *wq_h, *wkva_h, *wkvb_h, *wo_h, *ew13_h, *ew2_h, *sw13_h, *sw2_h;
    int *counts, *off, *tile_expert, *bucket_ts, *flat_tok, *tok2row;
    float *bucket_gate, *tok2gate;
    SYM(q, g_q); SYM(kv, g_kv); SYM(kpe, g_kpe); SYM(kvb, g_kvb);
    SYM(h, g_h); SYM(eo, g_eo); SYM(sh, g_sh);
    SYM(nx_h, g_nx_h); SYM(ckv_h, g_ckv_h); SYM(qh, g_qh); SYM(kcat, g_kcat_h);
    SYM(vT, g_vT_h); SYM(attn_h, g_attn_h); SYM(nh_h, g_nh_h);
    SYM(xg, g_xg_h); SYM(t13h, g_t13h); SYM(t1h, g_t1h); SYM(s13h, g_s13h); SYM(s1h, g_s1h);
    SYM(wq_h, g_wq_h); SYM(wkva_h, g_wkva_h); SYM(wkvb_h, g_wkvb_h); SYM(wo_h, g_wo_h);
    SYM(ew13_h, g_ew13_h); SYM(ew2_h, g_ew2_h); SYM(sw13_h, g_sw13_h); SYM(sw2_h, g_sw2_h);
    SYM(counts, g_counts); SYM(off, g_off); SYM(tile_expert, g_tile_expert);
    SYM(bucket_ts, g_bucket_ts); SYM(bucket_gate, g_bucket_gate);
    SYM(flat_tok, g_flat_tok); SYM(tok2row, g_tok2row); SYM(tok2gate, g_tok2gate);

    const long PE2 = (long)MINTERn * DIMn / 2;

    // 0. weight conversion
    launch_cvt(wq, wq_h, (long)QPROJ * DIMn);
    launch_cvt(wkv_a, wkva_h, (long)KVAP * DIMn);
    launch_cvt(wkv_b, wkvb_h, (long)KVBP * KVRn);
    launch_cvt(wo, wo_h, (long)DIMn * DIMn);
    {
        long tot2 = (long)NEn * PE2;
        int blocks = (int)((tot2 + 255) / 256);
        cvtmoe_k<<<blocks, 256>>>((const float2*)e_w1, (__half2*)ew13_h, PE2, 2 * PE2, 0, tot2);
        cvtmoe_k<<<blocks, 256>>>((const float2*)e_w3, (__half2*)ew13_h, PE2, 2 * PE2, PE2, tot2);
    }
    launch_cvt(e_w2, ew2_h, (long)NEn * DIMn * MINTERn);
    launch_cvt(s_w1, sw13_h, (long)SHIn * DIMn);
    launch_cvt(s_w3, sw13_h + (size_t)SHIn * DIMn, (long)SHIn * DIMn);
    launch_cvt(s_w2, sw2_h, (long)DIMn * SHIn);

    // 1. attention-input rmsnorm -> fp16
    rmsnorm_h<<<Tn, 256>>>(x, attn_w, nx_h, DIMn, DIMn, DIMn);
    // 2. q projection (fp32 out)
    launch_hgemm(nx_h, wq_h, q, nullptr, Tn, QPROJ, DIMn, DIMn, DIMn, QPROJ,
                 0, 0, 0, 0, 0, 0, 1, 1, nullptr, 0, 0);
    // 3. kv_a projection (fp32 out)
    launch_hgemm(nx_h, wkva_h, kv, nullptr, Tn, KVAP, DIMn, DIMn, DIMn, KVAP,
                 0, 0, 0, 0, 0, 0, 1, 1, nullptr, 0, 0);
    // 4. c_kv rmsnorm -> fp16
    rmsnorm_h<<<Tn, 256>>>(kv, kv_w, ckv_h, KVRn, KVAP, KVRn);
    // 5. rope k_pe
    rope_kpe_k<<<Tn, 32>>>(kv, fcos, fsin, kpe);
    // 6. kv_b projection (fp32 out)
    launch_hgemm(ckv_h, wkvb_h, kvb, nullptr, Tn, KVBP, KVRn, KVRn, KVRn, KVBP,
                 0, 0, 0, 0, 0, 0, 1, 1, nullptr, 0, 0);
    // 7. rope + scale q -> fp16
    ropescale_qh<<<Tn * NHn, 96>>>(q, fcos, fsin, qh);
    // 8. kcat + vT -> fp16
    { dim3 g(Sn, ZSn); kcat_h<<<g, QDn>>>(kvb, kpe, kcat); }
    { dim3 g(Sn / 32, VHn / 32, ZSn); dim3 b(32, 8); vtrans_h<<<g, b>>>(kvb, vT); }
    // 9-11. fused flash attention -> attn fp16
    { dim3 g(16, ZSn); fattn_k<<<g, 256, FA_SMEM>>>(qh, kcat, vT, attn_h); }
    // 12. h = x + attn @ wo^T
    launch_hgemm(attn_h, wo_h, h, x, Tn, DIMn, DIMn, DIMn, DIMn, DIMn,
                 0, 0, 0, 0, 0, 0, 1, 1, nullptr, 0, 1);
    // 13. ffn rmsnorm -> fp16
    rmsnorm_h<<<Tn, 256>>>(h, ffn_w, nh_h, DIMn, DIMn, DIMn);
    // 14. routing
    cudaMemsetAsync(counts, 0, NEn * sizeof(int), 0);
    cudaMemsetAsync(flat_tok, 0xFF, MOE_ROWS * sizeof(int), 0);
    router_h<<<Tn, 256>>>(nh_h, rw, counts, bucket_ts, bucket_gate);
    offsets_k<<<1, 1>>>(counts, off, tile_expert);
    compact_k<<<NEn, 256>>>(counts, off, bucket_ts, bucket_gate, flat_tok, tok2row, tok2gate);
    gather_h<<<MOE_ROWS, 256>>>(nh_h, flat_tok, xg);
    // 15. expert FFN (grouped, fused w1||w3)
    launch_hgemm(xg, ew13_h, t13h, nullptr, MOE_ROWS, 2 * MINTERn, DIMn,
                 DIMn, DIMn, 2 * MINTERn,
                 0, 0, 0, 0, 0, 0, 1, 1, tile_expert, 2L * MINTERn * DIMn, 8);
    {
        long n2 = (long)MOE_ROWS * MINTERn / 2;
        silumul2_h<<<(int)((n2 + 255) / 256), 256>>>(t13h, t1h, MINTERn, MOE_ROWS);
    }
    launch_hgemm(t1h, ew2_h, eo, nullptr, MOE_ROWS, DIMn, MINTERn, MINTERn, MINTERn, DIMn,
                 0, 0, 0, 0, 0, 0, 1, 1, tile_expert, (long)DIMn * MINTERn, 0);
    // 16. shared FFN (fused w1||w3)
    launch_hgemm(nh_h, sw13_h, s13h, nullptr, Tn, 2 * SHIn, DIMn, DIMn, DIMn, 2 * SHIn,
                 0, 0, 0, 0, 0, 0, 1, 1, nullptr, 0, 8);
    {
        long n2 = (long)Tn * SHIn / 2;
        silumul2_h<<<(int)((n2 + 255) / 256), 256>>>(s13h, s1h, SHIn, Tn);
    }
    launch_hgemm(s1h, sw2_h, sh, nullptr, Tn, DIMn, SHIn, SHIn, SHIn, DIMn,
                 0, 0, 0, 0, 0, 0, 1, 1, nullptr, 0, 0);
    // 17. combine
    combine_k<<<Tn, 256>>>(h, sh, eo, tok2row, tok2gate, out);
}